// round 4
// baseline (speedup 1.0000x reference)
#include <cuda_runtime.h>
#include <cuda_bf16.h>
#include <math.h>
#include <stdint.h>

// ---------------- problem constants ----------------
#define BB 64
#define NN_TOK 1029
#define DD 768
#define HH 12
#define HD 64
#define KK 128
#define RR 5
#define MM 4
#define PP 1024              // N - R
#define CC 133               // R + K

#define MPAD_X 65920         // 515*128  (>= B*N = 65856)
#define MPAD_C 8576          // 67*128   (>= B*C = 8512)

// output layout: [out (B*N*D)] [cls_n (B*D)] [idx (B)]
#define OUT_CLS ((long)BB * NN_TOK * DD)
#define OUT_IDX (OUT_CLS + (long)BB * DD)

// ---------------- scratch (device globals; no allocs allowed) ----------------
__device__ int   g_idx[BB];
__device__ float g_scores[(long)BB * KK * PP];
__device__ float g_kv[(long)BB * CC * 2 * DD];
__device__ float g_q[(long)BB * NN_TOK * DD];

// bf16 split buffers (zero-init covers padding rows)
__device__ __nv_bfloat16 g_x_hi[(long)MPAD_X * DD];
__device__ __nv_bfloat16 g_x_lo[(long)MPAD_X * DD];
__device__ __nv_bfloat16 g_y_hi[(long)MPAD_X * DD];
__device__ __nv_bfloat16 g_y_lo[(long)MPAD_X * DD];
__device__ __nv_bfloat16 g_c_hi[(long)MPAD_C * DD];
__device__ __nv_bfloat16 g_c_lo[(long)MPAD_C * DD];
__device__ __nv_bfloat16 g_s_hi[(long)BB * KK * PP];   // attn weights hi
__device__ __nv_bfloat16 g_s_lo[(long)BB * KK * PP];   // attn weights lo
__device__ __nv_bfloat16 g_qb_hi[(long)MM * KK * DD];
__device__ __nv_bfloat16 g_qb_lo[(long)MM * KK * DD];
__device__ __nv_bfloat16 g_wq_hi[DD * DD];
__device__ __nv_bfloat16 g_wq_lo[DD * DD];
__device__ __nv_bfloat16 g_wo_hi[DD * DD];
__device__ __nv_bfloat16 g_wo_lo[DD * DD];
__device__ __nv_bfloat16 g_wc_hi[2 * DD * DD];
__device__ __nv_bfloat16 g_wc_lo[2 * DD * DD];

// ---------------- PTX helpers ----------------
__device__ __forceinline__ uint32_t smem_u32(const void* p) {
    uint32_t a;
    asm("{ .reg .u64 t; cvta.to.shared.u64 t, %1; cvt.u32.u64 %0, t; }" : "=r"(a) : "l"(p));
    return a;
}
__device__ __forceinline__ void cpasync16(uint32_t dst, const void* src) {
    asm volatile("cp.async.cg.shared.global [%0], [%1], 16;" :: "r"(dst), "l"(src));
}
#define CP_COMMIT() asm volatile("cp.async.commit_group;" ::: "memory")
#define CP_WAIT1()  asm volatile("cp.async.wait_group 1;" ::: "memory")
#define CP_WAIT0()  asm volatile("cp.async.wait_group 0;" ::: "memory")

__device__ __forceinline__ void ldsm4(uint32_t* r, uint32_t addr) {
    asm volatile("ldmatrix.sync.aligned.m8n8.x4.shared.b16 {%0,%1,%2,%3}, [%4];"
        : "=r"(r[0]), "=r"(r[1]), "=r"(r[2]), "=r"(r[3]) : "r"(addr));
}
__device__ __forceinline__ void ldsm4t(uint32_t* r, uint32_t addr) {
    asm volatile("ldmatrix.sync.aligned.m8n8.x4.trans.shared.b16 {%0,%1,%2,%3}, [%4];"
        : "=r"(r[0]), "=r"(r[1]), "=r"(r[2]), "=r"(r[3]) : "r"(addr));
}
__device__ __forceinline__ void mma_bf16(float* c, const uint32_t* a, const uint32_t* b) {
    asm volatile(
        "mma.sync.aligned.m16n8k16.row.col.f32.bf16.bf16.f32 "
        "{%0,%1,%2,%3}, {%4,%5,%6,%7}, {%8,%9}, {%0,%1,%2,%3};"
        : "+f"(c[0]), "+f"(c[1]), "+f"(c[2]), "+f"(c[3])
        : "r"(a[0]), "r"(a[1]), "r"(a[2]), "r"(a[3]), "r"(b[0]), "r"(b[1]));
}

// split a float pair into bf16 hi/lo and store packed
__device__ __forceinline__ void split2_store(
    __nv_bfloat16* __restrict__ H, __nv_bfloat16* __restrict__ L, long off, float v0, float v1)
{
    __nv_bfloat16 h0 = __float2bfloat16(v0);
    __nv_bfloat16 h1 = __float2bfloat16(v1);
    __nv_bfloat16 l0 = __float2bfloat16(v0 - __bfloat162float(h0));
    __nv_bfloat16 l1 = __float2bfloat16(v1 - __bfloat162float(h1));
    uint32_t hw = (uint32_t)*reinterpret_cast<unsigned short*>(&h0)
                | ((uint32_t)*reinterpret_cast<unsigned short*>(&h1) << 16);
    uint32_t lw = (uint32_t)*reinterpret_cast<unsigned short*>(&l0)
                | ((uint32_t)*reinterpret_cast<unsigned short*>(&l1) << 16);
    *reinterpret_cast<uint32_t*>(H + off) = hw;
    *reinterpret_cast<uint32_t*>(L + off) = lw;
}

// ---------------- NT HMMA GEMM, fp32 via bf16 3-split, 3-stage pipeline ------
// C[m,n] (+= bias[n]) = sum_k A[m,k] * B[n,k]
#define LDSB 80                    // smem bytes per A/B-NT tile row (32 bf16 + pad)
#define TILE_B (128 * LDSB)        // 10240
#define STAGE_B (4 * TILE_B)       // 40960
#define GEMM_SMEM (3 * STAGE_B)    // 122880

template<bool BIAS, bool GATHER>
__global__ void __launch_bounds__(256) gemm_mma(
    const __nv_bfloat16* __restrict__ Ahb, const __nv_bfloat16* __restrict__ Alb,
    const __nv_bfloat16* __restrict__ Bhb, const __nv_bfloat16* __restrict__ Blb,
    const float* __restrict__ bias, float* __restrict__ Cb,
    int M, int Ntot, int Kd,
    long sA, long sB, long sC,
    const int* __restrict__ idxmap)
{
    extern __shared__ char smem[];
    uint32_t sb = smem_u32(smem);

    int tid = threadIdx.x, wid = tid >> 5, lane = tid & 31;
    int warp_m = wid & 3, warp_n = wid >> 2;
    int bz = blockIdx.z;
    long aoff = GATHER ? (long)idxmap[bz] * sA : (long)bz * sA;
    const __nv_bfloat16* Ah = Ahb + aoff;
    const __nv_bfloat16* Al = Alb + aoff;
    const __nv_bfloat16* Bh = Bhb + (long)bz * sB;
    const __nv_bfloat16* Bl = Blb + (long)bz * sB;
    float* C = Cb + (long)bz * sC;

    int m0 = blockIdx.y * 128;
    int n0 = blockIdx.x * 128;

    float acc[2][8][4];
#pragma unroll
    for (int i = 0; i < 2; i++)
#pragma unroll
        for (int j = 0; j < 8; j++)
#pragma unroll
            for (int k = 0; k < 4; k++) acc[i][j][k] = 0.f;

    const int nch = Kd / 32;

    auto issue = [&](int ch) {
        uint32_t st = sb + (ch % 3) * STAGE_B;
        int k0 = ch * 32;
#pragma unroll
        for (int it = 0; it < 2; it++) {
            int idx = tid + it * 256;
            int r = idx >> 2, c = idx & 3;
            uint32_t so = r * LDSB + c * 16;
            long gA = (long)(m0 + r) * Kd + k0 + c * 8;
            long gB = (long)(n0 + r) * Kd + k0 + c * 8;
            cpasync16(st + so,              Ah + gA);
            cpasync16(st + TILE_B + so,     Al + gA);
            cpasync16(st + 2 * TILE_B + so, Bh + gB);
            cpasync16(st + 3 * TILE_B + so, Bl + gB);
        }
        CP_COMMIT();
    };

    issue(0);
    if (nch > 1) issue(1);

    int lr = lane & 15, lc = lane >> 4;

    for (int ch = 0; ch < nch; ch++) {
        if (ch < nch - 1) { CP_WAIT1(); } else { CP_WAIT0(); }
        __syncthreads();
        if (ch + 2 < nch) issue(ch + 2);

        uint32_t stg = sb + (ch % 3) * STAGE_B;
        uint32_t Ah_s = stg;
        uint32_t Al_s = stg + TILE_B;
        uint32_t Bh_s = stg + 2 * TILE_B;
        uint32_t Bl_s = stg + 3 * TILE_B;

#pragma unroll
        for (int ks = 0; ks < 2; ks++) {
            uint32_t koff = ks * 32 + lc * 16;
            uint32_t ah[2][4], al[2][4], bh[8][2], bl[8][2];
#pragma unroll
            for (int mf = 0; mf < 2; mf++) {
                uint32_t row = warp_m * 32 + mf * 16 + lr;
                ldsm4(ah[mf], Ah_s + row * LDSB + koff);
                ldsm4(al[mf], Al_s + row * LDSB + koff);
            }
#pragma unroll
            for (int p = 0; p < 4; p++) {
                uint32_t row = warp_n * 64 + p * 16 + lr;
                uint32_t t[4];
                ldsm4(t, Bh_s + row * LDSB + koff);
                bh[2 * p][0] = t[0]; bh[2 * p][1] = t[2];
                bh[2 * p + 1][0] = t[1]; bh[2 * p + 1][1] = t[3];
                ldsm4(t, Bl_s + row * LDSB + koff);
                bl[2 * p][0] = t[0]; bl[2 * p][1] = t[2];
                bl[2 * p + 1][0] = t[1]; bl[2 * p + 1][1] = t[3];
            }
#pragma unroll
            for (int mf = 0; mf < 2; mf++)
#pragma unroll
                for (int nf = 0; nf < 8; nf++) {
                    mma_bf16(acc[mf][nf], ah[mf], bh[nf]);
                    mma_bf16(acc[mf][nf], ah[mf], bl[nf]);
                    mma_bf16(acc[mf][nf], al[mf], bh[nf]);
                }
        }
        __syncthreads();
    }

#pragma unroll
    for (int mf = 0; mf < 2; mf++) {
        int row0 = m0 + warp_m * 32 + mf * 16 + (lane >> 2);
#pragma unroll
        for (int nf = 0; nf < 8; nf++) {
            int col = n0 + warp_n * 64 + nf * 8 + (lane & 3) * 2;
            float b0 = 0.f, b1 = 0.f;
            if (BIAS) { b0 = bias[col]; b1 = bias[col + 1]; }
            if (row0 < M) {
                float2 v = make_float2(acc[mf][nf][0] + b0, acc[mf][nf][1] + b1);
                *reinterpret_cast<float2*>(&C[(long)row0 * Ntot + col]) = v;
            }
            if (row0 + 8 < M) {
                float2 v = make_float2(acc[mf][nf][2] + b0, acc[mf][nf][3] + b1);
                *reinterpret_cast<float2*>(&C[(long)(row0 + 8) * Ntot + col]) = v;
            }
        }
    }
}

// ---------------- NN HMMA GEMM (B row-major [k][n]), split bf16 output -------
// C[m,n] = sum_k A[m,k] * B[k,n];  M = 128 fixed; output written as hi/lo bf16.
#define LDSB_N 272                       // 128 bf16 (256B) + 16B pad
#define NTILE_B (32 * LDSB_N)            // 8704
#define NSTAGE_B (2 * TILE_B + 2 * NTILE_B)   // 37888
#define NN_SMEM (3 * NSTAGE_B)           // 113664

__global__ void __launch_bounds__(256) gemm_mma_nn(
    const __nv_bfloat16* __restrict__ Ahb, const __nv_bfloat16* __restrict__ Alb,
    const __nv_bfloat16* __restrict__ Bhb, const __nv_bfloat16* __restrict__ Blb,
    __nv_bfloat16* __restrict__ Chb, __nv_bfloat16* __restrict__ Clb,
    int Ntot, int Kd, int ldB,
    long sA, long sB, long sC)
{
    extern __shared__ char smem[];
    uint32_t sb = smem_u32(smem);

    int tid = threadIdx.x, wid = tid >> 5, lane = tid & 31;
    int warp_m = wid & 3, warp_n = wid >> 2;
    int bz = blockIdx.z;
    const __nv_bfloat16* Ah = Ahb + (long)bz * sA;
    const __nv_bfloat16* Al = Alb + (long)bz * sA;
    const __nv_bfloat16* Bh = Bhb + (long)bz * sB;
    const __nv_bfloat16* Bl = Blb + (long)bz * sB;
    __nv_bfloat16* Ch = Chb + (long)bz * sC;
    __nv_bfloat16* Cl = Clb + (long)bz * sC;

    int n0 = blockIdx.x * 128;

    float acc[2][8][4];
#pragma unroll
    for (int i = 0; i < 2; i++)
#pragma unroll
        for (int j = 0; j < 8; j++)
#pragma unroll
            for (int k = 0; k < 4; k++) acc[i][j][k] = 0.f;

    const int nch = Kd / 32;

    auto issue = [&](int ch) {
        uint32_t st = sb + (ch % 3) * NSTAGE_B;
        int k0 = ch * 32;
        // A hi/lo: 128 rows x 32 k
#pragma unroll
        for (int it = 0; it < 2; it++) {
            int idx = tid + it * 256;
            int r = idx >> 2, c = idx & 3;
            uint32_t so = r * LDSB + c * 16;
            long gA = (long)r * Kd + k0 + c * 8;
            cpasync16(st + so,          Ah + gA);
            cpasync16(st + TILE_B + so, Al + gA);
        }
        // B hi/lo: 32 k-rows x 128 n
#pragma unroll
        for (int it = 0; it < 2; it++) {
            int idx = tid + it * 256;
            int r = idx >> 4, c = idx & 15;
            uint32_t so = 2 * TILE_B + r * LDSB_N + c * 16;
            long gB = (long)(k0 + r) * ldB + n0 + c * 8;
            cpasync16(st + so,           Bh + gB);
            cpasync16(st + so + NTILE_B, Bl + gB);
        }
        CP_COMMIT();
    };

    issue(0);
    if (nch > 1) issue(1);

    int lr = lane & 15, lc = lane >> 4;
    int l8 = (lane >> 3) & 1;
    int krow = ((lane >> 4) & 1) * 8 + (lane & 7);   // 0..15

    for (int ch = 0; ch < nch; ch++) {
        if (ch < nch - 1) { CP_WAIT1(); } else { CP_WAIT0(); }
        __syncthreads();
        if (ch + 2 < nch) issue(ch + 2);

        uint32_t stg = sb + (ch % 3) * NSTAGE_B;
        uint32_t Ah_s = stg;
        uint32_t Al_s = stg + TILE_B;
        uint32_t Bh_s = stg + 2 * TILE_B;
        uint32_t Bl_s = Bh_s + NTILE_B;

#pragma unroll
        for (int ks = 0; ks < 2; ks++) {
            uint32_t koff = ks * 32 + lc * 16;
            uint32_t ah[2][4], al[2][4], bh[8][2], bl[8][2];
#pragma unroll
            for (int mf = 0; mf < 2; mf++) {
                uint32_t row = warp_m * 32 + mf * 16 + lr;
                ldsm4(ah[mf], Ah_s + row * LDSB + koff);
                ldsm4(al[mf], Al_s + row * LDSB + koff);
            }
            // B via ldmatrix.trans from [k][n] tiles
            uint32_t brow = (ks * 16 + krow) * LDSB_N + warp_n * 128 + l8 * 16;
#pragma unroll
            for (int p = 0; p < 4; p++) {
                uint32_t t[4];
                ldsm4t(t, Bh_s + brow + p * 32);
                bh[2 * p][0] = t[0]; bh[2 * p][1] = t[2];
                bh[2 * p + 1][0] = t[1]; bh[2 * p + 1][1] = t[3];
                ldsm4t(t, Bl_s + brow + p * 32);
                bl[2 * p][0] = t[0]; bl[2 * p][1] = t[2];
                bl[2 * p + 1][0] = t[1]; bl[2 * p + 1][1] = t[3];
            }
#pragma unroll
            for (int mf = 0; mf < 2; mf++)
#pragma unroll
                for (int nf = 0; nf < 8; nf++) {
                    mma_bf16(acc[mf][nf], ah[mf], bh[nf]);
                    mma_bf16(acc[mf][nf], ah[mf], bl[nf]);
                    mma_bf16(acc[mf][nf], al[mf], bh[nf]);
                }
        }
        __syncthreads();
    }

    // epilogue: split to bf16 hi/lo (M = 128 exact, no bounds checks)
#pragma unroll
    for (int mf = 0; mf < 2; mf++) {
        int row0 = warp_m * 32 + mf * 16 + (lane >> 2);
#pragma unroll
        for (int nf = 0; nf < 8; nf++) {
            int col = n0 + warp_n * 64 + nf * 8 + (lane & 3) * 2;
            split2_store(Ch, Cl, (long)row0 * Ntot + col, acc[mf][nf][0], acc[mf][nf][1]);
            split2_store(Ch, Cl, (long)(row0 + 8) * Ntot + col, acc[mf][nf][2], acc[mf][nf][3]);
        }
    }
}

// ---------------- split fp32 -> bf16 hi/lo (8 elems / thread) ----------------
__global__ __launch_bounds__(256) void split_kernel(
    const float4* __restrict__ in, uint4* __restrict__ hi, uint4* __restrict__ lo, long n8)
{
    long i = (long)blockIdx.x * 256 + threadIdx.x;
    if (i >= n8) return;
    float4 a = in[2 * i], b = in[2 * i + 1];
    float v[8] = { a.x, a.y, a.z, a.w, b.x, b.y, b.z, b.w };
    uint32_t hw[8], lw[8];
#pragma unroll
    for (int j = 0; j < 8; j++) {
        __nv_bfloat16 h = __float2bfloat16(v[j]);
        __nv_bfloat16 l = __float2bfloat16(v[j] - __bfloat162float(h));
        hw[j] = *reinterpret_cast<unsigned short*>(&h);
        lw[j] = *reinterpret_cast<unsigned short*>(&l);
    }
    uint4 H, L;
    H.x = hw[0] | (hw[1] << 16); H.y = hw[2] | (hw[3] << 16);
    H.z = hw[4] | (hw[5] << 16); H.w = hw[6] | (hw[7] << 16);
    L.x = lw[0] | (lw[1] << 16); L.y = lw[2] | (lw[3] << 16);
    L.z = lw[4] | (lw[5] << 16); L.w = lw[6] | (lw[7] << 16);
    hi[i] = H; lo[i] = L;
}

// ---------------- transpose + split weights: W[Kd,Nc] -> WT[Nc,Kd] ----------
__global__ __launch_bounds__(256) void tsplit_kernel(
    const float* __restrict__ W, __nv_bfloat16* __restrict__ hiT,
    __nv_bfloat16* __restrict__ loT, int Kd, int Nc)
{
    int idx = blockIdx.x * 256 + threadIdx.x;
    if (idx >= Kd * Nc) return;
    int k = idx / Nc, n = idx % Nc;
    float a = W[idx];
    __nv_bfloat16 h = __float2bfloat16(a);
    __nv_bfloat16 l = __float2bfloat16(a - __bfloat162float(h));
    hiT[(long)n * Kd + k] = h;
    loT[(long)n * Kd + k] = l;
}

// ---------------- kernel 1: cls_n, sims, argmax ----------------
__global__ __launch_bounds__(256) void cls_kernel(
    const float* __restrict__ x, const float* __restrict__ cents,
    float* __restrict__ out_cls, float* __restrict__ out_idx, int* __restrict__ idx)
{
    int b = blockIdx.x;
    int t = threadIdx.x;
    __shared__ float red[256];
    __shared__ float snorm;
    __shared__ float best_s;
    __shared__ int best_i;

    const float* xr = x + (long)b * NN_TOK * DD;
    float loc[3];
    float ss = 0.f;
#pragma unroll
    for (int i = 0; i < 3; i++) { loc[i] = xr[t + i * 256]; ss += loc[i] * loc[i]; }
    red[t] = ss; __syncthreads();
    for (int s = 128; s > 0; s >>= 1) { if (t < s) red[t] += red[t + s]; __syncthreads(); }
    if (t == 0) snorm = fmaxf(sqrtf(red[0]), 1e-12f);
    __syncthreads();
    float inv = 1.0f / snorm;
    float c[3];
#pragma unroll
    for (int i = 0; i < 3; i++) {
        c[i] = loc[i] * inv;
        out_cls[(long)b * DD + t + i * 256] = c[i];
    }
    if (t == 0) { best_s = -1e30f; best_i = 0; }
    __syncthreads();
    for (int m = 0; m < MM; m++) {
        float p = 0.f;
#pragma unroll
        for (int i = 0; i < 3; i++) p += c[i] * cents[(long)m * DD + t + i * 256];
        red[t] = p; __syncthreads();
        for (int s = 128; s > 0; s >>= 1) { if (t < s) red[t] += red[t + s]; __syncthreads(); }
        if (t == 0) { if (red[0] > best_s) { best_s = red[0]; best_i = m; } }
        __syncthreads();
    }
    if (t == 0) { idx[b] = best_i; out_idx[b] = (float)best_i; }
}

// ---------------- softmax over rows of length 1024, emit bf16 hi/lo ---------
__global__ __launch_bounds__(256) void softmax1024_split(
    const float* __restrict__ s, __nv_bfloat16* __restrict__ oh, __nv_bfloat16* __restrict__ ol)
{
    long row = blockIdx.x;
    const float* p = s + row * PP;
    int t = threadIdx.x;
    __shared__ float red[256];

    float4 v = reinterpret_cast<const float4*>(p)[t];
    float mx = fmaxf(fmaxf(v.x, v.y), fmaxf(v.z, v.w));
    red[t] = mx; __syncthreads();
    for (int st = 128; st > 0; st >>= 1) { if (t < st) red[t] = fmaxf(red[t], red[t + st]); __syncthreads(); }
    mx = red[0]; __syncthreads();

    v.x = expf(v.x - mx); v.y = expf(v.y - mx);
    v.z = expf(v.z - mx); v.w = expf(v.w - mx);
    float sm = v.x + v.y + v.z + v.w;
    red[t] = sm; __syncthreads();
    for (int st = 128; st > 0; st >>= 1) { if (t < st) red[t] += red[t + st]; __syncthreads(); }
    float inv = 1.0f / red[0];
    v.x *= inv; v.y *= inv; v.z *= inv; v.w *= inv;

    long off = row * PP + (long)t * 4;
    split2_store(oh, ol, off,     v.x, v.y);
    split2_store(oh, ol, off + 2, v.z, v.w);
}

// ---------------- copy x[:, :R, :] into ctx hi/lo rows 0..R-1 ---------------
__global__ __launch_bounds__(256) void copy_xreg_split(
    const float* __restrict__ x, __nv_bfloat16* __restrict__ ch, __nv_bfloat16* __restrict__ cl)
{
    long i = (long)blockIdx.x * blockDim.x + threadIdx.x;   // float4 index
    long total = (long)BB * RR * DD / 4;
    if (i >= total) return;
    long per_b = (long)RR * DD / 4;
    long b = i / per_b;
    long r = i - b * per_b;
    float4 v = reinterpret_cast<const float4*>(x)[b * ((long)NN_TOK * DD / 4) + r];
    long off = b * (long)CC * DD + r * 4;
    split2_store(ch, cl, off,     v.x, v.y);
    split2_store(ch, cl, off + 2, v.z, v.w);
}

// ---------------- attention: one (b,h) per block, no-max online softmax -----
// scores here are bounded (|q.k|/8 << 88), so exp without max subtraction is safe.
__global__ __launch_bounds__(256) void attn_kernel(
    const float* __restrict__ q, const float* __restrict__ kv,
    __nv_bfloat16* __restrict__ yh, __nv_bfloat16* __restrict__ yl)
{
    extern __shared__ float sh[];
    float* sk = sh;
    float* sv = sh + CC * HD;
    int b = blockIdx.x / HH;
    int h = blockIdx.x % HH;
    int tid = threadIdx.x;

    for (int i = tid; i < CC * 16; i += 256) {
        int m = i >> 4;
        int jc = (i & 15) * 4;
        long base = ((long)(b * CC + m)) * (2 * DD) + h * HD + jc;
        *reinterpret_cast<float4*>(&sk[m * HD + jc]) = *reinterpret_cast<const float4*>(&kv[base]);
        *reinterpret_cast<float4*>(&sv[m * HD + jc]) = *reinterpret_cast<const float4*>(&kv[base + DD]);
    }
    __syncthreads();

    const float scale = 0.125f;  // 1/sqrt(64), folded into q
    for (int nb = 0; nb < NN_TOK; nb += 256) {
        int n = nb + tid;
        if (n >= NN_TOK) break;
        const float* qp = q + ((long)(b * NN_TOK + n)) * DD + h * HD;
        float qr[HD];
#pragma unroll
        for (int j = 0; j < HD; j += 4) {
            float4 t4 = *reinterpret_cast<const float4*>(&qp[j]);
            qr[j] = t4.x * scale; qr[j + 1] = t4.y * scale;
            qr[j + 2] = t4.z * scale; qr[j + 3] = t4.w * scale;
        }

        float acc[HD];
#pragma unroll
        for (int j = 0; j < HD; j++) acc[j] = 0.f;
        float lsum = 0.f;

        for (int m = 0; m < CC; m++) {
            const float* kp = &sk[m * HD];
            float s0 = 0.f, s1 = 0.f, s2 = 0.f, s3 = 0.f;
#pragma unroll
            for (int j = 0; j < HD; j += 4) {
                float4 kv4 = *reinterpret_cast<const float4*>(&kp[j]);
                s0 += qr[j] * kv4.x; s1 += qr[j + 1] * kv4.y;
                s2 += qr[j + 2] * kv4.z; s3 += qr[j + 3] * kv4.w;
            }
            float e = __expf((s0 + s1) + (s2 + s3));
            lsum += e;
            const float* vp = &sv[m * HD];
#pragma unroll
            for (int j = 0; j < HD; j += 4) {
                float4 vv = *reinterpret_cast<const float4*>(&vp[j]);
                acc[j] += e * vv.x; acc[j + 1] += e * vv.y;
                acc[j + 2] += e * vv.z; acc[j + 3] += e * vv.w;
            }
        }
        float inv = 1.0f / lsum;
        long ybase = ((long)(b * NN_TOK + n)) * DD + h * HD;
#pragma unroll
        for (int j = 0; j < HD; j += 2)
            split2_store(yh, yl, ybase + j, acc[j] * inv, acc[j + 1] * inv);
    }
}

// ---------------- launch ----------------
extern "C" void kernel_launch(void* const* d_in, const int* in_sizes, int n_in,
                              void* d_out, int out_size)
{
    const float* x      = (const float*)d_in[0];
    const float* Qb     = (const float*)d_in[1];
    const float* Wq     = (const float*)d_in[2];
    const float* Wctx   = (const float*)d_in[3];
    const float* bctx   = (const float*)d_in[4];
    const float* Wout   = (const float*)d_in[5];
    const float* bout   = (const float*)d_in[6];
    const float* cents  = (const float*)d_in[7];
    float* out = (float*)d_out;

    void *p_idx, *p_scores, *p_kv, *p_q;
    void *p_xh, *p_xl, *p_yh, *p_yl, *p_ch, *p_cl, *p_sh, *p_sl;
    void *p_qbh, *p_qbl, *p_wqh, *p_wql, *p_woh, *p_wol, *p_wch, *p_wcl;
    cudaGetSymbolAddress(&p_idx, g_idx);
    cudaGetSymbolAddress(&p_scores, g_scores);
    cudaGetSymbolAddress(&p_kv, g_kv);
    cudaGetSymbolAddress(&p_q, g_q);
    cudaGetSymbolAddress(&p_xh, g_x_hi);  cudaGetSymbolAddress(&p_xl, g_x_lo);
    cudaGetSymbolAddress(&p_yh, g_y_hi);  cudaGetSymbolAddress(&p_yl, g_y_lo);
    cudaGetSymbolAddress(&p_ch, g_c_hi);  cudaGetSymbolAddress(&p_cl, g_c_lo);
    cudaGetSymbolAddress(&p_sh, g_s_hi);  cudaGetSymbolAddress(&p_sl, g_s_lo);
    cudaGetSymbolAddress(&p_qbh, g_qb_hi); cudaGetSymbolAddress(&p_qbl, g_qb_lo);
    cudaGetSymbolAddress(&p_wqh, g_wq_hi); cudaGetSymbolAddress(&p_wql, g_wq_lo);
    cudaGetSymbolAddress(&p_woh, g_wo_hi); cudaGetSymbolAddress(&p_wol, g_wo_lo);
    cudaGetSymbolAddress(&p_wch, g_wc_hi); cudaGetSymbolAddress(&p_wcl, g_wc_lo);

    int*   idxp   = (int*)p_idx;
    float* scores = (float*)p_scores;
    float* kvp    = (float*)p_kv;
    float* qp     = (float*)p_q;
    __nv_bfloat16 *xh = (__nv_bfloat16*)p_xh, *xl = (__nv_bfloat16*)p_xl;
    __nv_bfloat16 *yh = (__nv_bfloat16*)p_yh, *yl = (__nv_bfloat16*)p_yl;
    __nv_bfloat16 *ch = (__nv_bfloat16*)p_ch, *cl = (__nv_bfloat16*)p_cl;
    __nv_bfloat16 *shp = (__nv_bfloat16*)p_sh, *slp = (__nv_bfloat16*)p_sl;
    __nv_bfloat16 *qbh = (__nv_bfloat16*)p_qbh, *qbl = (__nv_bfloat16*)p_qbl;
    __nv_bfloat16 *wqh = (__nv_bfloat16*)p_wqh, *wql = (__nv_bfloat16*)p_wql;
    __nv_bfloat16 *woh = (__nv_bfloat16*)p_woh, *wol = (__nv_bfloat16*)p_wol;
    __nv_bfloat16 *wch = (__nv_bfloat16*)p_wch, *wcl = (__nv_bfloat16*)p_wcl;

    cudaFuncSetAttribute(gemm_mma<false, false>, cudaFuncAttributeMaxDynamicSharedMemorySize, GEMM_SMEM);
    cudaFuncSetAttribute(gemm_mma<true, false>,  cudaFuncAttributeMaxDynamicSharedMemorySize, GEMM_SMEM);
    cudaFuncSetAttribute(gemm_mma<false, true>,  cudaFuncAttributeMaxDynamicSharedMemorySize, GEMM_SMEM);
    cudaFuncSetAttribute(gemm_mma_nn, cudaFuncAttributeMaxDynamicSharedMemorySize, NN_SMEM);

    // 1. cls_n / idx
    cls_kernel<<<BB, 256>>>(x, cents, out + OUT_CLS, out + OUT_IDX, idxp);

    // 2. precision splits: x, Q_banks, weights (transposed)
    {
        long n8 = (long)BB * NN_TOK * DD / 8;
        split_kernel<<<(unsigned)((n8 + 255) / 256), 256>>>(
            (const float4*)x, (uint4*)xh, (uint4*)xl, n8);
        long q8 = (long)MM * KK * DD / 8;
        split_kernel<<<(unsigned)((q8 + 255) / 256), 256>>>(
            (const float4*)Qb, (uint4*)qbh, (uint4*)qbl, q8);
        tsplit_kernel<<<(DD * DD + 255) / 256, 256>>>(Wq, wqh, wql, DD, DD);
        tsplit_kernel<<<(DD * DD + 255) / 256, 256>>>(Wout, woh, wol, DD, DD);
        tsplit_kernel<<<(DD * 2 * DD + 255) / 256, 256>>>(Wctx, wch, wcl, DD, 2 * DD);
    }

    // 3. scores[b] = Q_banks[idx[b]] @ xp[b]^T  (128 x 1024, K=768) — HMMA NT
    gemm_mma<false, true><<<dim3(PP / 128, 1, BB), 256, GEMM_SMEM>>>(
        qbh, qbl, xh + (long)RR * DD, xl + (long)RR * DD, nullptr, scores,
        KK, PP, DD,
        (long)KK * DD, (long)NN_TOK * DD, (long)KK * PP, idxp);

    // 4. softmax rows (B*K x 1024) -> bf16 hi/lo attn weights
    softmax1024_split<<<BB * KK, 256>>>(scores, shp, slp);

    // 5. ctx[:, :R] = xreg (split)
    {
        long total = (long)BB * RR * DD / 4;
        copy_xreg_split<<<(unsigned)((total + 255) / 256), 256>>>(x, ch, cl);
    }

    // 6. ctx[:, R:] = attn (128x1024) @ xp (1024x768) — HMMA NN, split output
    gemm_mma_nn<<<dim3(DD / 128, 1, BB), 256, NN_SMEM>>>(
        shp, slp, xh + (long)RR * DD, xl + (long)RR * DD,
        ch + (long)RR * DD, cl + (long)RR * DD,
        DD, PP, DD,
        (long)KK * PP, (long)NN_TOK * DD, (long)CC * DD);

    // 7. kv = ctx (8512x768) @ Wctx + bctx — HMMA NT
    gemm_mma<true, false><<<dim3(2 * DD / 128, MPAD_C / 128, 1), 256, GEMM_SMEM>>>(
        ch, cl, wch, wcl, bctx, kvp,
        BB * CC, 2 * DD, DD, 0, 0, 0, nullptr);

    // 8. q = x (65856x768) @ Wq — HMMA NT
    gemm_mma<false, false><<<dim3(DD / 128, MPAD_X / 128, 1), 256, GEMM_SMEM>>>(
        xh, xl, wqh, wql, nullptr, qp,
        BB * NN_TOK, DD, DD, 0, 0, 0, nullptr);

    // 9. attention -> y hi/lo (SIMT, no-max online softmax)
    {
        int smem = CC * HD * 2 * (int)sizeof(float);
        cudaFuncSetAttribute(attn_kernel, cudaFuncAttributeMaxDynamicSharedMemorySize, smem);
        attn_kernel<<<BB * HH, 256, smem>>>(qp, kvp, yh, yl);
    }

    // 10. out = y @ Wout + bout — HMMA NT
    gemm_mma<true, false><<<dim3(DD / 128, MPAD_X / 128, 1), 256, GEMM_SMEM>>>(
        yh, yl, woh, wol, bout, out,
        BB * NN_TOK, DD, DD, 0, 0, 0, nullptr);
}

// round 5
// speedup vs baseline: 1.0906x; 1.0906x over previous
#include <cuda_runtime.h>
#include <cuda_bf16.h>
#include <math.h>
#include <stdint.h>

// ---------------- problem constants ----------------
#define BB 64
#define NN_TOK 1029
#define DD 768
#define HH 12
#define HD 64
#define KK 128
#define RR 5
#define MM 4
#define PP 1024              // N - R
#define CC 133               // R + K

#define MPAD_X 65920         // 515*128  (>= B*N = 65856)
#define MPAD_C 8576          // 67*128   (>= B*C = 8512)

// output layout: [out (B*N*D)] [cls_n (B*D)] [idx (B)]
#define OUT_CLS ((long)BB * NN_TOK * DD)
#define OUT_IDX (OUT_CLS + (long)BB * DD)

// ---------------- scratch (device globals; no allocs allowed) ----------------
__device__ int   g_idx[BB];
__device__ float g_scores[(long)BB * KK * PP];
__device__ float g_kv[(long)BB * CC * 2 * DD];
__device__ float g_q[(long)BB * NN_TOK * DD];

// bf16 split buffers (zero-init covers padding rows)
__device__ __nv_bfloat16 g_x_hi[(long)MPAD_X * DD];
__device__ __nv_bfloat16 g_x_lo[(long)MPAD_X * DD];
__device__ __nv_bfloat16 g_y_hi[(long)MPAD_X * DD];
__device__ __nv_bfloat16 g_y_lo[(long)MPAD_X * DD];
__device__ __nv_bfloat16 g_c_hi[(long)MPAD_C * DD];
__device__ __nv_bfloat16 g_c_lo[(long)MPAD_C * DD];
__device__ __nv_bfloat16 g_s_hi[(long)BB * KK * PP];   // attn weights hi
__device__ __nv_bfloat16 g_s_lo[(long)BB * KK * PP];   // attn weights lo
__device__ __nv_bfloat16 g_qb_hi[(long)MM * KK * DD];
__device__ __nv_bfloat16 g_qb_lo[(long)MM * KK * DD];
__device__ __nv_bfloat16 g_wq_hi[DD * DD];
__device__ __nv_bfloat16 g_wq_lo[DD * DD];
__device__ __nv_bfloat16 g_wo_hi[DD * DD];
__device__ __nv_bfloat16 g_wo_lo[DD * DD];
__device__ __nv_bfloat16 g_wc_hi[2 * DD * DD];
__device__ __nv_bfloat16 g_wc_lo[2 * DD * DD];

// ---------------- PTX helpers ----------------
__device__ __forceinline__ uint32_t smem_u32(const void* p) {
    uint32_t a;
    asm("{ .reg .u64 t; cvta.to.shared.u64 t, %1; cvt.u32.u64 %0, t; }" : "=r"(a) : "l"(p));
    return a;
}
__device__ __forceinline__ void cpasync16(uint32_t dst, const void* src) {
    asm volatile("cp.async.cg.shared.global [%0], [%1], 16;" :: "r"(dst), "l"(src));
}
#define CP_COMMIT() asm volatile("cp.async.commit_group;" ::: "memory")
#define CP_WAIT1()  asm volatile("cp.async.wait_group 1;" ::: "memory")
#define CP_WAIT0()  asm volatile("cp.async.wait_group 0;" ::: "memory")

__device__ __forceinline__ void ldsm4(uint32_t* r, uint32_t addr) {
    asm volatile("ldmatrix.sync.aligned.m8n8.x4.shared.b16 {%0,%1,%2,%3}, [%4];"
        : "=r"(r[0]), "=r"(r[1]), "=r"(r[2]), "=r"(r[3]) : "r"(addr));
}
__device__ __forceinline__ void ldsm4t(uint32_t* r, uint32_t addr) {
    asm volatile("ldmatrix.sync.aligned.m8n8.x4.trans.shared.b16 {%0,%1,%2,%3}, [%4];"
        : "=r"(r[0]), "=r"(r[1]), "=r"(r[2]), "=r"(r[3]) : "r"(addr));
}
__device__ __forceinline__ void mma_bf16(float* c, const uint32_t* a, const uint32_t* b) {
    asm volatile(
        "mma.sync.aligned.m16n8k16.row.col.f32.bf16.bf16.f32 "
        "{%0,%1,%2,%3}, {%4,%5,%6,%7}, {%8,%9}, {%0,%1,%2,%3};"
        : "+f"(c[0]), "+f"(c[1]), "+f"(c[2]), "+f"(c[3])
        : "r"(a[0]), "r"(a[1]), "r"(a[2]), "r"(a[3]), "r"(b[0]), "r"(b[1]));
}

// split a float pair into bf16 hi/lo and store packed
__device__ __forceinline__ void split2_store(
    __nv_bfloat16* __restrict__ H, __nv_bfloat16* __restrict__ L, long off, float v0, float v1)
{
    __nv_bfloat16 h0 = __float2bfloat16(v0);
    __nv_bfloat16 h1 = __float2bfloat16(v1);
    __nv_bfloat16 l0 = __float2bfloat16(v0 - __bfloat162float(h0));
    __nv_bfloat16 l1 = __float2bfloat16(v1 - __bfloat162float(h1));
    uint32_t hw = (uint32_t)*reinterpret_cast<unsigned short*>(&h0)
                | ((uint32_t)*reinterpret_cast<unsigned short*>(&h1) << 16);
    uint32_t lw = (uint32_t)*reinterpret_cast<unsigned short*>(&l0)
                | ((uint32_t)*reinterpret_cast<unsigned short*>(&l1) << 16);
    *reinterpret_cast<uint32_t*>(H + off) = hw;
    *reinterpret_cast<uint32_t*>(L + off) = lw;
}

// ---------------- NT HMMA GEMM, fp32 via bf16 3-split, 2-stage (2 CTA/SM) ---
// C[m,n] (+= bias[n]) = sum_k A[m,k] * B[n,k]
#define LDSB 80                    // smem bytes per A/B-NT tile row (32 bf16 + pad)
#define TILE_B (128 * LDSB)        // 10240
#define STAGE_B (4 * TILE_B)       // 40960
#define GEMM_SMEM (2 * STAGE_B)    // 81920  -> 2 CTAs/SM

template<bool BIAS, bool GATHER>
__global__ void __launch_bounds__(256) gemm_mma(
    const __nv_bfloat16* __restrict__ Ahb, const __nv_bfloat16* __restrict__ Alb,
    const __nv_bfloat16* __restrict__ Bhb, const __nv_bfloat16* __restrict__ Blb,
    const float* __restrict__ bias, float* __restrict__ Cb,
    int M, int Ntot, int Kd,
    long sA, long sB, long sC,
    const int* __restrict__ idxmap)
{
    extern __shared__ char smem[];
    uint32_t sb = smem_u32(smem);

    int tid = threadIdx.x, wid = tid >> 5, lane = tid & 31;
    int warp_m = wid & 3, warp_n = wid >> 2;
    int bz = blockIdx.z;
    long aoff = GATHER ? (long)idxmap[bz] * sA : (long)bz * sA;
    const __nv_bfloat16* Ah = Ahb + aoff;
    const __nv_bfloat16* Al = Alb + aoff;
    const __nv_bfloat16* Bh = Bhb + (long)bz * sB;
    const __nv_bfloat16* Bl = Blb + (long)bz * sB;
    float* C = Cb + (long)bz * sC;

    int m0 = blockIdx.y * 128;
    int n0 = blockIdx.x * 128;

    float acc[2][8][4];
#pragma unroll
    for (int i = 0; i < 2; i++)
#pragma unroll
        for (int j = 0; j < 8; j++)
#pragma unroll
            for (int k = 0; k < 4; k++) acc[i][j][k] = 0.f;

    const int nch = Kd / 32;

    auto issue = [&](int ch) {
        uint32_t st = sb + (ch & 1) * STAGE_B;
        int k0 = ch * 32;
#pragma unroll
        for (int it = 0; it < 2; it++) {
            int idx = tid + it * 256;
            int r = idx >> 2, c = idx & 3;
            uint32_t so = r * LDSB + c * 16;
            long gA = (long)(m0 + r) * Kd + k0 + c * 8;
            long gB = (long)(n0 + r) * Kd + k0 + c * 8;
            cpasync16(st + so,              Ah + gA);
            cpasync16(st + TILE_B + so,     Al + gA);
            cpasync16(st + 2 * TILE_B + so, Bh + gB);
            cpasync16(st + 3 * TILE_B + so, Bl + gB);
        }
        CP_COMMIT();
    };

    issue(0);
    if (nch > 1) issue(1);

    int lr = lane & 15, lc = lane >> 4;

    for (int ch = 0; ch < nch; ch++) {
        if (ch < nch - 1) { CP_WAIT1(); } else { CP_WAIT0(); }
        __syncthreads();

        uint32_t stg = sb + (ch & 1) * STAGE_B;
        uint32_t Ah_s = stg;
        uint32_t Al_s = stg + TILE_B;
        uint32_t Bh_s = stg + 2 * TILE_B;
        uint32_t Bl_s = stg + 3 * TILE_B;

#pragma unroll
        for (int ks = 0; ks < 2; ks++) {
            uint32_t koff = ks * 32 + lc * 16;
            uint32_t ah[2][4], al[2][4], bh[8][2], bl[8][2];
#pragma unroll
            for (int mf = 0; mf < 2; mf++) {
                uint32_t row = warp_m * 32 + mf * 16 + lr;
                ldsm4(ah[mf], Ah_s + row * LDSB + koff);
                ldsm4(al[mf], Al_s + row * LDSB + koff);
            }
#pragma unroll
            for (int p = 0; p < 4; p++) {
                uint32_t row = warp_n * 64 + p * 16 + lr;
                uint32_t t[4];
                ldsm4(t, Bh_s + row * LDSB + koff);
                bh[2 * p][0] = t[0]; bh[2 * p][1] = t[2];
                bh[2 * p + 1][0] = t[1]; bh[2 * p + 1][1] = t[3];
                ldsm4(t, Bl_s + row * LDSB + koff);
                bl[2 * p][0] = t[0]; bl[2 * p][1] = t[2];
                bl[2 * p + 1][0] = t[1]; bl[2 * p + 1][1] = t[3];
            }
#pragma unroll
            for (int mf = 0; mf < 2; mf++)
#pragma unroll
                for (int nf = 0; nf < 8; nf++) {
                    mma_bf16(acc[mf][nf], ah[mf], bh[nf]);
                    mma_bf16(acc[mf][nf], ah[mf], bl[nf]);
                    mma_bf16(acc[mf][nf], al[mf], bh[nf]);
                }
        }
        __syncthreads();
        if (ch + 2 < nch) issue(ch + 2);
    }

#pragma unroll
    for (int mf = 0; mf < 2; mf++) {
        int row0 = m0 + warp_m * 32 + mf * 16 + (lane >> 2);
#pragma unroll
        for (int nf = 0; nf < 8; nf++) {
            int col = n0 + warp_n * 64 + nf * 8 + (lane & 3) * 2;
            float b0 = 0.f, b1 = 0.f;
            if (BIAS) { b0 = bias[col]; b1 = bias[col + 1]; }
            if (row0 < M) {
                float2 v = make_float2(acc[mf][nf][0] + b0, acc[mf][nf][1] + b1);
                *reinterpret_cast<float2*>(&C[(long)row0 * Ntot + col]) = v;
            }
            if (row0 + 8 < M) {
                float2 v = make_float2(acc[mf][nf][2] + b0, acc[mf][nf][3] + b1);
                *reinterpret_cast<float2*>(&C[(long)(row0 + 8) * Ntot + col]) = v;
            }
        }
    }
}

// ---------------- NN HMMA GEMM (B row-major [k][n]), split bf16 output -------
// C[m,n] = sum_k A[m,k] * B[k,n];  M = 128 fixed; output written as hi/lo bf16.
#define LDSB_N 272                       // 128 bf16 (256B) + 16B pad
#define NTILE_B (32 * LDSB_N)            // 8704
#define NSTAGE_B (2 * TILE_B + 2 * NTILE_B)   // 37888
#define NN_SMEM (2 * NSTAGE_B)           // 75776 -> 2 CTAs/SM

__global__ void __launch_bounds__(256) gemm_mma_nn(
    const __nv_bfloat16* __restrict__ Ahb, const __nv_bfloat16* __restrict__ Alb,
    const __nv_bfloat16* __restrict__ Bhb, const __nv_bfloat16* __restrict__ Blb,
    __nv_bfloat16* __restrict__ Chb, __nv_bfloat16* __restrict__ Clb,
    int Ntot, int Kd, int ldB,
    long sA, long sB, long sC)
{
    extern __shared__ char smem[];
    uint32_t sb = smem_u32(smem);

    int tid = threadIdx.x, wid = tid >> 5, lane = tid & 31;
    int warp_m = wid & 3, warp_n = wid >> 2;
    int bz = blockIdx.z;
    const __nv_bfloat16* Ah = Ahb + (long)bz * sA;
    const __nv_bfloat16* Al = Alb + (long)bz * sA;
    const __nv_bfloat16* Bh = Bhb + (long)bz * sB;
    const __nv_bfloat16* Bl = Blb + (long)bz * sB;
    __nv_bfloat16* Ch = Chb + (long)bz * sC;
    __nv_bfloat16* Cl = Clb + (long)bz * sC;

    int n0 = blockIdx.x * 128;

    float acc[2][8][4];
#pragma unroll
    for (int i = 0; i < 2; i++)
#pragma unroll
        for (int j = 0; j < 8; j++)
#pragma unroll
            for (int k = 0; k < 4; k++) acc[i][j][k] = 0.f;

    const int nch = Kd / 32;

    auto issue = [&](int ch) {
        uint32_t st = sb + (ch & 1) * NSTAGE_B;
        int k0 = ch * 32;
        // A hi/lo: 128 rows x 32 k
#pragma unroll
        for (int it = 0; it < 2; it++) {
            int idx = tid + it * 256;
            int r = idx >> 2, c = idx & 3;
            uint32_t so = r * LDSB + c * 16;
            long gA = (long)r * Kd + k0 + c * 8;
            cpasync16(st + so,          Ah + gA);
            cpasync16(st + TILE_B + so, Al + gA);
        }
        // B hi/lo: 32 k-rows x 128 n
#pragma unroll
        for (int it = 0; it < 2; it++) {
            int idx = tid + it * 256;
            int r = idx >> 4, c = idx & 15;
            uint32_t so = 2 * TILE_B + r * LDSB_N + c * 16;
            long gB = (long)(k0 + r) * ldB + n0 + c * 8;
            cpasync16(st + so,           Bh + gB);
            cpasync16(st + so + NTILE_B, Bl + gB);
        }
        CP_COMMIT();
    };

    issue(0);
    if (nch > 1) issue(1);

    int lr = lane & 15, lc = lane >> 4;
    int l8 = (lane >> 3) & 1;
    int krow = ((lane >> 4) & 1) * 8 + (lane & 7);   // 0..15

    for (int ch = 0; ch < nch; ch++) {
        if (ch < nch - 1) { CP_WAIT1(); } else { CP_WAIT0(); }
        __syncthreads();

        uint32_t stg = sb + (ch & 1) * NSTAGE_B;
        uint32_t Ah_s = stg;
        uint32_t Al_s = stg + TILE_B;
        uint32_t Bh_s = stg + 2 * TILE_B;
        uint32_t Bl_s = Bh_s + NTILE_B;

#pragma unroll
        for (int ks = 0; ks < 2; ks++) {
            uint32_t koff = ks * 32 + lc * 16;
            uint32_t ah[2][4], al[2][4], bh[8][2], bl[8][2];
#pragma unroll
            for (int mf = 0; mf < 2; mf++) {
                uint32_t row = warp_m * 32 + mf * 16 + lr;
                ldsm4(ah[mf], Ah_s + row * LDSB + koff);
                ldsm4(al[mf], Al_s + row * LDSB + koff);
            }
            // B via ldmatrix.trans from [k][n] tiles
            uint32_t brow = (ks * 16 + krow) * LDSB_N + warp_n * 128 + l8 * 16;
#pragma unroll
            for (int p = 0; p < 4; p++) {
                uint32_t t[4];
                ldsm4t(t, Bh_s + brow + p * 32);
                bh[2 * p][0] = t[0]; bh[2 * p][1] = t[2];
                bh[2 * p + 1][0] = t[1]; bh[2 * p + 1][1] = t[3];
                ldsm4t(t, Bl_s + brow + p * 32);
                bl[2 * p][0] = t[0]; bl[2 * p][1] = t[2];
                bl[2 * p + 1][0] = t[1]; bl[2 * p + 1][1] = t[3];
            }
#pragma unroll
            for (int mf = 0; mf < 2; mf++)
#pragma unroll
                for (int nf = 0; nf < 8; nf++) {
                    mma_bf16(acc[mf][nf], ah[mf], bh[nf]);
                    mma_bf16(acc[mf][nf], ah[mf], bl[nf]);
                    mma_bf16(acc[mf][nf], al[mf], bh[nf]);
                }
        }
        __syncthreads();
        if (ch + 2 < nch) issue(ch + 2);
    }

    // epilogue: split to bf16 hi/lo (M = 128 exact, no bounds checks)
#pragma unroll
    for (int mf = 0; mf < 2; mf++) {
        int row0 = warp_m * 32 + mf * 16 + (lane >> 2);
#pragma unroll
        for (int nf = 0; nf < 8; nf++) {
            int col = n0 + warp_n * 64 + nf * 8 + (lane & 3) * 2;
            split2_store(Ch, Cl, (long)row0 * Ntot + col, acc[mf][nf][0], acc[mf][nf][1]);
            split2_store(Ch, Cl, (long)(row0 + 8) * Ntot + col, acc[mf][nf][2], acc[mf][nf][3]);
        }
    }
}

// ---------------- split fp32 -> bf16 hi/lo (8 elems / thread) ----------------
__global__ __launch_bounds__(256) void split_kernel(
    const float4* __restrict__ in, uint4* __restrict__ hi, uint4* __restrict__ lo, long n8)
{
    long i = (long)blockIdx.x * 256 + threadIdx.x;
    if (i >= n8) return;
    float4 a = in[2 * i], b = in[2 * i + 1];
    float v[8] = { a.x, a.y, a.z, a.w, b.x, b.y, b.z, b.w };
    uint32_t hw[8], lw[8];
#pragma unroll
    for (int j = 0; j < 8; j++) {
        __nv_bfloat16 h = __float2bfloat16(v[j]);
        __nv_bfloat16 l = __float2bfloat16(v[j] - __bfloat162float(h));
        hw[j] = *reinterpret_cast<unsigned short*>(&h);
        lw[j] = *reinterpret_cast<unsigned short*>(&l);
    }
    uint4 H, L;
    H.x = hw[0] | (hw[1] << 16); H.y = hw[2] | (hw[3] << 16);
    H.z = hw[4] | (hw[5] << 16); H.w = hw[6] | (hw[7] << 16);
    L.x = lw[0] | (lw[1] << 16); L.y = lw[2] | (lw[3] << 16);
    L.z = lw[4] | (lw[5] << 16); L.w = lw[6] | (lw[7] << 16);
    hi[i] = H; lo[i] = L;
}

// ---------------- transpose + split weights: W[Kd,Nc] -> WT[Nc,Kd] ----------
__global__ __launch_bounds__(256) void tsplit_kernel(
    const float* __restrict__ W, __nv_bfloat16* __restrict__ hiT,
    __nv_bfloat16* __restrict__ loT, int Kd, int Nc)
{
    int idx = blockIdx.x * 256 + threadIdx.x;
    if (idx >= Kd * Nc) return;
    int k = idx / Nc, n = idx % Nc;
    float a = W[idx];
    __nv_bfloat16 h = __float2bfloat16(a);
    __nv_bfloat16 l = __float2bfloat16(a - __bfloat162float(h));
    hiT[(long)n * Kd + k] = h;
    loT[(long)n * Kd + k] = l;
}

// ---------------- kernel 1: cls_n, sims, argmax ----------------
__global__ __launch_bounds__(256) void cls_kernel(
    const float* __restrict__ x, const float* __restrict__ cents,
    float* __restrict__ out_cls, float* __restrict__ out_idx, int* __restrict__ idx)
{
    int b = blockIdx.x;
    int t = threadIdx.x;
    __shared__ float red[256];
    __shared__ float snorm;
    __shared__ float best_s;
    __shared__ int best_i;

    const float* xr = x + (long)b * NN_TOK * DD;
    float loc[3];
    float ss = 0.f;
#pragma unroll
    for (int i = 0; i < 3; i++) { loc[i] = xr[t + i * 256]; ss += loc[i] * loc[i]; }
    red[t] = ss; __syncthreads();
    for (int s = 128; s > 0; s >>= 1) { if (t < s) red[t] += red[t + s]; __syncthreads(); }
    if (t == 0) snorm = fmaxf(sqrtf(red[0]), 1e-12f);
    __syncthreads();
    float inv = 1.0f / snorm;
    float c[3];
#pragma unroll
    for (int i = 0; i < 3; i++) {
        c[i] = loc[i] * inv;
        out_cls[(long)b * DD + t + i * 256] = c[i];
    }
    if (t == 0) { best_s = -1e30f; best_i = 0; }
    __syncthreads();
    for (int m = 0; m < MM; m++) {
        float p = 0.f;
#pragma unroll
        for (int i = 0; i < 3; i++) p += c[i] * cents[(long)m * DD + t + i * 256];
        red[t] = p; __syncthreads();
        for (int s = 128; s > 0; s >>= 1) { if (t < s) red[t] += red[t + s]; __syncthreads(); }
        if (t == 0) { if (red[0] > best_s) { best_s = red[0]; best_i = m; } }
        __syncthreads();
    }
    if (t == 0) { idx[b] = best_i; out_idx[b] = (float)best_i; }
}

// ---------------- softmax over rows of length 1024, emit bf16 hi/lo ---------
__global__ __launch_bounds__(256) void softmax1024_split(
    const float* __restrict__ s, __nv_bfloat16* __restrict__ oh, __nv_bfloat16* __restrict__ ol)
{
    long row = blockIdx.x;
    const float* p = s + row * PP;
    int t = threadIdx.x;
    __shared__ float red[256];

    float4 v = reinterpret_cast<const float4*>(p)[t];
    float mx = fmaxf(fmaxf(v.x, v.y), fmaxf(v.z, v.w));
    red[t] = mx; __syncthreads();
    for (int st = 128; st > 0; st >>= 1) { if (t < st) red[t] = fmaxf(red[t], red[t + st]); __syncthreads(); }
    mx = red[0]; __syncthreads();

    v.x = expf(v.x - mx); v.y = expf(v.y - mx);
    v.z = expf(v.z - mx); v.w = expf(v.w - mx);
    float sm = v.x + v.y + v.z + v.w;
    red[t] = sm; __syncthreads();
    for (int st = 128; st > 0; st >>= 1) { if (t < st) red[t] += red[t + st]; __syncthreads(); }
    float inv = 1.0f / red[0];
    v.x *= inv; v.y *= inv; v.z *= inv; v.w *= inv;

    long off = row * PP + (long)t * 4;
    split2_store(oh, ol, off,     v.x, v.y);
    split2_store(oh, ol, off + 2, v.z, v.w);
}

// ---------------- copy x[:, :R, :] into ctx hi/lo rows 0..R-1 ---------------
__global__ __launch_bounds__(256) void copy_xreg_split(
    const float* __restrict__ x, __nv_bfloat16* __restrict__ ch, __nv_bfloat16* __restrict__ cl)
{
    long i = (long)blockIdx.x * blockDim.x + threadIdx.x;   // float4 index
    long total = (long)BB * RR * DD / 4;
    if (i >= total) return;
    long per_b = (long)RR * DD / 4;
    long b = i / per_b;
    long r = i - b * per_b;
    float4 v = reinterpret_cast<const float4*>(x)[b * ((long)NN_TOK * DD / 4) + r];
    long off = b * (long)CC * DD + r * 4;
    split2_store(ch, cl, off,     v.x, v.y);
    split2_store(ch, cl, off + 2, v.z, v.w);
}

// ---------------- attention: one (b,h) per block, no-max online softmax -----
// scores here are bounded (|q.k|/8 << 88), so exp without max subtraction is safe.
__global__ __launch_bounds__(256) void attn_kernel(
    const float* __restrict__ q, const float* __restrict__ kv,
    __nv_bfloat16* __restrict__ yh, __nv_bfloat16* __restrict__ yl)
{
    extern __shared__ float sh[];
    float* sk = sh;
    float* sv = sh + CC * HD;
    int b = blockIdx.x / HH;
    int h = blockIdx.x % HH;
    int tid = threadIdx.x;

    for (int i = tid; i < CC * 16; i += 256) {
        int m = i >> 4;
        int jc = (i & 15) * 4;
        long base = ((long)(b * CC + m)) * (2 * DD) + h * HD + jc;
        *reinterpret_cast<float4*>(&sk[m * HD + jc]) = *reinterpret_cast<const float4*>(&kv[base]);
        *reinterpret_cast<float4*>(&sv[m * HD + jc]) = *reinterpret_cast<const float4*>(&kv[base + DD]);
    }
    __syncthreads();

    const float scale = 0.125f;  // 1/sqrt(64), folded into q
    for (int nb = 0; nb < NN_TOK; nb += 256) {
        int n = nb + tid;
        if (n >= NN_TOK) break;
        const float* qp = q + ((long)(b * NN_TOK + n)) * DD + h * HD;
        float qr[HD];
#pragma unroll
        for (int j = 0; j < HD; j += 4) {
            float4 t4 = *reinterpret_cast<const float4*>(&qp[j]);
            qr[j] = t4.x * scale; qr[j + 1] = t4.y * scale;
            qr[j + 2] = t4.z * scale; qr[j + 3] = t4.w * scale;
        }

        float acc[HD];
#pragma unroll
        for (int j = 0; j < HD; j++) acc[j] = 0.f;
        float lsum = 0.f;

        for (int m = 0; m < CC; m++) {
            const float* kp = &sk[m * HD];
            float s0 = 0.f, s1 = 0.f, s2 = 0.f, s3 = 0.f;
#pragma unroll
            for (int j = 0; j < HD; j += 4) {
                float4 kv4 = *reinterpret_cast<const float4*>(&kp[j]);
                s0 += qr[j] * kv4.x; s1 += qr[j + 1] * kv4.y;
                s2 += qr[j + 2] * kv4.z; s3 += qr[j + 3] * kv4.w;
            }
            float e = __expf((s0 + s1) + (s2 + s3));
            lsum += e;
            const float* vp = &sv[m * HD];
#pragma unroll
            for (int j = 0; j < HD; j += 4) {
                float4 vv = *reinterpret_cast<const float4*>(&vp[j]);
                acc[j] += e * vv.x; acc[j + 1] += e * vv.y;
                acc[j + 2] += e * vv.z; acc[j + 3] += e * vv.w;
            }
        }
        float inv = 1.0f / lsum;
        long ybase = ((long)(b * NN_TOK + n)) * DD + h * HD;
#pragma unroll
        for (int j = 0; j < HD; j += 2)
            split2_store(yh, yl, ybase + j, acc[j] * inv, acc[j + 1] * inv);
    }
}

// ---------------- launch ----------------
extern "C" void kernel_launch(void* const* d_in, const int* in_sizes, int n_in,
                              void* d_out, int out_size)
{
    const float* x      = (const float*)d_in[0];
    const float* Qb     = (const float*)d_in[1];
    const float* Wq     = (const float*)d_in[2];
    const float* Wctx   = (const float*)d_in[3];
    const float* bctx   = (const float*)d_in[4];
    const float* Wout   = (const float*)d_in[5];
    const float* bout   = (const float*)d_in[6];
    const float* cents  = (const float*)d_in[7];
    float* out = (float*)d_out;

    void *p_idx, *p_scores, *p_kv, *p_q;
    void *p_xh, *p_xl, *p_yh, *p_yl, *p_ch, *p_cl, *p_sh, *p_sl;
    void *p_qbh, *p_qbl, *p_wqh, *p_wql, *p_woh, *p_wol, *p_wch, *p_wcl;
    cudaGetSymbolAddress(&p_idx, g_idx);
    cudaGetSymbolAddress(&p_scores, g_scores);
    cudaGetSymbolAddress(&p_kv, g_kv);
    cudaGetSymbolAddress(&p_q, g_q);
    cudaGetSymbolAddress(&p_xh, g_x_hi);  cudaGetSymbolAddress(&p_xl, g_x_lo);
    cudaGetSymbolAddress(&p_yh, g_y_hi);  cudaGetSymbolAddress(&p_yl, g_y_lo);
    cudaGetSymbolAddress(&p_ch, g_c_hi);  cudaGetSymbolAddress(&p_cl, g_c_lo);
    cudaGetSymbolAddress(&p_sh, g_s_hi);  cudaGetSymbolAddress(&p_sl, g_s_lo);
    cudaGetSymbolAddress(&p_qbh, g_qb_hi); cudaGetSymbolAddress(&p_qbl, g_qb_lo);
    cudaGetSymbolAddress(&p_wqh, g_wq_hi); cudaGetSymbolAddress(&p_wql, g_wq_lo);
    cudaGetSymbolAddress(&p_woh, g_wo_hi); cudaGetSymbolAddress(&p_wol, g_wo_lo);
    cudaGetSymbolAddress(&p_wch, g_wc_hi); cudaGetSymbolAddress(&p_wcl, g_wc_lo);

    int*   idxp   = (int*)p_idx;
    float* scores = (float*)p_scores;
    float* kvp    = (float*)p_kv;
    float* qp     = (float*)p_q;
    __nv_bfloat16 *xh = (__nv_bfloat16*)p_xh, *xl = (__nv_bfloat16*)p_xl;
    __nv_bfloat16 *yh = (__nv_bfloat16*)p_yh, *yl = (__nv_bfloat16*)p_yl;
    __nv_bfloat16 *ch = (__nv_bfloat16*)p_ch, *cl = (__nv_bfloat16*)p_cl;
    __nv_bfloat16 *shp = (__nv_bfloat16*)p_sh, *slp = (__nv_bfloat16*)p_sl;
    __nv_bfloat16 *qbh = (__nv_bfloat16*)p_qbh, *qbl = (__nv_bfloat16*)p_qbl;
    __nv_bfloat16 *wqh = (__nv_bfloat16*)p_wqh, *wql = (__nv_bfloat16*)p_wql;
    __nv_bfloat16 *woh = (__nv_bfloat16*)p_woh, *wol = (__nv_bfloat16*)p_wol;
    __nv_bfloat16 *wch = (__nv_bfloat16*)p_wch, *wcl = (__nv_bfloat16*)p_wcl;

    cudaFuncSetAttribute(gemm_mma<false, false>, cudaFuncAttributeMaxDynamicSharedMemorySize, GEMM_SMEM);
    cudaFuncSetAttribute(gemm_mma<true, false>,  cudaFuncAttributeMaxDynamicSharedMemorySize, GEMM_SMEM);
    cudaFuncSetAttribute(gemm_mma<false, true>,  cudaFuncAttributeMaxDynamicSharedMemorySize, GEMM_SMEM);
    cudaFuncSetAttribute(gemm_mma_nn, cudaFuncAttributeMaxDynamicSharedMemorySize, NN_SMEM);

    // 1. cls_n / idx
    cls_kernel<<<BB, 256>>>(x, cents, out + OUT_CLS, out + OUT_IDX, idxp);

    // 2. precision splits: x, Q_banks, weights (transposed)
    {
        long n8 = (long)BB * NN_TOK * DD / 8;
        split_kernel<<<(unsigned)((n8 + 255) / 256), 256>>>(
            (const float4*)x, (uint4*)xh, (uint4*)xl, n8);
        long q8 = (long)MM * KK * DD / 8;
        split_kernel<<<(unsigned)((q8 + 255) / 256), 256>>>(
            (const float4*)Qb, (uint4*)qbh, (uint4*)qbl, q8);
        tsplit_kernel<<<(DD * DD + 255) / 256, 256>>>(Wq, wqh, wql, DD, DD);
        tsplit_kernel<<<(DD * DD + 255) / 256, 256>>>(Wout, woh, wol, DD, DD);
        tsplit_kernel<<<(DD * 2 * DD + 255) / 256, 256>>>(Wctx, wch, wcl, DD, 2 * DD);
    }

    // 3. scores[b] = Q_banks[idx[b]] @ xp[b]^T  (128 x 1024, K=768) — HMMA NT
    gemm_mma<false, true><<<dim3(PP / 128, 1, BB), 256, GEMM_SMEM>>>(
        qbh, qbl, xh + (long)RR * DD, xl + (long)RR * DD, nullptr, scores,
        KK, PP, DD,
        (long)KK * DD, (long)NN_TOK * DD, (long)KK * PP, idxp);

    // 4. softmax rows (B*K x 1024) -> bf16 hi/lo attn weights
    softmax1024_split<<<BB * KK, 256>>>(scores, shp, slp);

    // 5. ctx[:, :R] = xreg (split)
    {
        long total = (long)BB * RR * DD / 4;
        copy_xreg_split<<<(unsigned)((total + 255) / 256), 256>>>(x, ch, cl);
    }

    // 6. ctx[:, R:] = attn (128x1024) @ xp (1024x768) — HMMA NN, split output
    gemm_mma_nn<<<dim3(DD / 128, 1, BB), 256, NN_SMEM>>>(
        shp, slp, xh + (long)RR * DD, xl + (long)RR * DD,
        ch + (long)RR * DD, cl + (long)RR * DD,
        DD, PP, DD,
        (long)KK * PP, (long)NN_TOK * DD, (long)CC * DD);

    // 7. kv = ctx (8512x768) @ Wctx + bctx — HMMA NT
    gemm_mma<true, false><<<dim3(2 * DD / 128, MPAD_C / 128, 1), 256, GEMM_SMEM>>>(
        ch, cl, wch, wcl, bctx, kvp,
        BB * CC, 2 * DD, DD, 0, 0, 0, nullptr);

    // 8. q = x (65856x768) @ Wq — HMMA NT
    gemm_mma<false, false><<<dim3(DD / 128, MPAD_X / 128, 1), 256, GEMM_SMEM>>>(
        xh, xl, wqh, wql, nullptr, qp,
        BB * NN_TOK, DD, DD, 0, 0, 0, nullptr);

    // 9. attention -> y hi/lo (SIMT, no-max online softmax)
    {
        int smem = CC * HD * 2 * (int)sizeof(float);
        cudaFuncSetAttribute(attn_kernel, cudaFuncAttributeMaxDynamicSharedMemorySize, smem);
        attn_kernel<<<BB * HH, 256, smem>>>(qp, kvp, yh, yl);
    }

    // 10. out = y @ Wout + bout — HMMA NT
    gemm_mma<true, false><<<dim3(DD / 128, MPAD_X / 128, 1), 256, GEMM_SMEM>>>(
        yh, yl, woh, wol, bout, out,
        BB * NN_TOK, DD, DD, 0, 0, 0, nullptr);
}

// round 6
// speedup vs baseline: 1.4918x; 1.3679x over previous
#include <cuda_runtime.h>
#include <cuda_bf16.h>
#include <math.h>
#include <stdint.h>

// ---------------- problem constants ----------------
#define BB 64
#define NN_TOK 1029
#define DD 768
#define HH 12
#define HD 64
#define KK 128
#define RR 5
#define MM 4
#define PP 1024              // N - R
#define CC 133               // R + K

#define MPAD_X 65920         // 515*128  (>= B*N = 65856)
#define MPAD_C 8576          // 67*128   (>= B*C = 8512)

// output layout: [out (B*N*D)] [cls_n (B*D)] [idx (B)]
#define OUT_CLS ((long)BB * NN_TOK * DD)
#define OUT_IDX (OUT_CLS + (long)BB * DD)

// ---------------- scratch (device globals; no allocs allowed) ----------------
__device__ int   g_idx[BB];
__device__ float g_scores[(long)BB * KK * PP];

// bf16 split buffers (zero-init covers padding rows)
__device__ __nv_bfloat16 g_x_hi[(long)MPAD_X * DD];
__device__ __nv_bfloat16 g_x_lo[(long)MPAD_X * DD];
__device__ __nv_bfloat16 g_y_hi[(long)MPAD_X * DD];
__device__ __nv_bfloat16 g_y_lo[(long)MPAD_X * DD];
__device__ __nv_bfloat16 g_q_hi[(long)MPAD_X * DD];
__device__ __nv_bfloat16 g_q_lo[(long)MPAD_X * DD];
__device__ __nv_bfloat16 g_kv_hi[(long)MPAD_C * 2 * DD];
__device__ __nv_bfloat16 g_kv_lo[(long)MPAD_C * 2 * DD];
__device__ __nv_bfloat16 g_c_hi[(long)MPAD_C * DD];
__device__ __nv_bfloat16 g_c_lo[(long)MPAD_C * DD];
__device__ __nv_bfloat16 g_s_hi[(long)BB * KK * PP];   // attn weights hi
__device__ __nv_bfloat16 g_s_lo[(long)BB * KK * PP];   // attn weights lo
__device__ __nv_bfloat16 g_qb_hi[(long)MM * KK * DD];
__device__ __nv_bfloat16 g_qb_lo[(long)MM * KK * DD];
__device__ __nv_bfloat16 g_wq_hi[DD * DD];
__device__ __nv_bfloat16 g_wq_lo[DD * DD];
__device__ __nv_bfloat16 g_wo_hi[DD * DD];
__device__ __nv_bfloat16 g_wo_lo[DD * DD];
__device__ __nv_bfloat16 g_wc_hi[2 * DD * DD];
__device__ __nv_bfloat16 g_wc_lo[2 * DD * DD];

// ---------------- PTX helpers ----------------
__device__ __forceinline__ uint32_t smem_u32(const void* p) {
    uint32_t a;
    asm("{ .reg .u64 t; cvta.to.shared.u64 t, %1; cvt.u32.u64 %0, t; }" : "=r"(a) : "l"(p));
    return a;
}
__device__ __forceinline__ void cpasync16(uint32_t dst, const void* src) {
    asm volatile("cp.async.cg.shared.global [%0], [%1], 16;" :: "r"(dst), "l"(src));
}
#define CP_COMMIT() asm volatile("cp.async.commit_group;" ::: "memory")
#define CP_WAIT1()  asm volatile("cp.async.wait_group 1;" ::: "memory")
#define CP_WAIT0()  asm volatile("cp.async.wait_group 0;" ::: "memory")

__device__ __forceinline__ void ldsm4(uint32_t* r, uint32_t addr) {
    asm volatile("ldmatrix.sync.aligned.m8n8.x4.shared.b16 {%0,%1,%2,%3}, [%4];"
        : "=r"(r[0]), "=r"(r[1]), "=r"(r[2]), "=r"(r[3]) : "r"(addr));
}
__device__ __forceinline__ void ldsm4t(uint32_t* r, uint32_t addr) {
    asm volatile("ldmatrix.sync.aligned.m8n8.x4.trans.shared.b16 {%0,%1,%2,%3}, [%4];"
        : "=r"(r[0]), "=r"(r[1]), "=r"(r[2]), "=r"(r[3]) : "r"(addr));
}
__device__ __forceinline__ void mma_bf16(float* c, const uint32_t* a, const uint32_t* b) {
    asm volatile(
        "mma.sync.aligned.m16n8k16.row.col.f32.bf16.bf16.f32 "
        "{%0,%1,%2,%3}, {%4,%5,%6,%7}, {%8,%9}, {%0,%1,%2,%3};"
        : "+f"(c[0]), "+f"(c[1]), "+f"(c[2]), "+f"(c[3])
        : "r"(a[0]), "r"(a[1]), "r"(a[2]), "r"(a[3]), "r"(b[0]), "r"(b[1]));
}

// split a float pair into bf16 hi/lo and store packed (global)
__device__ __forceinline__ void split2_store(
    __nv_bfloat16* __restrict__ H, __nv_bfloat16* __restrict__ L, long off, float v0, float v1)
{
    __nv_bfloat16 h0 = __float2bfloat16(v0);
    __nv_bfloat16 h1 = __float2bfloat16(v1);
    __nv_bfloat16 l0 = __float2bfloat16(v0 - __bfloat162float(h0));
    __nv_bfloat16 l1 = __float2bfloat16(v1 - __bfloat162float(h1));
    uint32_t hw = (uint32_t)*reinterpret_cast<unsigned short*>(&h0)
                | ((uint32_t)*reinterpret_cast<unsigned short*>(&h1) << 16);
    uint32_t lw = (uint32_t)*reinterpret_cast<unsigned short*>(&l0)
                | ((uint32_t)*reinterpret_cast<unsigned short*>(&l1) << 16);
    *reinterpret_cast<uint32_t*>(H + off) = hw;
    *reinterpret_cast<uint32_t*>(L + off) = lw;
}

// split a float pair into bf16 hi/lo and store to smem
__device__ __forceinline__ void split2_sts(uint32_t ah, uint32_t al_, float v0, float v1)
{
    __nv_bfloat16 h0 = __float2bfloat16(v0);
    __nv_bfloat16 h1 = __float2bfloat16(v1);
    __nv_bfloat16 l0 = __float2bfloat16(v0 - __bfloat162float(h0));
    __nv_bfloat16 l1 = __float2bfloat16(v1 - __bfloat162float(h1));
    uint32_t hw = (uint32_t)*reinterpret_cast<unsigned short*>(&h0)
                | ((uint32_t)*reinterpret_cast<unsigned short*>(&h1) << 16);
    uint32_t lw = (uint32_t)*reinterpret_cast<unsigned short*>(&l0)
                | ((uint32_t)*reinterpret_cast<unsigned short*>(&l1) << 16);
    asm volatile("st.shared.b32 [%0], %1;" :: "r"(ah), "r"(hw) : "memory");
    asm volatile("st.shared.b32 [%0], %1;" :: "r"(al_), "r"(lw) : "memory");
}

// ---------------- NT HMMA GEMM, fp32 via bf16 3-split, 2-stage (2 CTA/SM) ---
// C[m,n] (+= bias[n]) = sum_k A[m,k] * B[n,k]
#define LDSB 80                    // smem bytes per A/B-NT tile row (32 bf16 + pad)
#define TILE_B (128 * LDSB)        // 10240
#define STAGE_B (4 * TILE_B)       // 40960
#define GEMM_SMEM (2 * STAGE_B)    // 81920  -> 2 CTAs/SM

template<bool BIAS, bool GATHER, bool SPLITOUT>
__global__ void __launch_bounds__(256) gemm_mma(
    const __nv_bfloat16* __restrict__ Ahb, const __nv_bfloat16* __restrict__ Alb,
    const __nv_bfloat16* __restrict__ Bhb, const __nv_bfloat16* __restrict__ Blb,
    const float* __restrict__ bias, float* __restrict__ Cb,
    __nv_bfloat16* __restrict__ Chb, __nv_bfloat16* __restrict__ Clb,
    int M, int Ntot, int Kd,
    long sA, long sB, long sC,
    const int* __restrict__ idxmap)
{
    extern __shared__ char smem[];
    uint32_t sb = smem_u32(smem);

    int tid = threadIdx.x, wid = tid >> 5, lane = tid & 31;
    int warp_m = wid & 3, warp_n = wid >> 2;
    int bz = blockIdx.z;
    long aoff = GATHER ? (long)idxmap[bz] * sA : (long)bz * sA;
    const __nv_bfloat16* Ah = Ahb + aoff;
    const __nv_bfloat16* Al = Alb + aoff;
    const __nv_bfloat16* Bh = Bhb + (long)bz * sB;
    const __nv_bfloat16* Bl = Blb + (long)bz * sB;

    int m0 = blockIdx.y * 128;
    int n0 = blockIdx.x * 128;

    float acc[2][8][4];
#pragma unroll
    for (int i = 0; i < 2; i++)
#pragma unroll
        for (int j = 0; j < 8; j++)
#pragma unroll
            for (int k = 0; k < 4; k++) acc[i][j][k] = 0.f;

    const int nch = Kd / 32;

    auto issue = [&](int ch) {
        uint32_t st = sb + (ch & 1) * STAGE_B;
        int k0 = ch * 32;
#pragma unroll
        for (int it = 0; it < 2; it++) {
            int idx = tid + it * 256;
            int r = idx >> 2, c = idx & 3;
            uint32_t so = r * LDSB + c * 16;
            long gA = (long)(m0 + r) * Kd + k0 + c * 8;
            long gB = (long)(n0 + r) * Kd + k0 + c * 8;
            cpasync16(st + so,              Ah + gA);
            cpasync16(st + TILE_B + so,     Al + gA);
            cpasync16(st + 2 * TILE_B + so, Bh + gB);
            cpasync16(st + 3 * TILE_B + so, Bl + gB);
        }
        CP_COMMIT();
    };

    issue(0);
    if (nch > 1) issue(1);

    int lr = lane & 15, lc = lane >> 4;

    for (int ch = 0; ch < nch; ch++) {
        if (ch < nch - 1) { CP_WAIT1(); } else { CP_WAIT0(); }
        __syncthreads();

        uint32_t stg = sb + (ch & 1) * STAGE_B;
        uint32_t Ah_s = stg;
        uint32_t Al_s = stg + TILE_B;
        uint32_t Bh_s = stg + 2 * TILE_B;
        uint32_t Bl_s = stg + 3 * TILE_B;

#pragma unroll
        for (int ks = 0; ks < 2; ks++) {
            uint32_t koff = ks * 32 + lc * 16;
            uint32_t ah[2][4], al[2][4], bh[8][2], bl[8][2];
#pragma unroll
            for (int mf = 0; mf < 2; mf++) {
                uint32_t row = warp_m * 32 + mf * 16 + lr;
                ldsm4(ah[mf], Ah_s + row * LDSB + koff);
                ldsm4(al[mf], Al_s + row * LDSB + koff);
            }
#pragma unroll
            for (int p = 0; p < 4; p++) {
                uint32_t row = warp_n * 64 + p * 16 + lr;
                uint32_t t[4];
                ldsm4(t, Bh_s + row * LDSB + koff);
                bh[2 * p][0] = t[0]; bh[2 * p][1] = t[2];
                bh[2 * p + 1][0] = t[1]; bh[2 * p + 1][1] = t[3];
                ldsm4(t, Bl_s + row * LDSB + koff);
                bl[2 * p][0] = t[0]; bl[2 * p][1] = t[2];
                bl[2 * p + 1][0] = t[1]; bl[2 * p + 1][1] = t[3];
            }
#pragma unroll
            for (int mf = 0; mf < 2; mf++)
#pragma unroll
                for (int nf = 0; nf < 8; nf++) {
                    mma_bf16(acc[mf][nf], ah[mf], bh[nf]);
                    mma_bf16(acc[mf][nf], ah[mf], bl[nf]);
                    mma_bf16(acc[mf][nf], al[mf], bh[nf]);
                }
        }
        __syncthreads();
        if (ch + 2 < nch) issue(ch + 2);
    }

#pragma unroll
    for (int mf = 0; mf < 2; mf++) {
        int row0 = m0 + warp_m * 32 + mf * 16 + (lane >> 2);
#pragma unroll
        for (int nf = 0; nf < 8; nf++) {
            int col = n0 + warp_n * 64 + nf * 8 + (lane & 3) * 2;
            float b0 = 0.f, b1 = 0.f;
            if (BIAS) { b0 = bias[col]; b1 = bias[col + 1]; }
            if (SPLITOUT) {
                __nv_bfloat16* Ch = Chb + (long)blockIdx.z * sC;
                __nv_bfloat16* Cl = Clb + (long)blockIdx.z * sC;
                if (row0 < M)
                    split2_store(Ch, Cl, (long)row0 * Ntot + col,
                                 acc[mf][nf][0] + b0, acc[mf][nf][1] + b1);
                if (row0 + 8 < M)
                    split2_store(Ch, Cl, (long)(row0 + 8) * Ntot + col,
                                 acc[mf][nf][2] + b0, acc[mf][nf][3] + b1);
            } else {
                float* C = Cb + (long)blockIdx.z * sC;
                if (row0 < M) {
                    float2 v = make_float2(acc[mf][nf][0] + b0, acc[mf][nf][1] + b1);
                    *reinterpret_cast<float2*>(&C[(long)row0 * Ntot + col]) = v;
                }
                if (row0 + 8 < M) {
                    float2 v = make_float2(acc[mf][nf][2] + b0, acc[mf][nf][3] + b1);
                    *reinterpret_cast<float2*>(&C[(long)(row0 + 8) * Ntot + col]) = v;
                }
            }
        }
    }
}

// ---------------- NN HMMA GEMM (B row-major [k][n]), split bf16 output -------
// C[m,n] = sum_k A[m,k] * B[k,n];  M = 128 fixed; output written as hi/lo bf16.
#define LDSB_N 272                       // 128 bf16 (256B) + 16B pad
#define NTILE_B (32 * LDSB_N)            // 8704
#define NSTAGE_B (2 * TILE_B + 2 * NTILE_B)   // 37888
#define NN_SMEM (2 * NSTAGE_B)           // 75776 -> 2 CTAs/SM

__global__ void __launch_bounds__(256) gemm_mma_nn(
    const __nv_bfloat16* __restrict__ Ahb, const __nv_bfloat16* __restrict__ Alb,
    const __nv_bfloat16* __restrict__ Bhb, const __nv_bfloat16* __restrict__ Blb,
    __nv_bfloat16* __restrict__ Chb, __nv_bfloat16* __restrict__ Clb,
    int Ntot, int Kd, int ldB,
    long sA, long sB, long sC)
{
    extern __shared__ char smem[];
    uint32_t sb = smem_u32(smem);

    int tid = threadIdx.x, wid = tid >> 5, lane = tid & 31;
    int warp_m = wid & 3, warp_n = wid >> 2;
    int bz = blockIdx.z;
    const __nv_bfloat16* Ah = Ahb + (long)bz * sA;
    const __nv_bfloat16* Al = Alb + (long)bz * sA;
    const __nv_bfloat16* Bh = Bhb + (long)bz * sB;
    const __nv_bfloat16* Bl = Blb + (long)bz * sB;
    __nv_bfloat16* Ch = Chb + (long)bz * sC;
    __nv_bfloat16* Cl = Clb + (long)bz * sC;

    int n0 = blockIdx.x * 128;

    float acc[2][8][4];
#pragma unroll
    for (int i = 0; i < 2; i++)
#pragma unroll
        for (int j = 0; j < 8; j++)
#pragma unroll
            for (int k = 0; k < 4; k++) acc[i][j][k] = 0.f;

    const int nch = Kd / 32;

    auto issue = [&](int ch) {
        uint32_t st = sb + (ch & 1) * NSTAGE_B;
        int k0 = ch * 32;
#pragma unroll
        for (int it = 0; it < 2; it++) {
            int idx = tid + it * 256;
            int r = idx >> 2, c = idx & 3;
            uint32_t so = r * LDSB + c * 16;
            long gA = (long)r * Kd + k0 + c * 8;
            cpasync16(st + so,          Ah + gA);
            cpasync16(st + TILE_B + so, Al + gA);
        }
#pragma unroll
        for (int it = 0; it < 2; it++) {
            int idx = tid + it * 256;
            int r = idx >> 4, c = idx & 15;
            uint32_t so = 2 * TILE_B + r * LDSB_N + c * 16;
            long gB = (long)(k0 + r) * ldB + n0 + c * 8;
            cpasync16(st + so,           Bh + gB);
            cpasync16(st + so + NTILE_B, Bl + gB);
        }
        CP_COMMIT();
    };

    issue(0);
    if (nch > 1) issue(1);

    int lr = lane & 15, lc = lane >> 4;
    int l8 = (lane >> 3) & 1;
    int krow = ((lane >> 4) & 1) * 8 + (lane & 7);   // 0..15

    for (int ch = 0; ch < nch; ch++) {
        if (ch < nch - 1) { CP_WAIT1(); } else { CP_WAIT0(); }
        __syncthreads();

        uint32_t stg = sb + (ch & 1) * NSTAGE_B;
        uint32_t Ah_s = stg;
        uint32_t Al_s = stg + TILE_B;
        uint32_t Bh_s = stg + 2 * TILE_B;
        uint32_t Bl_s = Bh_s + NTILE_B;

#pragma unroll
        for (int ks = 0; ks < 2; ks++) {
            uint32_t koff = ks * 32 + lc * 16;
            uint32_t ah[2][4], al[2][4], bh[8][2], bl[8][2];
#pragma unroll
            for (int mf = 0; mf < 2; mf++) {
                uint32_t row = warp_m * 32 + mf * 16 + lr;
                ldsm4(ah[mf], Ah_s + row * LDSB + koff);
                ldsm4(al[mf], Al_s + row * LDSB + koff);
            }
            uint32_t brow = (ks * 16 + krow) * LDSB_N + warp_n * 128 + l8 * 16;
#pragma unroll
            for (int p = 0; p < 4; p++) {
                uint32_t t[4];
                ldsm4t(t, Bh_s + brow + p * 32);
                bh[2 * p][0] = t[0]; bh[2 * p][1] = t[2];
                bh[2 * p + 1][0] = t[1]; bh[2 * p + 1][1] = t[3];
                ldsm4t(t, Bl_s + brow + p * 32);
                bl[2 * p][0] = t[0]; bl[2 * p][1] = t[2];
                bl[2 * p + 1][0] = t[1]; bl[2 * p + 1][1] = t[3];
            }
#pragma unroll
            for (int mf = 0; mf < 2; mf++)
#pragma unroll
                for (int nf = 0; nf < 8; nf++) {
                    mma_bf16(acc[mf][nf], ah[mf], bh[nf]);
                    mma_bf16(acc[mf][nf], ah[mf], bl[nf]);
                    mma_bf16(acc[mf][nf], al[mf], bh[nf]);
                }
        }
        __syncthreads();
        if (ch + 2 < nch) issue(ch + 2);
    }

#pragma unroll
    for (int mf = 0; mf < 2; mf++) {
        int row0 = warp_m * 32 + mf * 16 + (lane >> 2);
#pragma unroll
        for (int nf = 0; nf < 8; nf++) {
            int col = n0 + warp_n * 64 + nf * 8 + (lane & 3) * 2;
            split2_store(Ch, Cl, (long)row0 * Ntot + col, acc[mf][nf][0], acc[mf][nf][1]);
            split2_store(Ch, Cl, (long)(row0 + 8) * Ntot + col, acc[mf][nf][2], acc[mf][nf][3]);
        }
    }
}

// ---------------- HMMA flash attention ----------------
// grid (9, HH, BB); 256 threads (8 warps x 16 q-rows).
// S = q@k^T (3-split), no-max exp, normalize, P@V (3-split) -> y hi/lo.
#define SKV 144
#define LDSK 144
#define LDSQ 144
#define LDSP 304
#define A_KH 0
#define A_KL (A_KH + SKV * LDSK)
#define A_VH (A_KL + SKV * LDSK)
#define A_VL (A_VH + SKV * LDSK)
#define A_QH (A_VL + SKV * LDSK)          // 82944
#define A_QL (A_QH + 128 * LDSQ)
#define A_PH A_QH                          // P reuses q region (after sync)
#define A_PL (A_PH + 128 * LDSP)
#define ATTN_SMEM (A_PL + 128 * LDSP)      // 160768

__global__ void __launch_bounds__(256) attn_mma(
    const __nv_bfloat16* __restrict__ qh_g, const __nv_bfloat16* __restrict__ ql_g,
    const __nv_bfloat16* __restrict__ kvh, const __nv_bfloat16* __restrict__ kvl,
    __nv_bfloat16* __restrict__ yh, __nv_bfloat16* __restrict__ yl)
{
    extern __shared__ char smem[];
    uint32_t sb = smem_u32(smem);
    int tid = threadIdx.x, wid = tid >> 5, lane = tid & 31;
    int n0 = blockIdx.x * 128;
    int h = blockIdx.y, b = blockIdx.z;

    // ---- loads: K/V rows (133) + q tile (128 rows) ----
    for (int i = tid; i < CC * 8; i += 256) {
        int m = i >> 3, c = i & 7;
        long g = ((long)(b * CC + m) * 2) * DD + h * HD + c * 8;
        uint32_t so = m * LDSK + c * 16;
        cpasync16(sb + A_KH + so, kvh + g);
        cpasync16(sb + A_KL + so, kvl + g);
        cpasync16(sb + A_VH + so, kvh + g + DD);
        cpasync16(sb + A_VL + so, kvl + g + DD);
    }
    for (int i = tid; i < 128 * 8; i += 256) {
        int r = i >> 3, c = i & 7;
        int qrow = n0 + r; if (qrow >= NN_TOK) qrow = 0;
        long g = (long)(b * NN_TOK + qrow) * DD + h * HD + c * 8;
        cpasync16(sb + A_QH + r * LDSQ + c * 16, qh_g + g);
        cpasync16(sb + A_QL + r * LDSQ + c * 16, ql_g + g);
    }
    CP_COMMIT();
    // zero K/V pad rows 133..143 (V pad must be 0; K pad zeroed for safety)
    for (int i = tid; i < (SKV - CC) * 32; i += 256) {
        int m = CC + i / 32; int w4 = (i % 32) * 4;
        uint32_t so = m * LDSK + w4;
        *reinterpret_cast<uint32_t*>(smem + A_KH + so) = 0;
        *reinterpret_cast<uint32_t*>(smem + A_KL + so) = 0;
        *reinterpret_cast<uint32_t*>(smem + A_VH + so) = 0;
        *reinterpret_cast<uint32_t*>(smem + A_VL + so) = 0;
    }
    CP_WAIT0();
    __syncthreads();

    int lr = lane & 15, lg = lane >> 4;

    // ---- S = q @ k^T : warp tile 16 x 144 ----
    float sacc[18][4];
#pragma unroll
    for (int f = 0; f < 18; f++)
#pragma unroll
        for (int k = 0; k < 4; k++) sacc[f][k] = 0.f;

#pragma unroll
    for (int ks = 0; ks < 4; ks++) {
        uint32_t koff = ks * 32 + lg * 16;
        uint32_t ah[4], al[4];
        ldsm4(ah, sb + A_QH + (wid * 16 + lr) * LDSQ + koff);
        ldsm4(al, sb + A_QL + (wid * 16 + lr) * LDSQ + koff);
#pragma unroll
        for (int p = 0; p < 9; p++) {
            uint32_t th[4], tl[4];
            ldsm4(th, sb + A_KH + (p * 16 + lr) * LDSK + koff);
            ldsm4(tl, sb + A_KL + (p * 16 + lr) * LDSK + koff);
            uint32_t bh0[2] = { th[0], th[2] }, bh1[2] = { th[1], th[3] };
            uint32_t bl0[2] = { tl[0], tl[2] }, bl1[2] = { tl[1], tl[3] };
            mma_bf16(sacc[2 * p],     ah, bh0);
            mma_bf16(sacc[2 * p],     ah, bl0);
            mma_bf16(sacc[2 * p],     al, bh0);
            mma_bf16(sacc[2 * p + 1], ah, bh1);
            mma_bf16(sacc[2 * p + 1], ah, bl1);
            mma_bf16(sacc[2 * p + 1], al, bh1);
        }
    }

    // ---- softmax (no-max exp; scale already folded into Wq) ----
    float s0 = 0.f, s1 = 0.f;
#pragma unroll
    for (int f = 0; f < 18; f++) {
        int col = f * 8 + (lane & 3) * 2;
        float e0 = (col     < CC) ? __expf(sacc[f][0]) : 0.f;
        float e1 = (col + 1 < CC) ? __expf(sacc[f][1]) : 0.f;
        float e2 = (col     < CC) ? __expf(sacc[f][2]) : 0.f;
        float e3 = (col + 1 < CC) ? __expf(sacc[f][3]) : 0.f;
        sacc[f][0] = e0; sacc[f][1] = e1; sacc[f][2] = e2; sacc[f][3] = e3;
        s0 += e0 + e1; s1 += e2 + e3;
    }
    s0 += __shfl_xor_sync(0xffffffffu, s0, 1);
    s0 += __shfl_xor_sync(0xffffffffu, s0, 2);
    s1 += __shfl_xor_sync(0xffffffffu, s1, 1);
    s1 += __shfl_xor_sync(0xffffffffu, s1, 2);
    float i0 = 1.f / s0, i1 = 1.f / s1;

    __syncthreads();   // all warps done reading q before P overwrites it

    // ---- write normalized P (bf16 hi/lo) to smem ----
    int prow0 = wid * 16 + (lane >> 2), prow1 = prow0 + 8;
#pragma unroll
    for (int f = 0; f < 18; f++) {
        uint32_t colb = (f * 8 + (lane & 3) * 2) * 2;
        split2_sts(sb + A_PH + prow0 * LDSP + colb, sb + A_PL + prow0 * LDSP + colb,
                   sacc[f][0] * i0, sacc[f][1] * i0);
        split2_sts(sb + A_PH + prow1 * LDSP + colb, sb + A_PL + prow1 * LDSP + colb,
                   sacc[f][2] * i1, sacc[f][3] * i1);
    }
    __syncthreads();

    // ---- y = P @ V : warp tile 16 x 64, k = 144 ----
    float yacc[8][4];
#pragma unroll
    for (int f = 0; f < 8; f++)
#pragma unroll
        for (int k = 0; k < 4; k++) yacc[f][k] = 0.f;

    int l8 = (lane >> 3) & 1;
    int krow = ((lane >> 4) & 1) * 8 + (lane & 7);
#pragma unroll
    for (int ks = 0; ks < 9; ks++) {
        uint32_t ph[4], pl[4];
        ldsm4(ph, sb + A_PH + (wid * 16 + lr) * LDSP + ks * 32 + lg * 16);
        ldsm4(pl, sb + A_PL + (wid * 16 + lr) * LDSP + ks * 32 + lg * 16);
        uint32_t vrow = (ks * 16 + krow) * LDSK + l8 * 16;
#pragma unroll
        for (int p = 0; p < 4; p++) {
            uint32_t th[4], tl[4];
            ldsm4t(th, sb + A_VH + vrow + p * 32);
            ldsm4t(tl, sb + A_VL + vrow + p * 32);
            uint32_t bh0[2] = { th[0], th[2] }, bh1[2] = { th[1], th[3] };
            uint32_t bl0[2] = { tl[0], tl[2] }, bl1[2] = { tl[1], tl[3] };
            mma_bf16(yacc[2 * p],     ph, bh0);
            mma_bf16(yacc[2 * p],     ph, bl0);
            mma_bf16(yacc[2 * p],     pl, bh0);
            mma_bf16(yacc[2 * p + 1], ph, bh1);
            mma_bf16(yacc[2 * p + 1], ph, bl1);
            mma_bf16(yacc[2 * p + 1], pl, bh1);
        }
    }

    // ---- store y (bf16 hi/lo), masked to valid rows ----
    int row0 = n0 + wid * 16 + (lane >> 2);
    int row1 = row0 + 8;
#pragma unroll
    for (int f = 0; f < 8; f++) {
        int col = f * 8 + (lane & 3) * 2;
        if (row0 < NN_TOK)
            split2_store(yh, yl, (long)(b * NN_TOK + row0) * DD + h * HD + col,
                         yacc[f][0], yacc[f][1]);
        if (row1 < NN_TOK)
            split2_store(yh, yl, (long)(b * NN_TOK + row1) * DD + h * HD + col,
                         yacc[f][2], yacc[f][3]);
    }
}

// ---------------- split fp32 -> bf16 hi/lo (8 elems / thread) ----------------
__global__ __launch_bounds__(256) void split_kernel(
    const float4* __restrict__ in, uint4* __restrict__ hi, uint4* __restrict__ lo, long n8)
{
    long i = (long)blockIdx.x * 256 + threadIdx.x;
    if (i >= n8) return;
    float4 a = in[2 * i], b = in[2 * i + 1];
    float v[8] = { a.x, a.y, a.z, a.w, b.x, b.y, b.z, b.w };
    uint32_t hw[8], lw[8];
#pragma unroll
    for (int j = 0; j < 8; j++) {
        __nv_bfloat16 h = __float2bfloat16(v[j]);
        __nv_bfloat16 l = __float2bfloat16(v[j] - __bfloat162float(h));
        hw[j] = *reinterpret_cast<unsigned short*>(&h);
        lw[j] = *reinterpret_cast<unsigned short*>(&l);
    }
    uint4 H, L;
    H.x = hw[0] | (hw[1] << 16); H.y = hw[2] | (hw[3] << 16);
    H.z = hw[4] | (hw[5] << 16); H.w = hw[6] | (hw[7] << 16);
    L.x = lw[0] | (lw[1] << 16); L.y = lw[2] | (lw[3] << 16);
    L.z = lw[4] | (lw[5] << 16); L.w = lw[6] | (lw[7] << 16);
    hi[i] = H; lo[i] = L;
}

// ------------ transpose + split weights (scale folded): W[Kd,Nc]->WT[Nc,Kd] --
__global__ __launch_bounds__(256) void tsplit_kernel(
    const float* __restrict__ W, __nv_bfloat16* __restrict__ hiT,
    __nv_bfloat16* __restrict__ loT, int Kd, int Nc, float scale)
{
    int idx = blockIdx.x * 256 + threadIdx.x;
    if (idx >= Kd * Nc) return;
    int k = idx / Nc, n = idx % Nc;
    float a = W[idx] * scale;
    __nv_bfloat16 h = __float2bfloat16(a);
    __nv_bfloat16 l = __float2bfloat16(a - __bfloat162float(h));
    hiT[(long)n * Kd + k] = h;
    loT[(long)n * Kd + k] = l;
}

// ---------------- kernel 1: cls_n, sims, argmax ----------------
__global__ __launch_bounds__(256) void cls_kernel(
    const float* __restrict__ x, const float* __restrict__ cents,
    float* __restrict__ out_cls, float* __restrict__ out_idx, int* __restrict__ idx)
{
    int b = blockIdx.x;
    int t = threadIdx.x;
    __shared__ float red[256];
    __shared__ float snorm;
    __shared__ float best_s;
    __shared__ int best_i;

    const float* xr = x + (long)b * NN_TOK * DD;
    float loc[3];
    float ss = 0.f;
#pragma unroll
    for (int i = 0; i < 3; i++) { loc[i] = xr[t + i * 256]; ss += loc[i] * loc[i]; }
    red[t] = ss; __syncthreads();
    for (int s = 128; s > 0; s >>= 1) { if (t < s) red[t] += red[t + s]; __syncthreads(); }
    if (t == 0) snorm = fmaxf(sqrtf(red[0]), 1e-12f);
    __syncthreads();
    float inv = 1.0f / snorm;
    float c[3];
#pragma unroll
    for (int i = 0; i < 3; i++) {
        c[i] = loc[i] * inv;
        out_cls[(long)b * DD + t + i * 256] = c[i];
    }
    if (t == 0) { best_s = -1e30f; best_i = 0; }
    __syncthreads();
    for (int m = 0; m < MM; m++) {
        float p = 0.f;
#pragma unroll
        for (int i = 0; i < 3; i++) p += c[i] * cents[(long)m * DD + t + i * 256];
        red[t] = p; __syncthreads();
        for (int s = 128; s > 0; s >>= 1) { if (t < s) red[t] += red[t + s]; __syncthreads(); }
        if (t == 0) { if (red[0] > best_s) { best_s = red[0]; best_i = m; } }
        __syncthreads();
    }
    if (t == 0) { idx[b] = best_i; out_idx[b] = (float)best_i; }
}

// ---------------- softmax over rows of length 1024, emit bf16 hi/lo ---------
__global__ __launch_bounds__(256) void softmax1024_split(
    const float* __restrict__ s, __nv_bfloat16* __restrict__ oh, __nv_bfloat16* __restrict__ ol)
{
    long row = blockIdx.x;
    const float* p = s + row * PP;
    int t = threadIdx.x;
    __shared__ float red[256];

    float4 v = reinterpret_cast<const float4*>(p)[t];
    float mx = fmaxf(fmaxf(v.x, v.y), fmaxf(v.z, v.w));
    red[t] = mx; __syncthreads();
    for (int st = 128; st > 0; st >>= 1) { if (t < st) red[t] = fmaxf(red[t], red[t + st]); __syncthreads(); }
    mx = red[0]; __syncthreads();

    v.x = expf(v.x - mx); v.y = expf(v.y - mx);
    v.z = expf(v.z - mx); v.w = expf(v.w - mx);
    float sm = v.x + v.y + v.z + v.w;
    red[t] = sm; __syncthreads();
    for (int st = 128; st > 0; st >>= 1) { if (t < st) red[t] += red[t + st]; __syncthreads(); }
    float inv = 1.0f / red[0];
    v.x *= inv; v.y *= inv; v.z *= inv; v.w *= inv;

    long off = row * PP + (long)t * 4;
    split2_store(oh, ol, off,     v.x, v.y);
    split2_store(oh, ol, off + 2, v.z, v.w);
}

// ---------------- copy x[:, :R, :] into ctx hi/lo rows 0..R-1 ---------------
__global__ __launch_bounds__(256) void copy_xreg_split(
    const float* __restrict__ x, __nv_bfloat16* __restrict__ ch, __nv_bfloat16* __restrict__ cl)
{
    long i = (long)blockIdx.x * blockDim.x + threadIdx.x;   // float4 index
    long total = (long)BB * RR * DD / 4;
    if (i >= total) return;
    long per_b = (long)RR * DD / 4;
    long b = i / per_b;
    long r = i - b * per_b;
    float4 v = reinterpret_cast<const float4*>(x)[b * ((long)NN_TOK * DD / 4) + r];
    long off = b * (long)CC * DD + r * 4;
    split2_store(ch, cl, off,     v.x, v.y);
    split2_store(ch, cl, off + 2, v.z, v.w);
}

// ---------------- launch ----------------
extern "C" void kernel_launch(void* const* d_in, const int* in_sizes, int n_in,
                              void* d_out, int out_size)
{
    const float* x      = (const float*)d_in[0];
    const float* Qb     = (const float*)d_in[1];
    const float* Wq     = (const float*)d_in[2];
    const float* Wctx   = (const float*)d_in[3];
    const float* bctx   = (const float*)d_in[4];
    const float* Wout   = (const float*)d_in[5];
    const float* bout   = (const float*)d_in[6];
    const float* cents  = (const float*)d_in[7];
    float* out = (float*)d_out;

    void *p_idx, *p_scores;
    void *p_xh, *p_xl, *p_yh, *p_yl, *p_qh, *p_ql, *p_kvh, *p_kvl;
    void *p_ch, *p_cl, *p_sh, *p_sl;
    void *p_qbh, *p_qbl, *p_wqh, *p_wql, *p_woh, *p_wol, *p_wch, *p_wcl;
    cudaGetSymbolAddress(&p_idx, g_idx);
    cudaGetSymbolAddress(&p_scores, g_scores);
    cudaGetSymbolAddress(&p_xh, g_x_hi);   cudaGetSymbolAddress(&p_xl, g_x_lo);
    cudaGetSymbolAddress(&p_yh, g_y_hi);   cudaGetSymbolAddress(&p_yl, g_y_lo);
    cudaGetSymbolAddress(&p_qh, g_q_hi);   cudaGetSymbolAddress(&p_ql, g_q_lo);
    cudaGetSymbolAddress(&p_kvh, g_kv_hi); cudaGetSymbolAddress(&p_kvl, g_kv_lo);
    cudaGetSymbolAddress(&p_ch, g_c_hi);   cudaGetSymbolAddress(&p_cl, g_c_lo);
    cudaGetSymbolAddress(&p_sh, g_s_hi);   cudaGetSymbolAddress(&p_sl, g_s_lo);
    cudaGetSymbolAddress(&p_qbh, g_qb_hi); cudaGetSymbolAddress(&p_qbl, g_qb_lo);
    cudaGetSymbolAddress(&p_wqh, g_wq_hi); cudaGetSymbolAddress(&p_wql, g_wq_lo);
    cudaGetSymbolAddress(&p_woh, g_wo_hi); cudaGetSymbolAddress(&p_wol, g_wo_lo);
    cudaGetSymbolAddress(&p_wch, g_wc_hi); cudaGetSymbolAddress(&p_wcl, g_wc_lo);

    int*   idxp   = (int*)p_idx;
    float* scores = (float*)p_scores;
    __nv_bfloat16 *xh = (__nv_bfloat16*)p_xh,  *xl = (__nv_bfloat16*)p_xl;
    __nv_bfloat16 *yh = (__nv_bfloat16*)p_yh,  *yl = (__nv_bfloat16*)p_yl;
    __nv_bfloat16 *qh = (__nv_bfloat16*)p_qh,  *ql = (__nv_bfloat16*)p_ql;
    __nv_bfloat16 *kvh = (__nv_bfloat16*)p_kvh, *kvl = (__nv_bfloat16*)p_kvl;
    __nv_bfloat16 *ch = (__nv_bfloat16*)p_ch,  *cl = (__nv_bfloat16*)p_cl;
    __nv_bfloat16 *shp = (__nv_bfloat16*)p_sh, *slp = (__nv_bfloat16*)p_sl;
    __nv_bfloat16 *qbh = (__nv_bfloat16*)p_qbh, *qbl = (__nv_bfloat16*)p_qbl;
    __nv_bfloat16 *wqh = (__nv_bfloat16*)p_wqh, *wql = (__nv_bfloat16*)p_wql;
    __nv_bfloat16 *woh = (__nv_bfloat16*)p_woh, *wol = (__nv_bfloat16*)p_wol;
    __nv_bfloat16 *wch = (__nv_bfloat16*)p_wch, *wcl = (__nv_bfloat16*)p_wcl;

    cudaFuncSetAttribute(gemm_mma<false, false, false>, cudaFuncAttributeMaxDynamicSharedMemorySize, GEMM_SMEM);
    cudaFuncSetAttribute(gemm_mma<true,  false, false>, cudaFuncAttributeMaxDynamicSharedMemorySize, GEMM_SMEM);
    cudaFuncSetAttribute(gemm_mma<false, true,  false>, cudaFuncAttributeMaxDynamicSharedMemorySize, GEMM_SMEM);
    cudaFuncSetAttribute(gemm_mma<false, false, true>,  cudaFuncAttributeMaxDynamicSharedMemorySize, GEMM_SMEM);
    cudaFuncSetAttribute(gemm_mma<true,  false, true>,  cudaFuncAttributeMaxDynamicSharedMemorySize, GEMM_SMEM);
    cudaFuncSetAttribute(gemm_mma_nn, cudaFuncAttributeMaxDynamicSharedMemorySize, NN_SMEM);
    cudaFuncSetAttribute(attn_mma, cudaFuncAttributeMaxDynamicSharedMemorySize, ATTN_SMEM);

    // 1. cls_n / idx
    cls_kernel<<<BB, 256>>>(x, cents, out + OUT_CLS, out + OUT_IDX, idxp);

    // 2. precision splits: x, Q_banks, weights (transposed; 1/sqrt(d) folded into Wq)
    {
        long n8 = (long)BB * NN_TOK * DD / 8;
        split_kernel<<<(unsigned)((n8 + 255) / 256), 256>>>(
            (const float4*)x, (uint4*)xh, (uint4*)xl, n8);
        long q8 = (long)MM * KK * DD / 8;
        split_kernel<<<(unsigned)((q8 + 255) / 256), 256>>>(
            (const float4*)Qb, (uint4*)qbh, (uint4*)qbl, q8);
        tsplit_kernel<<<(DD * DD + 255) / 256, 256>>>(Wq, wqh, wql, DD, DD, 0.125f);
        tsplit_kernel<<<(DD * DD + 255) / 256, 256>>>(Wout, woh, wol, DD, DD, 1.0f);
        tsplit_kernel<<<(DD * 2 * DD + 255) / 256, 256>>>(Wctx, wch, wcl, DD, 2 * DD, 1.0f);
    }

    // 3. scores[b] = Q_banks[idx[b]] @ xp[b]^T — HMMA NT, fp32 out
    gemm_mma<false, true, false><<<dim3(PP / 128, 1, BB), 256, GEMM_SMEM>>>(
        qbh, qbl, xh + (long)RR * DD, xl + (long)RR * DD, nullptr, scores, nullptr, nullptr,
        KK, PP, DD,
        (long)KK * DD, (long)NN_TOK * DD, (long)KK * PP, idxp);

    // 4. softmax rows (B*K x 1024) -> bf16 hi/lo attn weights
    softmax1024_split<<<BB * KK, 256>>>(scores, shp, slp);

    // 5. ctx[:, :R] = xreg (split)
    {
        long total = (long)BB * RR * DD / 4;
        copy_xreg_split<<<(unsigned)((total + 255) / 256), 256>>>(x, ch, cl);
    }

    // 6. ctx[:, R:] = attn @ xp — HMMA NN, split output
    gemm_mma_nn<<<dim3(DD / 128, 1, BB), 256, NN_SMEM>>>(
        shp, slp, xh + (long)RR * DD, xl + (long)RR * DD,
        ch + (long)RR * DD, cl + (long)RR * DD,
        DD, PP, DD,
        (long)KK * PP, (long)NN_TOK * DD, (long)CC * DD);

    // 7. kv = ctx @ Wctx + bctx — HMMA NT, split bf16 output
    gemm_mma<true, false, true><<<dim3(2 * DD / 128, MPAD_C / 128, 1), 256, GEMM_SMEM>>>(
        ch, cl, wch, wcl, bctx, nullptr, kvh, kvl,
        BB * CC, 2 * DD, DD, 0, 0, 0, nullptr);

    // 8. q = x @ (Wq/8) — HMMA NT, split bf16 output
    gemm_mma<false, false, true><<<dim3(DD / 128, MPAD_X / 128, 1), 256, GEMM_SMEM>>>(
        xh, xl, wqh, wql, nullptr, nullptr, qh, ql,
        BB * NN_TOK, DD, DD, 0, 0, 0, nullptr);

    // 9. attention — HMMA flash, y hi/lo out
    attn_mma<<<dim3((NN_TOK + 127) / 128, HH, BB), 256, ATTN_SMEM>>>(
        qh, ql, kvh, kvl, yh, yl);

    // 10. out = y @ Wout + bout — HMMA NT, fp32 out
    gemm_mma<true, false, false><<<dim3(DD / 128, MPAD_X / 128, 1), 256, GEMM_SMEM>>>(
        yh, yl, woh, wol, bout, out, nullptr, nullptr,
        BB * NN_TOK, DD, DD, 0, 0, 0, nullptr);
}

// round 7
// speedup vs baseline: 1.9940x; 1.3366x over previous
#include <cuda_runtime.h>
#include <cuda_fp16.h>
#include <math.h>
#include <stdint.h>

// ---------------- problem constants ----------------
#define BB 64
#define NN_TOK 1029
#define DD 768
#define HH 12
#define HD 64
#define KK 128
#define RR 5
#define MM 4
#define PP 1024              // N - R
#define CC 133               // R + K

#define MPAD_X 65920         // 515*128  (>= B*N = 65856)
#define MPAD_C 8576          // 67*128   (>= B*C = 8512)

// output layout: [out (B*N*D)] [cls_n (B*D)] [idx (B)]
#define OUT_CLS ((long)BB * NN_TOK * DD)
#define OUT_IDX (OUT_CLS + (long)BB * DD)

// ---------------- scratch (device globals; no allocs allowed) ----------------
__device__ int   g_idx[BB];
__device__ float g_scores[(long)BB * KK * PP];

// fp16 split buffers (zero-init covers padding rows)
__device__ __half g_x_hi[(long)MPAD_X * DD];
__device__ __half g_x_lo[(long)MPAD_X * DD];
__device__ __half g_y_hi[(long)MPAD_X * DD];
__device__ __half g_y_lo[(long)MPAD_X * DD];
__device__ __half g_q_hi[(long)MPAD_X * DD];
__device__ __half g_q_lo[(long)MPAD_X * DD];
__device__ __half g_kv_hi[(long)MPAD_C * 2 * DD];
__device__ __half g_kv_lo[(long)MPAD_C * 2 * DD];
__device__ __half g_c_hi[(long)MPAD_C * DD];
__device__ __half g_c_lo[(long)MPAD_C * DD];
__device__ __half g_s_hi[(long)BB * KK * PP];   // attn weights hi
__device__ __half g_s_lo[(long)BB * KK * PP];   // attn weights lo
__device__ __half g_qb_hi[(long)MM * KK * DD];
__device__ __half g_qb_lo[(long)MM * KK * DD];
__device__ __half g_wq_hi[DD * DD];
__device__ __half g_wo_hi[DD * DD];
__device__ __half g_wc_hi[2 * DD * DD];

// ---------------- PTX helpers ----------------
__device__ __forceinline__ uint32_t smem_u32(const void* p) {
    uint32_t a;
    asm("{ .reg .u64 t; cvta.to.shared.u64 t, %1; cvt.u32.u64 %0, t; }" : "=r"(a) : "l"(p));
    return a;
}
__device__ __forceinline__ void cpasync16(uint32_t dst, const void* src) {
    asm volatile("cp.async.cg.shared.global [%0], [%1], 16;" :: "r"(dst), "l"(src));
}
#define CP_COMMIT() asm volatile("cp.async.commit_group;" ::: "memory")
#define CP_WAIT2()  asm volatile("cp.async.wait_group 2;" ::: "memory")
#define CP_WAIT1()  asm volatile("cp.async.wait_group 1;" ::: "memory")
#define CP_WAIT0()  asm volatile("cp.async.wait_group 0;" ::: "memory")

__device__ __forceinline__ void ldsm4(uint32_t* r, uint32_t addr) {
    asm volatile("ldmatrix.sync.aligned.m8n8.x4.shared.b16 {%0,%1,%2,%3}, [%4];"
        : "=r"(r[0]), "=r"(r[1]), "=r"(r[2]), "=r"(r[3]) : "r"(addr));
}
__device__ __forceinline__ void ldsm4t(uint32_t* r, uint32_t addr) {
    asm volatile("ldmatrix.sync.aligned.m8n8.x4.trans.shared.b16 {%0,%1,%2,%3}, [%4];"
        : "=r"(r[0]), "=r"(r[1]), "=r"(r[2]), "=r"(r[3]) : "r"(addr));
}
__device__ __forceinline__ void mma_f16(float* c, const uint32_t* a, const uint32_t* b) {
    asm volatile(
        "mma.sync.aligned.m16n8k16.row.col.f32.f16.f16.f32 "
        "{%0,%1,%2,%3}, {%4,%5,%6,%7}, {%8,%9}, {%0,%1,%2,%3};"
        : "+f"(c[0]), "+f"(c[1]), "+f"(c[2]), "+f"(c[3])
        : "r"(a[0]), "r"(a[1]), "r"(a[2]), "r"(a[3]), "r"(b[0]), "r"(b[1]));
}

// split a float pair into fp16 hi/lo and store packed (global)
__device__ __forceinline__ void split2_store(
    __half* __restrict__ H, __half* __restrict__ L, long off, float v0, float v1)
{
    __half h0 = __float2half(v0);
    __half h1 = __float2half(v1);
    __half l0 = __float2half(v0 - __half2float(h0));
    __half l1 = __float2half(v1 - __half2float(h1));
    uint32_t hw = (uint32_t)*reinterpret_cast<unsigned short*>(&h0)
                | ((uint32_t)*reinterpret_cast<unsigned short*>(&h1) << 16);
    uint32_t lw = (uint32_t)*reinterpret_cast<unsigned short*>(&l0)
                | ((uint32_t)*reinterpret_cast<unsigned short*>(&l1) << 16);
    *reinterpret_cast<uint32_t*>(H + off) = hw;
    *reinterpret_cast<uint32_t*>(L + off) = lw;
}

// split a float pair into fp16 hi/lo and store to smem
__device__ __forceinline__ void split2_sts(uint32_t ah, uint32_t al_, float v0, float v1)
{
    __half h0 = __float2half(v0);
    __half h1 = __float2half(v1);
    __half l0 = __float2half(v0 - __half2float(h0));
    __half l1 = __float2half(v1 - __half2float(h1));
    uint32_t hw = (uint32_t)*reinterpret_cast<unsigned short*>(&h0)
                | ((uint32_t)*reinterpret_cast<unsigned short*>(&h1) << 16);
    uint32_t lw = (uint32_t)*reinterpret_cast<unsigned short*>(&l0)
                | ((uint32_t)*reinterpret_cast<unsigned short*>(&l1) << 16);
    asm volatile("st.shared.b32 [%0], %1;" :: "r"(ah), "r"(hw) : "memory");
    asm volatile("st.shared.b32 [%0], %1;" :: "r"(al_), "r"(lw) : "memory");
}

// ---------------- NT HMMA GEMM, fp16 2-term (A hi/lo, B hi), 3-stage ---------
// C[m,n] (+= bias[n]) = sum_k A[m,k] * B[n,k]
#define LDSB 80                    // smem bytes per tile row (32 fp16 + pad)
#define TILE_B (128 * LDSB)        // 10240
#define STAGE3 (3 * TILE_B)        // 30720 (Ah, Al, Bh)
#define GEMM_SMEM (3 * STAGE3)     // 92160  -> 2 CTAs/SM

template<bool BIAS, bool GATHER, bool SPLITOUT>
__global__ void __launch_bounds__(256) gemm_mma(
    const __half* __restrict__ Ahb, const __half* __restrict__ Alb,
    const __half* __restrict__ Bhb,
    const float* __restrict__ bias, float* __restrict__ Cb,
    __half* __restrict__ Chb, __half* __restrict__ Clb,
    int M, int Ntot, int Kd,
    long sA, long sB, long sC,
    const int* __restrict__ idxmap)
{
    extern __shared__ char smem[];
    uint32_t sb = smem_u32(smem);

    int tid = threadIdx.x, wid = tid >> 5, lane = tid & 31;
    int warp_m = wid & 3, warp_n = wid >> 2;
    int bz = blockIdx.z;
    long aoff = GATHER ? (long)idxmap[bz] * sA : (long)bz * sA;
    const __half* Ah = Ahb + aoff;
    const __half* Al = Alb + aoff;
    const __half* Bh = Bhb + (long)bz * sB;

    int m0 = blockIdx.y * 128;
    int n0 = blockIdx.x * 128;

    float acc[2][8][4];
#pragma unroll
    for (int i = 0; i < 2; i++)
#pragma unroll
        for (int j = 0; j < 8; j++)
#pragma unroll
            for (int k = 0; k < 4; k++) acc[i][j][k] = 0.f;

    const int nch = Kd / 32;

    auto issue = [&](int ch) {
        uint32_t st = sb + (ch % 3) * STAGE3;
        int k0 = ch * 32;
#pragma unroll
        for (int it = 0; it < 2; it++) {
            int idx = tid + it * 256;
            int r = idx >> 2, c = idx & 3;
            uint32_t so = r * LDSB + c * 16;
            long gA = (long)(m0 + r) * Kd + k0 + c * 8;
            long gB = (long)(n0 + r) * Kd + k0 + c * 8;
            cpasync16(st + so,              Ah + gA);
            cpasync16(st + TILE_B + so,     Al + gA);
            cpasync16(st + 2 * TILE_B + so, Bh + gB);
        }
        CP_COMMIT();
    };

    issue(0);
    if (nch > 1) issue(1);
    if (nch > 2) issue(2);

    int lr = lane & 15, lc = lane >> 4;

    for (int ch = 0; ch < nch; ch++) {
        if (ch + 2 < nch)      { CP_WAIT2(); }
        else if (ch + 1 < nch) { CP_WAIT1(); }
        else                   { CP_WAIT0(); }
        __syncthreads();

        uint32_t stg = sb + (ch % 3) * STAGE3;
        uint32_t Ah_s = stg;
        uint32_t Al_s = stg + TILE_B;
        uint32_t Bh_s = stg + 2 * TILE_B;

#pragma unroll
        for (int ks = 0; ks < 2; ks++) {
            uint32_t koff = ks * 32 + lc * 16;
            uint32_t ah[2][4], al[2][4], bh[8][2];
#pragma unroll
            for (int mf = 0; mf < 2; mf++) {
                uint32_t row = warp_m * 32 + mf * 16 + lr;
                ldsm4(ah[mf], Ah_s + row * LDSB + koff);
                ldsm4(al[mf], Al_s + row * LDSB + koff);
            }
#pragma unroll
            for (int p = 0; p < 4; p++) {
                uint32_t row = warp_n * 64 + p * 16 + lr;
                uint32_t t[4];
                ldsm4(t, Bh_s + row * LDSB + koff);
                bh[2 * p][0] = t[0]; bh[2 * p][1] = t[2];
                bh[2 * p + 1][0] = t[1]; bh[2 * p + 1][1] = t[3];
            }
#pragma unroll
            for (int mf = 0; mf < 2; mf++)
#pragma unroll
                for (int nf = 0; nf < 8; nf++) {
                    mma_f16(acc[mf][nf], ah[mf], bh[nf]);
                    mma_f16(acc[mf][nf], al[mf], bh[nf]);
                }
        }
        __syncthreads();
        if (ch + 3 < nch) issue(ch + 3);
    }

#pragma unroll
    for (int mf = 0; mf < 2; mf++) {
        int row0 = m0 + warp_m * 32 + mf * 16 + (lane >> 2);
#pragma unroll
        for (int nf = 0; nf < 8; nf++) {
            int col = n0 + warp_n * 64 + nf * 8 + (lane & 3) * 2;
            float b0 = 0.f, b1 = 0.f;
            if (BIAS) { b0 = bias[col]; b1 = bias[col + 1]; }
            if (SPLITOUT) {
                __half* Ch = Chb + (long)blockIdx.z * sC;
                __half* Cl = Clb + (long)blockIdx.z * sC;
                if (row0 < M)
                    split2_store(Ch, Cl, (long)row0 * Ntot + col,
                                 acc[mf][nf][0] + b0, acc[mf][nf][1] + b1);
                if (row0 + 8 < M)
                    split2_store(Ch, Cl, (long)(row0 + 8) * Ntot + col,
                                 acc[mf][nf][2] + b0, acc[mf][nf][3] + b1);
            } else {
                float* C = Cb + (long)blockIdx.z * sC;
                if (row0 < M) {
                    float2 v = make_float2(acc[mf][nf][0] + b0, acc[mf][nf][1] + b1);
                    *reinterpret_cast<float2*>(&C[(long)row0 * Ntot + col]) = v;
                }
                if (row0 + 8 < M) {
                    float2 v = make_float2(acc[mf][nf][2] + b0, acc[mf][nf][3] + b1);
                    *reinterpret_cast<float2*>(&C[(long)(row0 + 8) * Ntot + col]) = v;
                }
            }
        }
    }
}

// ---------------- NN HMMA GEMM (B row-major [k][n]), fp16 2-term, 3-stage ----
// C[m,n] = sum_k A[m,k] * B[k,n];  M = 128 fixed; output written as hi/lo fp16.
#define LDSB_N 272                       // 128 fp16 (256B) + 16B pad
#define NTILE_B (32 * LDSB_N)            // 8704
#define NSTAGE3 (2 * TILE_B + NTILE_B)   // 29184 (Ah, Al, Bh)
#define NN_SMEM (3 * NSTAGE3)            // 87552 -> 2 CTAs/SM

__global__ void __launch_bounds__(256) gemm_mma_nn(
    const __half* __restrict__ Ahb, const __half* __restrict__ Alb,
    const __half* __restrict__ Bhb,
    __half* __restrict__ Chb, __half* __restrict__ Clb,
    int Ntot, int Kd, int ldB,
    long sA, long sB, long sC)
{
    extern __shared__ char smem[];
    uint32_t sb = smem_u32(smem);

    int tid = threadIdx.x, wid = tid >> 5, lane = tid & 31;
    int warp_m = wid & 3, warp_n = wid >> 2;
    int bz = blockIdx.z;
    const __half* Ah = Ahb + (long)bz * sA;
    const __half* Al = Alb + (long)bz * sA;
    const __half* Bh = Bhb + (long)bz * sB;
    __half* Ch = Chb + (long)bz * sC;
    __half* Cl = Clb + (long)bz * sC;

    int n0 = blockIdx.x * 128;

    float acc[2][8][4];
#pragma unroll
    for (int i = 0; i < 2; i++)
#pragma unroll
        for (int j = 0; j < 8; j++)
#pragma unroll
            for (int k = 0; k < 4; k++) acc[i][j][k] = 0.f;

    const int nch = Kd / 32;

    auto issue = [&](int ch) {
        uint32_t st = sb + (ch % 3) * NSTAGE3;
        int k0 = ch * 32;
#pragma unroll
        for (int it = 0; it < 2; it++) {
            int idx = tid + it * 256;
            int r = idx >> 2, c = idx & 3;
            uint32_t so = r * LDSB + c * 16;
            long gA = (long)r * Kd + k0 + c * 8;
            cpasync16(st + so,          Ah + gA);
            cpasync16(st + TILE_B + so, Al + gA);
        }
#pragma unroll
        for (int it = 0; it < 2; it++) {
            int idx = tid + it * 256;
            int r = idx >> 4, c = idx & 15;
            uint32_t so = 2 * TILE_B + r * LDSB_N + c * 16;
            long gB = (long)(k0 + r) * ldB + n0 + c * 8;
            cpasync16(st + so, Bh + gB);
        }
        CP_COMMIT();
    };

    issue(0);
    if (nch > 1) issue(1);
    if (nch > 2) issue(2);

    int lr = lane & 15, lc = lane >> 4;
    int l8 = (lane >> 3) & 1;
    int krow = ((lane >> 4) & 1) * 8 + (lane & 7);   // 0..15

    for (int ch = 0; ch < nch; ch++) {
        if (ch + 2 < nch)      { CP_WAIT2(); }
        else if (ch + 1 < nch) { CP_WAIT1(); }
        else                   { CP_WAIT0(); }
        __syncthreads();

        uint32_t stg = sb + (ch % 3) * NSTAGE3;
        uint32_t Ah_s = stg;
        uint32_t Al_s = stg + TILE_B;
        uint32_t Bh_s = stg + 2 * TILE_B;

#pragma unroll
        for (int ks = 0; ks < 2; ks++) {
            uint32_t koff = ks * 32 + lc * 16;
            uint32_t ah[2][4], al[2][4], bh[8][2];
#pragma unroll
            for (int mf = 0; mf < 2; mf++) {
                uint32_t row = warp_m * 32 + mf * 16 + lr;
                ldsm4(ah[mf], Ah_s + row * LDSB + koff);
                ldsm4(al[mf], Al_s + row * LDSB + koff);
            }
            uint32_t brow = (ks * 16 + krow) * LDSB_N + warp_n * 128 + l8 * 16;
#pragma unroll
            for (int p = 0; p < 4; p++) {
                uint32_t t[4];
                ldsm4t(t, Bh_s + brow + p * 32);
                bh[2 * p][0] = t[0]; bh[2 * p][1] = t[2];
                bh[2 * p + 1][0] = t[1]; bh[2 * p + 1][1] = t[3];
            }
#pragma unroll
            for (int mf = 0; mf < 2; mf++)
#pragma unroll
                for (int nf = 0; nf < 8; nf++) {
                    mma_f16(acc[mf][nf], ah[mf], bh[nf]);
                    mma_f16(acc[mf][nf], al[mf], bh[nf]);
                }
        }
        __syncthreads();
        if (ch + 3 < nch) issue(ch + 3);
    }

    // epilogue: split to fp16 hi/lo (M = 128 exact, no bounds checks)
#pragma unroll
    for (int mf = 0; mf < 2; mf++) {
        int row0 = warp_m * 32 + mf * 16 + (lane >> 2);
#pragma unroll
        for (int nf = 0; nf < 8; nf++) {
            int col = n0 + warp_n * 64 + nf * 8 + (lane & 3) * 2;
            split2_store(Ch, Cl, (long)row0 * Ntot + col, acc[mf][nf][0], acc[mf][nf][1]);
            split2_store(Ch, Cl, (long)(row0 + 8) * Ntot + col, acc[mf][nf][2], acc[mf][nf][3]);
        }
    }
}

// ---------------- HMMA flash attention (fp16 2-term) ----------------
// grid (9, HH, BB); 256 threads (8 warps x 16 q-rows).
#define SKV 144
#define LDSK 144
#define LDSQ 144
#define LDSP 304
#define A_KH 0                           // 144*144 = 20736
#define A_VH 20736
#define A_QH 41472                       // 128*144 = 18432
#define A_QL (A_QH + 18432)              // ..78336
#define A_PH A_QH                        // P reuses q region (after sync)
#define A_PL (A_PH + 128 * LDSP)         // 80384
#define ATTN_SMEM (A_PL + 128 * LDSP)    // 119296

__global__ void __launch_bounds__(256) attn_mma(
    const __half* __restrict__ qh_g, const __half* __restrict__ ql_g,
    const __half* __restrict__ kvh,
    __half* __restrict__ yh, __half* __restrict__ yl)
{
    extern __shared__ char smem[];
    uint32_t sb = smem_u32(smem);
    int tid = threadIdx.x, wid = tid >> 5, lane = tid & 31;
    int n0 = blockIdx.x * 128;
    int h = blockIdx.y, b = blockIdx.z;

    // ---- loads: K/V hi rows (133) + q hi/lo tile (128 rows) ----
    for (int i = tid; i < CC * 8; i += 256) {
        int m = i >> 3, c = i & 7;
        long g = ((long)(b * CC + m) * 2) * DD + h * HD + c * 8;
        uint32_t so = m * LDSK + c * 16;
        cpasync16(sb + A_KH + so, kvh + g);
        cpasync16(sb + A_VH + so, kvh + g + DD);
    }
    for (int i = tid; i < 128 * 8; i += 256) {
        int r = i >> 3, c = i & 7;
        int qrow = n0 + r; if (qrow >= NN_TOK) qrow = 0;
        long g = (long)(b * NN_TOK + qrow) * DD + h * HD + c * 8;
        cpasync16(sb + A_QH + r * LDSQ + c * 16, qh_g + g);
        cpasync16(sb + A_QL + r * LDSQ + c * 16, ql_g + g);
    }
    CP_COMMIT();
    // zero K/V pad rows 133..143 (V pad must be 0)
    for (int i = tid; i < (SKV - CC) * 32; i += 256) {
        int m = CC + i / 32; int w4 = (i % 32) * 4;
        uint32_t so = m * LDSK + w4;
        *reinterpret_cast<uint32_t*>(smem + A_KH + so) = 0;
        *reinterpret_cast<uint32_t*>(smem + A_VH + so) = 0;
    }
    CP_WAIT0();
    __syncthreads();

    int lr = lane & 15, lg = lane >> 4;

    // ---- S = q @ k^T : warp tile 16 x 144, 2-term ----
    float sacc[18][4];
#pragma unroll
    for (int f = 0; f < 18; f++)
#pragma unroll
        for (int k = 0; k < 4; k++) sacc[f][k] = 0.f;

#pragma unroll
    for (int ks = 0; ks < 4; ks++) {
        uint32_t koff = ks * 32 + lg * 16;
        uint32_t ah[4], al[4];
        ldsm4(ah, sb + A_QH + (wid * 16 + lr) * LDSQ + koff);
        ldsm4(al, sb + A_QL + (wid * 16 + lr) * LDSQ + koff);
#pragma unroll
        for (int p = 0; p < 9; p++) {
            uint32_t th[4];
            ldsm4(th, sb + A_KH + (p * 16 + lr) * LDSK + koff);
            uint32_t bh0[2] = { th[0], th[2] }, bh1[2] = { th[1], th[3] };
            mma_f16(sacc[2 * p],     ah, bh0);
            mma_f16(sacc[2 * p],     al, bh0);
            mma_f16(sacc[2 * p + 1], ah, bh1);
            mma_f16(sacc[2 * p + 1], al, bh1);
        }
    }

    // ---- softmax (no-max exp; scale folded into Wq) ----
    float s0 = 0.f, s1 = 0.f;
#pragma unroll
    for (int f = 0; f < 18; f++) {
        int col = f * 8 + (lane & 3) * 2;
        float e0 = (col     < CC) ? __expf(sacc[f][0]) : 0.f;
        float e1 = (col + 1 < CC) ? __expf(sacc[f][1]) : 0.f;
        float e2 = (col     < CC) ? __expf(sacc[f][2]) : 0.f;
        float e3 = (col + 1 < CC) ? __expf(sacc[f][3]) : 0.f;
        sacc[f][0] = e0; sacc[f][1] = e1; sacc[f][2] = e2; sacc[f][3] = e3;
        s0 += e0 + e1; s1 += e2 + e3;
    }
    s0 += __shfl_xor_sync(0xffffffffu, s0, 1);
    s0 += __shfl_xor_sync(0xffffffffu, s0, 2);
    s1 += __shfl_xor_sync(0xffffffffu, s1, 1);
    s1 += __shfl_xor_sync(0xffffffffu, s1, 2);
    float i0 = 1.f / s0, i1 = 1.f / s1;

    __syncthreads();   // all warps done reading q before P overwrites it

    // ---- write normalized P (fp16 hi/lo) to smem ----
    int prow0 = wid * 16 + (lane >> 2), prow1 = prow0 + 8;
#pragma unroll
    for (int f = 0; f < 18; f++) {
        uint32_t colb = (f * 8 + (lane & 3) * 2) * 2;
        split2_sts(sb + A_PH + prow0 * LDSP + colb, sb + A_PL + prow0 * LDSP + colb,
                   sacc[f][0] * i0, sacc[f][1] * i0);
        split2_sts(sb + A_PH + prow1 * LDSP + colb, sb + A_PL + prow1 * LDSP + colb,
                   sacc[f][2] * i1, sacc[f][3] * i1);
    }
    __syncthreads();

    // ---- y = P @ V : warp tile 16 x 64, k = 144, 2-term ----
    float yacc[8][4];
#pragma unroll
    for (int f = 0; f < 8; f++)
#pragma unroll
        for (int k = 0; k < 4; k++) yacc[f][k] = 0.f;

    int l8 = (lane >> 3) & 1;
    int krow = ((lane >> 4) & 1) * 8 + (lane & 7);
#pragma unroll
    for (int ks = 0; ks < 9; ks++) {
        uint32_t ph[4], pl[4];
        ldsm4(ph, sb + A_PH + (wid * 16 + lr) * LDSP + ks * 32 + lg * 16);
        ldsm4(pl, sb + A_PL + (wid * 16 + lr) * LDSP + ks * 32 + lg * 16);
        uint32_t vrow = (ks * 16 + krow) * LDSK + l8 * 16;
#pragma unroll
        for (int p = 0; p < 4; p++) {
            uint32_t th[4];
            ldsm4t(th, sb + A_VH + vrow + p * 32);
            uint32_t bh0[2] = { th[0], th[2] }, bh1[2] = { th[1], th[3] };
            mma_f16(yacc[2 * p],     ph, bh0);
            mma_f16(yacc[2 * p],     pl, bh0);
            mma_f16(yacc[2 * p + 1], ph, bh1);
            mma_f16(yacc[2 * p + 1], pl, bh1);
        }
    }

    // ---- store y (fp16 hi/lo), masked to valid rows ----
    int row0 = n0 + wid * 16 + (lane >> 2);
    int row1 = row0 + 8;
#pragma unroll
    for (int f = 0; f < 8; f++) {
        int col = f * 8 + (lane & 3) * 2;
        if (row0 < NN_TOK)
            split2_store(yh, yl, (long)(b * NN_TOK + row0) * DD + h * HD + col,
                         yacc[f][0], yacc[f][1]);
        if (row1 < NN_TOK)
            split2_store(yh, yl, (long)(b * NN_TOK + row1) * DD + h * HD + col,
                         yacc[f][2], yacc[f][3]);
    }
}

// ---------------- split fp32 -> fp16 hi/lo (8 elems / thread) ----------------
__global__ __launch_bounds__(256) void split_kernel(
    const float4* __restrict__ in, uint4* __restrict__ hi, uint4* __restrict__ lo, long n8)
{
    long i = (long)blockIdx.x * 256 + threadIdx.x;
    if (i >= n8) return;
    float4 a = in[2 * i], b = in[2 * i + 1];
    float v[8] = { a.x, a.y, a.z, a.w, b.x, b.y, b.z, b.w };
    uint32_t hw[8], lw[8];
#pragma unroll
    for (int j = 0; j < 8; j++) {
        __half h = __float2half(v[j]);
        __half l = __float2half(v[j] - __half2float(h));
        hw[j] = *reinterpret_cast<unsigned short*>(&h);
        lw[j] = *reinterpret_cast<unsigned short*>(&l);
    }
    uint4 H, L;
    H.x = hw[0] | (hw[1] << 16); H.y = hw[2] | (hw[3] << 16);
    H.z = hw[4] | (hw[5] << 16); H.w = hw[6] | (hw[7] << 16);
    L.x = lw[0] | (lw[1] << 16); L.y = lw[2] | (lw[3] << 16);
    L.z = lw[4] | (lw[5] << 16); L.w = lw[6] | (lw[7] << 16);
    hi[i] = H; lo[i] = L;
}

// ------------ transpose weights (scale folded), fp16 hi only -----------------
__global__ __launch_bounds__(256) void tsplit_kernel(
    const float* __restrict__ W, __half* __restrict__ hiT,
    int Kd, int Nc, float scale)
{
    int idx = blockIdx.x * 256 + threadIdx.x;
    if (idx >= Kd * Nc) return;
    int k = idx / Nc, n = idx % Nc;
    hiT[(long)n * Kd + k] = __float2half(W[idx] * scale);
}

// ---------------- kernel 1: cls_n, sims, argmax ----------------
__global__ __launch_bounds__(256) void cls_kernel(
    const float* __restrict__ x, const float* __restrict__ cents,
    float* __restrict__ out_cls, float* __restrict__ out_idx, int* __restrict__ idx)
{
    int b = blockIdx.x;
    int t = threadIdx.x;
    __shared__ float red[256];
    __shared__ float snorm;
    __shared__ float best_s;
    __shared__ int best_i;

    const float* xr = x + (long)b * NN_TOK * DD;
    float loc[3];
    float ss = 0.f;
#pragma unroll
    for (int i = 0; i < 3; i++) { loc[i] = xr[t + i * 256]; ss += loc[i] * loc[i]; }
    red[t] = ss; __syncthreads();
    for (int s = 128; s > 0; s >>= 1) { if (t < s) red[t] += red[t + s]; __syncthreads(); }
    if (t == 0) snorm = fmaxf(sqrtf(red[0]), 1e-12f);
    __syncthreads();
    float inv = 1.0f / snorm;
    float c[3];
#pragma unroll
    for (int i = 0; i < 3; i++) {
        c[i] = loc[i] * inv;
        out_cls[(long)b * DD + t + i * 256] = c[i];
    }
    if (t == 0) { best_s = -1e30f; best_i = 0; }
    __syncthreads();
    for (int m = 0; m < MM; m++) {
        float p = 0.f;
#pragma unroll
        for (int i = 0; i < 3; i++) p += c[i] * cents[(long)m * DD + t + i * 256];
        red[t] = p; __syncthreads();
        for (int s = 128; s > 0; s >>= 1) { if (t < s) red[t] += red[t + s]; __syncthreads(); }
        if (t == 0) { if (red[0] > best_s) { best_s = red[0]; best_i = m; } }
        __syncthreads();
    }
    if (t == 0) { idx[b] = best_i; out_idx[b] = (float)best_i; }
}

// ---------------- softmax over rows of length 1024, emit fp16 hi/lo ---------
__global__ __launch_bounds__(256) void softmax1024_split(
    const float* __restrict__ s, __half* __restrict__ oh, __half* __restrict__ ol)
{
    long row = blockIdx.x;
    const float* p = s + row * PP;
    int t = threadIdx.x;
    __shared__ float red[256];

    float4 v = reinterpret_cast<const float4*>(p)[t];
    float mx = fmaxf(fmaxf(v.x, v.y), fmaxf(v.z, v.w));
    red[t] = mx; __syncthreads();
    for (int st = 128; st > 0; st >>= 1) { if (t < st) red[t] = fmaxf(red[t], red[t + st]); __syncthreads(); }
    mx = red[0]; __syncthreads();

    v.x = expf(v.x - mx); v.y = expf(v.y - mx);
    v.z = expf(v.z - mx); v.w = expf(v.w - mx);
    float sm = v.x + v.y + v.z + v.w;
    red[t] = sm; __syncthreads();
    for (int st = 128; st > 0; st >>= 1) { if (t < st) red[t] += red[t + st]; __syncthreads(); }
    float inv = 1.0f / red[0];
    v.x *= inv; v.y *= inv; v.z *= inv; v.w *= inv;

    long off = row * PP + (long)t * 4;
    split2_store(oh, ol, off,     v.x, v.y);
    split2_store(oh, ol, off + 2, v.z, v.w);
}

// ---------------- copy x[:, :R, :] into ctx hi/lo rows 0..R-1 ---------------
__global__ __launch_bounds__(256) void copy_xreg_split(
    const float* __restrict__ x, __half* __restrict__ ch, __half* __restrict__ cl)
{
    long i = (long)blockIdx.x * blockDim.x + threadIdx.x;   // float4 index
    long total = (long)BB * RR * DD / 4;
    if (i >= total) return;
    long per_b = (long)RR * DD / 4;
    long b = i / per_b;
    long r = i - b * per_b;
    float4 v = reinterpret_cast<const float4*>(x)[b * ((long)NN_TOK * DD / 4) + r];
    long off = b * (long)CC * DD + r * 4;
    split2_store(ch, cl, off,     v.x, v.y);
    split2_store(ch, cl, off + 2, v.z, v.w);
}

// ---------------- launch ----------------
extern "C" void kernel_launch(void* const* d_in, const int* in_sizes, int n_in,
                              void* d_out, int out_size)
{
    const float* x      = (const float*)d_in[0];
    const float* Qb     = (const float*)d_in[1];
    const float* Wq     = (const float*)d_in[2];
    const float* Wctx   = (const float*)d_in[3];
    const float* bctx   = (const float*)d_in[4];
    const float* Wout   = (const float*)d_in[5];
    const float* bout   = (const float*)d_in[6];
    const float* cents  = (const float*)d_in[7];
    float* out = (float*)d_out;

    void *p_idx, *p_scores;
    void *p_xh, *p_xl, *p_yh, *p_yl, *p_qh, *p_ql, *p_kvh, *p_kvl;
    void *p_ch, *p_cl, *p_sh, *p_sl;
    void *p_qbh, *p_qbl, *p_wqh, *p_woh, *p_wch;
    cudaGetSymbolAddress(&p_idx, g_idx);
    cudaGetSymbolAddress(&p_scores, g_scores);
    cudaGetSymbolAddress(&p_xh, g_x_hi);   cudaGetSymbolAddress(&p_xl, g_x_lo);
    cudaGetSymbolAddress(&p_yh, g_y_hi);   cudaGetSymbolAddress(&p_yl, g_y_lo);
    cudaGetSymbolAddress(&p_qh, g_q_hi);   cudaGetSymbolAddress(&p_ql, g_q_lo);
    cudaGetSymbolAddress(&p_kvh, g_kv_hi); cudaGetSymbolAddress(&p_kvl, g_kv_lo);
    cudaGetSymbolAddress(&p_ch, g_c_hi);   cudaGetSymbolAddress(&p_cl, g_c_lo);
    cudaGetSymbolAddress(&p_sh, g_s_hi);   cudaGetSymbolAddress(&p_sl, g_s_lo);
    cudaGetSymbolAddress(&p_qbh, g_qb_hi); cudaGetSymbolAddress(&p_qbl, g_qb_lo);
    cudaGetSymbolAddress(&p_wqh, g_wq_hi);
    cudaGetSymbolAddress(&p_woh, g_wo_hi);
    cudaGetSymbolAddress(&p_wch, g_wc_hi);

    int*   idxp   = (int*)p_idx;
    float* scores = (float*)p_scores;
    __half *xh = (__half*)p_xh,  *xl = (__half*)p_xl;
    __half *yh = (__half*)p_yh,  *yl = (__half*)p_yl;
    __half *qh = (__half*)p_qh,  *ql = (__half*)p_ql;
    __half *kvh = (__half*)p_kvh, *kvl = (__half*)p_kvl;
    __half *ch = (__half*)p_ch,  *cl = (__half*)p_cl;
    __half *shp = (__half*)p_sh, *slp = (__half*)p_sl;
    __half *qbh = (__half*)p_qbh, *qbl = (__half*)p_qbl;
    __half *wqh = (__half*)p_wqh;
    __half *woh = (__half*)p_woh;
    __half *wch = (__half*)p_wch;

    cudaFuncSetAttribute(gemm_mma<false, false, false>, cudaFuncAttributeMaxDynamicSharedMemorySize, GEMM_SMEM);
    cudaFuncSetAttribute(gemm_mma<true,  false, false>, cudaFuncAttributeMaxDynamicSharedMemorySize, GEMM_SMEM);
    cudaFuncSetAttribute(gemm_mma<false, true,  false>, cudaFuncAttributeMaxDynamicSharedMemorySize, GEMM_SMEM);
    cudaFuncSetAttribute(gemm_mma<false, false, true>,  cudaFuncAttributeMaxDynamicSharedMemorySize, GEMM_SMEM);
    cudaFuncSetAttribute(gemm_mma<true,  false, true>,  cudaFuncAttributeMaxDynamicSharedMemorySize, GEMM_SMEM);
    cudaFuncSetAttribute(gemm_mma_nn, cudaFuncAttributeMaxDynamicSharedMemorySize, NN_SMEM);
    cudaFuncSetAttribute(attn_mma, cudaFuncAttributeMaxDynamicSharedMemorySize, ATTN_SMEM);

    // 1. cls_n / idx
    cls_kernel<<<BB, 256>>>(x, cents, out + OUT_CLS, out + OUT_IDX, idxp);

    // 2. precision splits: x, Q_banks hi/lo; weights hi only (1/sqrt(d) in Wq)
    {
        long n8 = (long)BB * NN_TOK * DD / 8;
        split_kernel<<<(unsigned)((n8 + 255) / 256), 256>>>(
            (const float4*)x, (uint4*)xh, (uint4*)xl, n8);
        long q8 = (long)MM * KK * DD / 8;
        split_kernel<<<(unsigned)((q8 + 255) / 256), 256>>>(
            (const float4*)Qb, (uint4*)qbh, (uint4*)qbl, q8);
        tsplit_kernel<<<(DD * DD + 255) / 256, 256>>>(Wq, wqh, DD, DD, 0.125f);
        tsplit_kernel<<<(DD * DD + 255) / 256, 256>>>(Wout, woh, DD, DD, 1.0f);
        tsplit_kernel<<<(DD * 2 * DD + 255) / 256, 256>>>(Wctx, wch, DD, 2 * DD, 1.0f);
    }

    // 3. scores[b] = Q_banks[idx[b]] @ xp[b]^T — NT, A=Qb hi/lo, B=x hi
    gemm_mma<false, true, false><<<dim3(PP / 128, 1, BB), 256, GEMM_SMEM>>>(
        qbh, qbl, xh + (long)RR * DD, nullptr, scores, nullptr, nullptr,
        KK, PP, DD,
        (long)KK * DD, (long)NN_TOK * DD, (long)KK * PP, idxp);

    // 4. softmax rows (B*K x 1024) -> fp16 hi/lo attn weights
    softmax1024_split<<<BB * KK, 256>>>(scores, shp, slp);

    // 5. ctx[:, :R] = xreg (split)
    {
        long total = (long)BB * RR * DD / 4;
        copy_xreg_split<<<(unsigned)((total + 255) / 256), 256>>>(x, ch, cl);
    }

    // 6. ctx[:, R:] = attn @ xp — NN, A=attn hi/lo, B=x hi, split output
    gemm_mma_nn<<<dim3(DD / 128, 1, BB), 256, NN_SMEM>>>(
        shp, slp, xh + (long)RR * DD,
        ch + (long)RR * DD, cl + (long)RR * DD,
        DD, PP, DD,
        (long)KK * PP, (long)NN_TOK * DD, (long)CC * DD);

    // 7. kv = ctx @ Wctx + bctx — NT, A=ctx hi/lo, B=Wctx hi, split output
    gemm_mma<true, false, true><<<dim3(2 * DD / 128, MPAD_C / 128, 1), 256, GEMM_SMEM>>>(
        ch, cl, wch, bctx, nullptr, kvh, kvl,
        BB * CC, 2 * DD, DD, 0, 0, 0, nullptr);

    // 8. q = x @ (Wq/8) — NT, A=x hi/lo, B=Wq hi, split output
    gemm_mma<false, false, true><<<dim3(DD / 128, MPAD_X / 128, 1), 256, GEMM_SMEM>>>(
        xh, xl, wqh, nullptr, nullptr, qh, ql,
        BB * NN_TOK, DD, DD, 0, 0, 0, nullptr);

    // 9. attention — HMMA flash, q hi/lo vs kv hi, y hi/lo out
    attn_mma<<<dim3((NN_TOK + 127) / 128, HH, BB), 256, ATTN_SMEM>>>(
        qh, ql, kvh, yh, yl);

    // 10. out = y @ Wout + bout — NT, A=y hi/lo, B=Wout hi, fp32 out
    gemm_mma<true, false, false><<<dim3(DD / 128, MPAD_X / 128, 1), 256, GEMM_SMEM>>>(
        yh, yl, woh, bout, out, nullptr, nullptr,
        BB * NN_TOK, DD, DD, 0, 0, 0, nullptr);
}

// round 8
// speedup vs baseline: 2.8483x; 1.4284x over previous
#include <cuda_runtime.h>
#include <cuda_fp16.h>
#include <math.h>
#include <stdint.h>

// ---------------- problem constants ----------------
#define BB 64
#define NN_TOK 1029
#define DD 768
#define HH 12
#define HD 64
#define KK 128
#define RR 5
#define MM 4
#define PP 1024              // N - R
#define CC 133               // R + K

#define MPAD_X 65920         // 515*128  (>= B*N = 65856)
#define MPAD_C 8576          // 67*128   (>= B*C = 8512)

// output layout: [out (B*N*D)] [cls_n (B*D)] [idx (B)]
#define OUT_CLS ((long)BB * NN_TOK * DD)
#define OUT_IDX (OUT_CLS + (long)BB * DD)

// ---------------- scratch (device globals; no allocs allowed) ----------------
__device__ int   g_idx[BB];
__device__ float g_scores[(long)BB * KK * PP];

// fp16 split buffers (zero-init covers padding rows)
__device__ __half g_x_hi[(long)MPAD_X * DD];
__device__ __half g_x_lo[(long)MPAD_X * DD];
__device__ __half g_y_hi[(long)MPAD_X * DD];
__device__ __half g_q_hi[(long)MPAD_X * DD];
__device__ __half g_q_lo[(long)MPAD_X * DD];
__device__ __half g_kv_hi[(long)MPAD_C * 2 * DD];
__device__ __half g_c_hi[(long)MPAD_C * DD];
__device__ __half g_c_lo[(long)MPAD_C * DD];
__device__ __half g_s_hi[(long)BB * KK * PP];   // attn weights hi
__device__ __half g_qb_hi[(long)MM * KK * DD];
__device__ __half g_wq_hi[DD * DD];
__device__ __half g_wo_hi[DD * DD];
__device__ __half g_wc_hi[2 * DD * DD];

// ---------------- PTX helpers ----------------
__device__ __forceinline__ uint32_t smem_u32(const void* p) {
    uint32_t a;
    asm("{ .reg .u64 t; cvta.to.shared.u64 t, %1; cvt.u32.u64 %0, t; }" : "=r"(a) : "l"(p));
    return a;
}
__device__ __forceinline__ void cpasync16(uint32_t dst, const void* src) {
    asm volatile("cp.async.cg.shared.global [%0], [%1], 16;" :: "r"(dst), "l"(src));
}
#define CP_COMMIT() asm volatile("cp.async.commit_group;" ::: "memory")
#define CP_WAIT2()  asm volatile("cp.async.wait_group 2;" ::: "memory")
#define CP_WAIT1()  asm volatile("cp.async.wait_group 1;" ::: "memory")
#define CP_WAIT0()  asm volatile("cp.async.wait_group 0;" ::: "memory")

__device__ __forceinline__ void ldsm4(uint32_t* r, uint32_t addr) {
    asm volatile("ldmatrix.sync.aligned.m8n8.x4.shared.b16 {%0,%1,%2,%3}, [%4];"
        : "=r"(r[0]), "=r"(r[1]), "=r"(r[2]), "=r"(r[3]) : "r"(addr));
}
__device__ __forceinline__ void ldsm4t(uint32_t* r, uint32_t addr) {
    asm volatile("ldmatrix.sync.aligned.m8n8.x4.trans.shared.b16 {%0,%1,%2,%3}, [%4];"
        : "=r"(r[0]), "=r"(r[1]), "=r"(r[2]), "=r"(r[3]) : "r"(addr));
}
__device__ __forceinline__ void mma_f16(float* c, const uint32_t* a, const uint32_t* b) {
    asm volatile(
        "mma.sync.aligned.m16n8k16.row.col.f32.f16.f16.f32 "
        "{%0,%1,%2,%3}, {%4,%5,%6,%7}, {%8,%9}, {%0,%1,%2,%3};"
        : "+f"(c[0]), "+f"(c[1]), "+f"(c[2]), "+f"(c[3])
        : "r"(a[0]), "r"(a[1]), "r"(a[2]), "r"(a[3]), "r"(b[0]), "r"(b[1]));
}

// split a float pair into fp16 hi/lo and store packed (global)
__device__ __forceinline__ void split2_store(
    __half* __restrict__ H, __half* __restrict__ L, long off, float v0, float v1)
{
    __half h0 = __float2half(v0);
    __half h1 = __float2half(v1);
    __half l0 = __float2half(v0 - __half2float(h0));
    __half l1 = __float2half(v1 - __half2float(h1));
    uint32_t hw = (uint32_t)*reinterpret_cast<unsigned short*>(&h0)
                | ((uint32_t)*reinterpret_cast<unsigned short*>(&h1) << 16);
    uint32_t lw = (uint32_t)*reinterpret_cast<unsigned short*>(&l0)
                | ((uint32_t)*reinterpret_cast<unsigned short*>(&l1) << 16);
    *reinterpret_cast<uint32_t*>(H + off) = hw;
    *reinterpret_cast<uint32_t*>(L + off) = lw;
}

// store a float pair as fp16 (hi only)
__device__ __forceinline__ void h2_store(__half* __restrict__ H, long off, float v0, float v1)
{
    __half h0 = __float2half(v0);
    __half h1 = __float2half(v1);
    uint32_t hw = (uint32_t)*reinterpret_cast<unsigned short*>(&h0)
                | ((uint32_t)*reinterpret_cast<unsigned short*>(&h1) << 16);
    *reinterpret_cast<uint32_t*>(H + off) = hw;
}

// split a float pair into fp16 hi/lo and store to smem
__device__ __forceinline__ void split2_sts(uint32_t ah, uint32_t al_, float v0, float v1)
{
    __half h0 = __float2half(v0);
    __half h1 = __float2half(v1);
    __half l0 = __float2half(v0 - __half2float(h0));
    __half l1 = __float2half(v1 - __half2float(h1));
    uint32_t hw = (uint32_t)*reinterpret_cast<unsigned short*>(&h0)
                | ((uint32_t)*reinterpret_cast<unsigned short*>(&h1) << 16);
    uint32_t lw = (uint32_t)*reinterpret_cast<unsigned short*>(&l0)
                | ((uint32_t)*reinterpret_cast<unsigned short*>(&l1) << 16);
    asm volatile("st.shared.b32 [%0], %1;" :: "r"(ah), "r"(hw) : "memory");
    asm volatile("st.shared.b32 [%0], %1;" :: "r"(al_), "r"(lw) : "memory");
}

// ---------------- NT HMMA GEMM, fp16 (A hi[/lo], B hi), 3-stage --------------
// C[m,n] (+= bias[n]) = sum_k A[m,k] * B[n,k]
// OUTMODE: 0 = fp32, 1 = fp16 hi/lo split, 2 = fp16 hi only
#define LDSB 80                    // smem bytes per tile row (32 fp16 + pad)
#define TILE_B (128 * LDSB)        // 10240
#define STAGE3 (3 * TILE_B)        // 30720 (Ah, Al, Bh)
#define GEMM_SMEM (3 * STAGE3)     // 92160  -> 2 CTAs/SM

template<bool BIAS, bool GATHER, int OUTMODE, bool A2>
__global__ void __launch_bounds__(256) gemm_mma(
    const __half* __restrict__ Ahb, const __half* __restrict__ Alb,
    const __half* __restrict__ Bhb,
    const float* __restrict__ bias, float* __restrict__ Cb,
    __half* __restrict__ Chb, __half* __restrict__ Clb,
    int M, int Ntot, int Kd,
    long sA, long sB, long sC,
    const int* __restrict__ idxmap)
{
    extern __shared__ char smem[];
    uint32_t sb = smem_u32(smem);

    int tid = threadIdx.x, wid = tid >> 5, lane = tid & 31;
    int warp_m = wid & 3, warp_n = wid >> 2;
    int bz = blockIdx.z;
    long aoff = GATHER ? (long)idxmap[bz] * sA : (long)bz * sA;
    const __half* Ah = Ahb + aoff;
    const __half* Al = A2 ? (Alb + aoff) : nullptr;
    const __half* Bh = Bhb + (long)bz * sB;

    int m0 = blockIdx.y * 128;
    int n0 = blockIdx.x * 128;

    float acc[2][8][4];
#pragma unroll
    for (int i = 0; i < 2; i++)
#pragma unroll
        for (int j = 0; j < 8; j++)
#pragma unroll
            for (int k = 0; k < 4; k++) acc[i][j][k] = 0.f;

    const int nch = Kd / 32;

    auto issue = [&](int ch) {
        uint32_t st = sb + (ch % 3) * STAGE3;
        int k0 = ch * 32;
#pragma unroll
        for (int it = 0; it < 2; it++) {
            int idx = tid + it * 256;
            int r = idx >> 2, c = idx & 3;
            uint32_t so = r * LDSB + c * 16;
            long gA = (long)(m0 + r) * Kd + k0 + c * 8;
            long gB = (long)(n0 + r) * Kd + k0 + c * 8;
            cpasync16(st + so,              Ah + gA);
            if (A2) cpasync16(st + TILE_B + so, Al + gA);
            cpasync16(st + 2 * TILE_B + so, Bh + gB);
        }
        CP_COMMIT();
    };

    issue(0);
    if (nch > 1) issue(1);
    if (nch > 2) issue(2);

    int lr = lane & 15, lc = lane >> 4;

    for (int ch = 0; ch < nch; ch++) {
        if (ch + 2 < nch)      { CP_WAIT2(); }
        else if (ch + 1 < nch) { CP_WAIT1(); }
        else                   { CP_WAIT0(); }
        __syncthreads();

        uint32_t stg = sb + (ch % 3) * STAGE3;
        uint32_t Ah_s = stg;
        uint32_t Al_s = stg + TILE_B;
        uint32_t Bh_s = stg + 2 * TILE_B;

#pragma unroll
        for (int ks = 0; ks < 2; ks++) {
            uint32_t koff = ks * 32 + lc * 16;
            uint32_t ah[2][4], al[2][4], bh[8][2];
#pragma unroll
            for (int mf = 0; mf < 2; mf++) {
                uint32_t row = warp_m * 32 + mf * 16 + lr;
                ldsm4(ah[mf], Ah_s + row * LDSB + koff);
                if (A2) ldsm4(al[mf], Al_s + row * LDSB + koff);
            }
#pragma unroll
            for (int p = 0; p < 4; p++) {
                uint32_t row = warp_n * 64 + p * 16 + lr;
                uint32_t t[4];
                ldsm4(t, Bh_s + row * LDSB + koff);
                bh[2 * p][0] = t[0]; bh[2 * p][1] = t[2];
                bh[2 * p + 1][0] = t[1]; bh[2 * p + 1][1] = t[3];
            }
#pragma unroll
            for (int mf = 0; mf < 2; mf++)
#pragma unroll
                for (int nf = 0; nf < 8; nf++) {
                    mma_f16(acc[mf][nf], ah[mf], bh[nf]);
                    if (A2) mma_f16(acc[mf][nf], al[mf], bh[nf]);
                }
        }
        __syncthreads();
        if (ch + 3 < nch) issue(ch + 3);
    }

#pragma unroll
    for (int mf = 0; mf < 2; mf++) {
        int row0 = m0 + warp_m * 32 + mf * 16 + (lane >> 2);
#pragma unroll
        for (int nf = 0; nf < 8; nf++) {
            int col = n0 + warp_n * 64 + nf * 8 + (lane & 3) * 2;
            float b0 = 0.f, b1 = 0.f;
            if (BIAS) { b0 = bias[col]; b1 = bias[col + 1]; }
            if (OUTMODE == 1) {
                __half* Ch = Chb + (long)blockIdx.z * sC;
                __half* Cl = Clb + (long)blockIdx.z * sC;
                if (row0 < M)
                    split2_store(Ch, Cl, (long)row0 * Ntot + col,
                                 acc[mf][nf][0] + b0, acc[mf][nf][1] + b1);
                if (row0 + 8 < M)
                    split2_store(Ch, Cl, (long)(row0 + 8) * Ntot + col,
                                 acc[mf][nf][2] + b0, acc[mf][nf][3] + b1);
            } else if (OUTMODE == 2) {
                __half* Ch = Chb + (long)blockIdx.z * sC;
                if (row0 < M)
                    h2_store(Ch, (long)row0 * Ntot + col,
                             acc[mf][nf][0] + b0, acc[mf][nf][1] + b1);
                if (row0 + 8 < M)
                    h2_store(Ch, (long)(row0 + 8) * Ntot + col,
                             acc[mf][nf][2] + b0, acc[mf][nf][3] + b1);
            } else {
                float* C = Cb + (long)blockIdx.z * sC;
                if (row0 < M) {
                    float2 v = make_float2(acc[mf][nf][0] + b0, acc[mf][nf][1] + b1);
                    *reinterpret_cast<float2*>(&C[(long)row0 * Ntot + col]) = v;
                }
                if (row0 + 8 < M) {
                    float2 v = make_float2(acc[mf][nf][2] + b0, acc[mf][nf][3] + b1);
                    *reinterpret_cast<float2*>(&C[(long)(row0 + 8) * Ntot + col]) = v;
                }
            }
        }
    }
}

// ---------------- NN HMMA GEMM (B row-major [k][n]), 1-term, 3-stage ---------
// C[m,n] = sum_k A[m,k] * B[k,n];  M = 128 fixed; output written as hi/lo fp16.
#define LDSB_N 272                       // 128 fp16 (256B) + 16B pad
#define NTILE_B (32 * LDSB_N)            // 8704
#define NSTAGE3 (TILE_B + NTILE_B)       // 18944 (Ah, Bh)
#define NN_SMEM (3 * NSTAGE3)            // 56832

__global__ void __launch_bounds__(256) gemm_mma_nn(
    const __half* __restrict__ Ahb,
    const __half* __restrict__ Bhb,
    __half* __restrict__ Chb, __half* __restrict__ Clb,
    int Ntot, int Kd, int ldB,
    long sA, long sB, long sC)
{
    extern __shared__ char smem[];
    uint32_t sb = smem_u32(smem);

    int tid = threadIdx.x, wid = tid >> 5, lane = tid & 31;
    int warp_m = wid & 3, warp_n = wid >> 2;
    int bz = blockIdx.z;
    const __half* Ah = Ahb + (long)bz * sA;
    const __half* Bh = Bhb + (long)bz * sB;
    __half* Ch = Chb + (long)bz * sC;
    __half* Cl = Clb + (long)bz * sC;

    int n0 = blockIdx.x * 128;

    float acc[2][8][4];
#pragma unroll
    for (int i = 0; i < 2; i++)
#pragma unroll
        for (int j = 0; j < 8; j++)
#pragma unroll
            for (int k = 0; k < 4; k++) acc[i][j][k] = 0.f;

    const int nch = Kd / 32;

    auto issue = [&](int ch) {
        uint32_t st = sb + (ch % 3) * NSTAGE3;
        int k0 = ch * 32;
#pragma unroll
        for (int it = 0; it < 2; it++) {
            int idx = tid + it * 256;
            int r = idx >> 2, c = idx & 3;
            uint32_t so = r * LDSB + c * 16;
            long gA = (long)r * Kd + k0 + c * 8;
            cpasync16(st + so, Ah + gA);
        }
#pragma unroll
        for (int it = 0; it < 2; it++) {
            int idx = tid + it * 256;
            int r = idx >> 4, c = idx & 15;
            uint32_t so = TILE_B + r * LDSB_N + c * 16;
            long gB = (long)(k0 + r) * ldB + n0 + c * 8;
            cpasync16(st + so, Bh + gB);
        }
        CP_COMMIT();
    };

    issue(0);
    if (nch > 1) issue(1);
    if (nch > 2) issue(2);

    int lr = lane & 15, lc = lane >> 4;
    int l8 = (lane >> 3) & 1;
    int krow = ((lane >> 4) & 1) * 8 + (lane & 7);   // 0..15

    for (int ch = 0; ch < nch; ch++) {
        if (ch + 2 < nch)      { CP_WAIT2(); }
        else if (ch + 1 < nch) { CP_WAIT1(); }
        else                   { CP_WAIT0(); }
        __syncthreads();

        uint32_t stg = sb + (ch % 3) * NSTAGE3;
        uint32_t Ah_s = stg;
        uint32_t Bh_s = stg + TILE_B;

#pragma unroll
        for (int ks = 0; ks < 2; ks++) {
            uint32_t koff = ks * 32 + lc * 16;
            uint32_t ah[2][4], bh[8][2];
#pragma unroll
            for (int mf = 0; mf < 2; mf++) {
                uint32_t row = warp_m * 32 + mf * 16 + lr;
                ldsm4(ah[mf], Ah_s + row * LDSB + koff);
            }
            uint32_t brow = (ks * 16 + krow) * LDSB_N + warp_n * 128 + l8 * 16;
#pragma unroll
            for (int p = 0; p < 4; p++) {
                uint32_t t[4];
                ldsm4t(t, Bh_s + brow + p * 32);
                bh[2 * p][0] = t[0]; bh[2 * p][1] = t[2];
                bh[2 * p + 1][0] = t[1]; bh[2 * p + 1][1] = t[3];
            }
#pragma unroll
            for (int mf = 0; mf < 2; mf++)
#pragma unroll
                for (int nf = 0; nf < 8; nf++)
                    mma_f16(acc[mf][nf], ah[mf], bh[nf]);
        }
        __syncthreads();
        if (ch + 3 < nch) issue(ch + 3);
    }

    // epilogue: split to fp16 hi/lo (M = 128 exact, no bounds checks)
#pragma unroll
    for (int mf = 0; mf < 2; mf++) {
        int row0 = warp_m * 32 + mf * 16 + (lane >> 2);
#pragma unroll
        for (int nf = 0; nf < 8; nf++) {
            int col = n0 + warp_n * 64 + nf * 8 + (lane & 3) * 2;
            split2_store(Ch, Cl, (long)row0 * Ntot + col, acc[mf][nf][0], acc[mf][nf][1]);
            split2_store(Ch, Cl, (long)(row0 + 8) * Ntot + col, acc[mf][nf][2], acc[mf][nf][3]);
        }
    }
}

// ---------------- HMMA flash attention (fp16; q 2-term, P 2-term) -----------
// grid (9, HH, BB); 256 threads (8 warps x 16 q-rows).
#define SKV 144
#define LDSK 144
#define LDSQ 144
#define LDSP 304
#define A_KH 0                           // 144*144 = 20736
#define A_VH 20736
#define A_QH 41472                       // 128*144 = 18432
#define A_QL (A_QH + 18432)              // ..78336
#define A_PH A_QH                        // P reuses q region (after sync)
#define A_PL (A_PH + 128 * LDSP)         // 80384
#define ATTN_SMEM (A_PL + 128 * LDSP)    // 119296

__global__ void __launch_bounds__(256) attn_mma(
    const __half* __restrict__ qh_g, const __half* __restrict__ ql_g,
    const __half* __restrict__ kvh,
    __half* __restrict__ yh)
{
    extern __shared__ char smem[];
    uint32_t sb = smem_u32(smem);
    int tid = threadIdx.x, wid = tid >> 5, lane = tid & 31;
    int n0 = blockIdx.x * 128;
    int h = blockIdx.y, b = blockIdx.z;

    // ---- loads: K/V hi rows (133) + q hi/lo tile (128 rows) ----
    for (int i = tid; i < CC * 8; i += 256) {
        int m = i >> 3, c = i & 7;
        long g = ((long)(b * CC + m) * 2) * DD + h * HD + c * 8;
        uint32_t so = m * LDSK + c * 16;
        cpasync16(sb + A_KH + so, kvh + g);
        cpasync16(sb + A_VH + so, kvh + g + DD);
    }
    for (int i = tid; i < 128 * 8; i += 256) {
        int r = i >> 3, c = i & 7;
        int qrow = n0 + r; if (qrow >= NN_TOK) qrow = 0;
        long g = (long)(b * NN_TOK + qrow) * DD + h * HD + c * 8;
        cpasync16(sb + A_QH + r * LDSQ + c * 16, qh_g + g);
        cpasync16(sb + A_QL + r * LDSQ + c * 16, ql_g + g);
    }
    CP_COMMIT();
    // zero K/V pad rows 133..143 (V pad must be 0)
    for (int i = tid; i < (SKV - CC) * 32; i += 256) {
        int m = CC + i / 32; int w4 = (i % 32) * 4;
        uint32_t so = m * LDSK + w4;
        *reinterpret_cast<uint32_t*>(smem + A_KH + so) = 0;
        *reinterpret_cast<uint32_t*>(smem + A_VH + so) = 0;
    }
    CP_WAIT0();
    __syncthreads();

    int lr = lane & 15, lg = lane >> 4;

    // ---- S = q @ k^T : warp tile 16 x 144, 2-term ----
    float sacc[18][4];
#pragma unroll
    for (int f = 0; f < 18; f++)
#pragma unroll
        for (int k = 0; k < 4; k++) sacc[f][k] = 0.f;

#pragma unroll
    for (int ks = 0; ks < 4; ks++) {
        uint32_t koff = ks * 32 + lg * 16;
        uint32_t ah[4], al[4];
        ldsm4(ah, sb + A_QH + (wid * 16 + lr) * LDSQ + koff);
        ldsm4(al, sb + A_QL + (wid * 16 + lr) * LDSQ + koff);
#pragma unroll
        for (int p = 0; p < 9; p++) {
            uint32_t th[4];
            ldsm4(th, sb + A_KH + (p * 16 + lr) * LDSK + koff);
            uint32_t bh0[2] = { th[0], th[2] }, bh1[2] = { th[1], th[3] };
            mma_f16(sacc[2 * p],     ah, bh0);
            mma_f16(sacc[2 * p],     al, bh0);
            mma_f16(sacc[2 * p + 1], ah, bh1);
            mma_f16(sacc[2 * p + 1], al, bh1);
        }
    }

    // ---- softmax (no-max exp; scale folded into Wq) ----
    float s0 = 0.f, s1 = 0.f;
#pragma unroll
    for (int f = 0; f < 18; f++) {
        int col = f * 8 + (lane & 3) * 2;
        float e0 = (col     < CC) ? __expf(sacc[f][0]) : 0.f;
        float e1 = (col + 1 < CC) ? __expf(sacc[f][1]) : 0.f;
        float e2 = (col     < CC) ? __expf(sacc[f][2]) : 0.f;
        float e3 = (col + 1 < CC) ? __expf(sacc[f][3]) : 0.f;
        sacc[f][0] = e0; sacc[f][1] = e1; sacc[f][2] = e2; sacc[f][3] = e3;
        s0 += e0 + e1; s1 += e2 + e3;
    }
    s0 += __shfl_xor_sync(0xffffffffu, s0, 1);
    s0 += __shfl_xor_sync(0xffffffffu, s0, 2);
    s1 += __shfl_xor_sync(0xffffffffu, s1, 1);
    s1 += __shfl_xor_sync(0xffffffffu, s1, 2);
    float i0 = 1.f / s0, i1 = 1.f / s1;

    __syncthreads();   // all warps done reading q before P overwrites it

    // ---- write normalized P (fp16 hi/lo) to smem ----
    int prow0 = wid * 16 + (lane >> 2), prow1 = prow0 + 8;
#pragma unroll
    for (int f = 0; f < 18; f++) {
        uint32_t colb = (f * 8 + (lane & 3) * 2) * 2;
        split2_sts(sb + A_PH + prow0 * LDSP + colb, sb + A_PL + prow0 * LDSP + colb,
                   sacc[f][0] * i0, sacc[f][1] * i0);
        split2_sts(sb + A_PH + prow1 * LDSP + colb, sb + A_PL + prow1 * LDSP + colb,
                   sacc[f][2] * i1, sacc[f][3] * i1);
    }
    __syncthreads();

    // ---- y = P @ V : warp tile 16 x 64, k = 144, 2-term ----
    float yacc[8][4];
#pragma unroll
    for (int f = 0; f < 8; f++)
#pragma unroll
        for (int k = 0; k < 4; k++) yacc[f][k] = 0.f;

    int l8 = (lane >> 3) & 1;
    int krow = ((lane >> 4) & 1) * 8 + (lane & 7);
#pragma unroll
    for (int ks = 0; ks < 9; ks++) {
        uint32_t ph[4], pl[4];
        ldsm4(ph, sb + A_PH + (wid * 16 + lr) * LDSP + ks * 32 + lg * 16);
        ldsm4(pl, sb + A_PL + (wid * 16 + lr) * LDSP + ks * 32 + lg * 16);
        uint32_t vrow = (ks * 16 + krow) * LDSK + l8 * 16;
#pragma unroll
        for (int p = 0; p < 4; p++) {
            uint32_t th[4];
            ldsm4t(th, sb + A_VH + vrow + p * 32);
            uint32_t bh0[2] = { th[0], th[2] }, bh1[2] = { th[1], th[3] };
            mma_f16(yacc[2 * p],     ph, bh0);
            mma_f16(yacc[2 * p],     pl, bh0);
            mma_f16(yacc[2 * p + 1], ph, bh1);
            mma_f16(yacc[2 * p + 1], pl, bh1);
        }
    }

    // ---- store y (fp16 hi only), masked to valid rows ----
    int row0 = n0 + wid * 16 + (lane >> 2);
    int row1 = row0 + 8;
#pragma unroll
    for (int f = 0; f < 8; f++) {
        int col = f * 8 + (lane & 3) * 2;
        if (row0 < NN_TOK)
            h2_store(yh, (long)(b * NN_TOK + row0) * DD + h * HD + col,
                     yacc[f][0], yacc[f][1]);
        if (row1 < NN_TOK)
            h2_store(yh, (long)(b * NN_TOK + row1) * DD + h * HD + col,
                     yacc[f][2], yacc[f][3]);
    }
}

// ---------------- split fp32 -> fp16 hi/lo (8 elems / thread) ----------------
__global__ __launch_bounds__(256) void split_kernel(
    const float4* __restrict__ in, uint4* __restrict__ hi, uint4* __restrict__ lo, long n8)
{
    long i = (long)blockIdx.x * 256 + threadIdx.x;
    if (i >= n8) return;
    float4 a = in[2 * i], b = in[2 * i + 1];
    float v[8] = { a.x, a.y, a.z, a.w, b.x, b.y, b.z, b.w };
    uint32_t hw[8], lw[8];
#pragma unroll
    for (int j = 0; j < 8; j++) {
        __half h = __float2half(v[j]);
        __half l = __float2half(v[j] - __half2float(h));
        hw[j] = *reinterpret_cast<unsigned short*>(&h);
        lw[j] = *reinterpret_cast<unsigned short*>(&l);
    }
    uint4 H, L;
    H.x = hw[0] | (hw[1] << 16); H.y = hw[2] | (hw[3] << 16);
    H.z = hw[4] | (hw[5] << 16); H.w = hw[6] | (hw[7] << 16);
    L.x = lw[0] | (lw[1] << 16); L.y = lw[2] | (lw[3] << 16);
    L.z = lw[4] | (lw[5] << 16); L.w = lw[6] | (lw[7] << 16);
    hi[i] = H; lo[i] = L;
}

// ---------------- fp32 -> fp16 hi-only convert (contiguous) -----------------
__global__ __launch_bounds__(256) void hconv_kernel(
    const float* __restrict__ in, __half* __restrict__ oh, long n)
{
    long i = (long)blockIdx.x * 256 + threadIdx.x;
    if (i * 2 + 1 >= n) return;
    float2 v = reinterpret_cast<const float2*>(in)[i];
    h2_store(oh, i * 2, v.x, v.y);
}

// ------------ transpose weights (scale folded), fp16 hi only -----------------
__global__ __launch_bounds__(256) void tsplit_kernel(
    const float* __restrict__ W, __half* __restrict__ hiT,
    int Kd, int Nc, float scale)
{
    int idx = blockIdx.x * 256 + threadIdx.x;
    if (idx >= Kd * Nc) return;
    int k = idx / Nc, n = idx % Nc;
    hiT[(long)n * Kd + k] = __float2half(W[idx] * scale);
}

// ---------------- kernel 1: cls_n, sims, argmax ----------------
__global__ __launch_bounds__(256) void cls_kernel(
    const float* __restrict__ x, const float* __restrict__ cents,
    float* __restrict__ out_cls, float* __restrict__ out_idx, int* __restrict__ idx)
{
    int b = blockIdx.x;
    int t = threadIdx.x;
    __shared__ float red[256];
    __shared__ float snorm;
    __shared__ float best_s;
    __shared__ int best_i;

    const float* xr = x + (long)b * NN_TOK * DD;
    float loc[3];
    float ss = 0.f;
#pragma unroll
    for (int i = 0; i < 3; i++) { loc[i] = xr[t + i * 256]; ss += loc[i] * loc[i]; }
    red[t] = ss; __syncthreads();
    for (int s = 128; s > 0; s >>= 1) { if (t < s) red[t] += red[t + s]; __syncthreads(); }
    if (t == 0) snorm = fmaxf(sqrtf(red[0]), 1e-12f);
    __syncthreads();
    float inv = 1.0f / snorm;
    float c[3];
#pragma unroll
    for (int i = 0; i < 3; i++) {
        c[i] = loc[i] * inv;
        out_cls[(long)b * DD + t + i * 256] = c[i];
    }
    if (t == 0) { best_s = -1e30f; best_i = 0; }
    __syncthreads();
    for (int m = 0; m < MM; m++) {
        float p = 0.f;
#pragma unroll
        for (int i = 0; i < 3; i++) p += c[i] * cents[(long)m * DD + t + i * 256];
        red[t] = p; __syncthreads();
        for (int s = 128; s > 0; s >>= 1) { if (t < s) red[t] += red[t + s]; __syncthreads(); }
        if (t == 0) { if (red[0] > best_s) { best_s = red[0]; best_i = m; } }
        __syncthreads();
    }
    if (t == 0) { idx[b] = best_i; out_idx[b] = (float)best_i; }
}

// ---------------- softmax over rows of length 1024, emit fp16 hi ------------
__global__ __launch_bounds__(256) void softmax1024_h(
    const float* __restrict__ s, __half* __restrict__ oh)
{
    long row = blockIdx.x;
    const float* p = s + row * PP;
    int t = threadIdx.x;
    __shared__ float red[256];

    float4 v = reinterpret_cast<const float4*>(p)[t];
    float mx = fmaxf(fmaxf(v.x, v.y), fmaxf(v.z, v.w));
    red[t] = mx; __syncthreads();
    for (int st = 128; st > 0; st >>= 1) { if (t < st) red[t] = fmaxf(red[t], red[t + st]); __syncthreads(); }
    mx = red[0]; __syncthreads();

    v.x = expf(v.x - mx); v.y = expf(v.y - mx);
    v.z = expf(v.z - mx); v.w = expf(v.w - mx);
    float sm = v.x + v.y + v.z + v.w;
    red[t] = sm; __syncthreads();
    for (int st = 128; st > 0; st >>= 1) { if (t < st) red[t] += red[t + st]; __syncthreads(); }
    float inv = 1.0f / red[0];
    v.x *= inv; v.y *= inv; v.z *= inv; v.w *= inv;

    long off = row * PP + (long)t * 4;
    h2_store(oh, off,     v.x, v.y);
    h2_store(oh, off + 2, v.z, v.w);
}

// ---------------- copy x[:, :R, :] into ctx hi/lo rows 0..R-1 ---------------
__global__ __launch_bounds__(256) void copy_xreg_split(
    const float* __restrict__ x, __half* __restrict__ ch, __half* __restrict__ cl)
{
    long i = (long)blockIdx.x * blockDim.x + threadIdx.x;   // float4 index
    long total = (long)BB * RR * DD / 4;
    if (i >= total) return;
    long per_b = (long)RR * DD / 4;
    long b = i / per_b;
    long r = i - b * per_b;
    float4 v = reinterpret_cast<const float4*>(x)[b * ((long)NN_TOK * DD / 4) + r];
    long off = b * (long)CC * DD + r * 4;
    split2_store(ch, cl, off,     v.x, v.y);
    split2_store(ch, cl, off + 2, v.z, v.w);
}

// ---------------- launch ----------------
extern "C" void kernel_launch(void* const* d_in, const int* in_sizes, int n_in,
                              void* d_out, int out_size)
{
    const float* x      = (const float*)d_in[0];
    const float* Qb     = (const float*)d_in[1];
    const float* Wq     = (const float*)d_in[2];
    const float* Wctx   = (const float*)d_in[3];
    const float* bctx   = (const float*)d_in[4];
    const float* Wout   = (const float*)d_in[5];
    const float* bout   = (const float*)d_in[6];
    const float* cents  = (const float*)d_in[7];
    float* out = (float*)d_out;

    void *p_idx, *p_scores;
    void *p_xh, *p_xl, *p_yh, *p_qh, *p_ql, *p_kvh;
    void *p_ch, *p_cl, *p_sh;
    void *p_qbh, *p_wqh, *p_woh, *p_wch;
    cudaGetSymbolAddress(&p_idx, g_idx);
    cudaGetSymbolAddress(&p_scores, g_scores);
    cudaGetSymbolAddress(&p_xh, g_x_hi);   cudaGetSymbolAddress(&p_xl, g_x_lo);
    cudaGetSymbolAddress(&p_yh, g_y_hi);
    cudaGetSymbolAddress(&p_qh, g_q_hi);   cudaGetSymbolAddress(&p_ql, g_q_lo);
    cudaGetSymbolAddress(&p_kvh, g_kv_hi);
    cudaGetSymbolAddress(&p_ch, g_c_hi);   cudaGetSymbolAddress(&p_cl, g_c_lo);
    cudaGetSymbolAddress(&p_sh, g_s_hi);
    cudaGetSymbolAddress(&p_qbh, g_qb_hi);
    cudaGetSymbolAddress(&p_wqh, g_wq_hi);
    cudaGetSymbolAddress(&p_woh, g_wo_hi);
    cudaGetSymbolAddress(&p_wch, g_wc_hi);

    int*   idxp   = (int*)p_idx;
    float* scores = (float*)p_scores;
    __half *xh = (__half*)p_xh,  *xl = (__half*)p_xl;
    __half *yh = (__half*)p_yh;
    __half *qh = (__half*)p_qh,  *ql = (__half*)p_ql;
    __half *kvh = (__half*)p_kvh;
    __half *ch = (__half*)p_ch,  *cl = (__half*)p_cl;
    __half *shp = (__half*)p_sh;
    __half *qbh = (__half*)p_qbh;
    __half *wqh = (__half*)p_wqh;
    __half *woh = (__half*)p_woh;
    __half *wch = (__half*)p_wch;

    cudaFuncSetAttribute(gemm_mma<false, true,  0, false>, cudaFuncAttributeMaxDynamicSharedMemorySize, GEMM_SMEM);
    cudaFuncSetAttribute(gemm_mma<true,  false, 2, true>,  cudaFuncAttributeMaxDynamicSharedMemorySize, GEMM_SMEM);
    cudaFuncSetAttribute(gemm_mma<false, false, 1, false>, cudaFuncAttributeMaxDynamicSharedMemorySize, GEMM_SMEM);
    cudaFuncSetAttribute(gemm_mma<true,  false, 0, false>, cudaFuncAttributeMaxDynamicSharedMemorySize, GEMM_SMEM);
    cudaFuncSetAttribute(gemm_mma_nn, cudaFuncAttributeMaxDynamicSharedMemorySize, NN_SMEM);
    cudaFuncSetAttribute(attn_mma, cudaFuncAttributeMaxDynamicSharedMemorySize, ATTN_SMEM);

    // 1. cls_n / idx
    cls_kernel<<<BB, 256>>>(x, cents, out + OUT_CLS, out + OUT_IDX, idxp);

    // 2. precision conversions
    {
        long n8 = (long)BB * NN_TOK * DD / 8;
        split_kernel<<<(unsigned)((n8 + 255) / 256), 256>>>(
            (const float4*)x, (uint4*)xh, (uint4*)xl, n8);
        long qn = (long)MM * KK * DD;
        hconv_kernel<<<(unsigned)((qn / 2 + 255) / 256), 256>>>(Qb, qbh, qn);
        tsplit_kernel<<<(DD * DD + 255) / 256, 256>>>(Wq, wqh, DD, DD, 0.125f);
        tsplit_kernel<<<(DD * DD + 255) / 256, 256>>>(Wout, woh, DD, DD, 1.0f);
        tsplit_kernel<<<(DD * 2 * DD + 255) / 256, 256>>>(Wctx, wch, DD, 2 * DD, 1.0f);
    }

    // 3. scores = Q_banks[idx] @ xp^T — NT 1-term, fp32 out
    gemm_mma<false, true, 0, false><<<dim3(PP / 128, 1, BB), 256, GEMM_SMEM>>>(
        qbh, nullptr, xh + (long)RR * DD, nullptr, scores, nullptr, nullptr,
        KK, PP, DD,
        (long)KK * DD, (long)NN_TOK * DD, (long)KK * PP, idxp);

    // 4. softmax -> fp16 hi attn weights
    softmax1024_h<<<BB * KK, 256>>>(scores, shp);

    // 5. ctx[:, :R] = xreg (split hi/lo)
    {
        long total = (long)BB * RR * DD / 4;
        copy_xreg_split<<<(unsigned)((total + 255) / 256), 256>>>(x, ch, cl);
    }

    // 6. ctx[:, R:] = attn @ xp — NN 1-term, hi/lo out
    gemm_mma_nn<<<dim3(DD / 128, 1, BB), 256, NN_SMEM>>>(
        shp, xh + (long)RR * DD,
        ch + (long)RR * DD, cl + (long)RR * DD,
        DD, PP, DD,
        (long)KK * PP, (long)NN_TOK * DD, (long)CC * DD);

    // 7. kv = ctx @ Wctx + bctx — NT 2-term (ctx hi/lo), fp16 hi out
    gemm_mma<true, false, 2, true><<<dim3(2 * DD / 128, MPAD_C / 128, 1), 256, GEMM_SMEM>>>(
        ch, cl, wch, bctx, nullptr, kvh, nullptr,
        BB * CC, 2 * DD, DD, 0, 0, 0, nullptr);

    // 8. q = x @ (Wq/8) — NT 1-term, hi/lo out (attention uses both)
    gemm_mma<false, false, 1, false><<<dim3(DD / 128, MPAD_X / 128, 1), 256, GEMM_SMEM>>>(
        xh, nullptr, wqh, nullptr, nullptr, qh, ql,
        BB * NN_TOK, DD, DD, 0, 0, 0, nullptr);

    // 9. attention — HMMA flash, y hi out
    attn_mma<<<dim3((NN_TOK + 127) / 128, HH, BB), 256, ATTN_SMEM>>>(
        qh, ql, kvh, yh);

    // 10. out = y @ Wout + bout — NT 1-term, fp32 out
    gemm_mma<true, false, 0, false><<<dim3(DD / 128, MPAD_X / 128, 1), 256, GEMM_SMEM>>>(
        yh, nullptr, woh, bout, out, nullptr, nullptr,
        BB * NN_TOK, DD, DD, 0, 0, 0, nullptr);
}

// round 9
// speedup vs baseline: 3.3871x; 1.1892x over previous
#include <cuda_runtime.h>
#include <cuda_fp16.h>
#include <math.h>
#include <stdint.h>

// ---------------- problem constants ----------------
#define BB 64
#define NN_TOK 1029
#define DD 768
#define HH 12
#define HD 64
#define KK 128
#define RR 5
#define MM 4
#define PP 1024              // N - R
#define CC 133               // R + K

#define MPAD_X 65920         // 515*128  (>= B*N = 65856)
#define MPAD_C 8576          // 67*128   (>= B*C = 8512)

// output layout: [out (B*N*D)] [cls_n (B*D)] [idx (B)]
#define OUT_CLS ((long)BB * NN_TOK * DD)
#define OUT_IDX (OUT_CLS + (long)BB * DD)

// ---------------- scratch (device globals; no allocs allowed) ----------------
__device__ int   g_idx[BB];
__device__ float g_scores[(long)BB * KK * PP];

// fp16 split buffers (zero-init covers padding rows)
__device__ __half g_x_hi[(long)MPAD_X * DD];
__device__ __half g_x_lo[(long)MPAD_X * DD];
__device__ __half g_y_hi[(long)MPAD_X * DD];
__device__ __half g_q_hi[(long)MPAD_X * DD];
__device__ __half g_q_lo[(long)MPAD_X * DD];
__device__ __half g_kv_hi[(long)MPAD_C * 2 * DD];
__device__ __half g_c_hi[(long)MPAD_C * DD];
__device__ __half g_s_hi[(long)BB * KK * PP];   // attn weights hi
__device__ __half g_qb_hi[(long)MM * KK * DD];
__device__ __half g_wq_hi[DD * DD];
__device__ __half g_wo_hi[DD * DD];
__device__ __half g_wc_hi[2 * DD * DD];

// ---------------- PTX helpers ----------------
__device__ __forceinline__ uint32_t smem_u32(const void* p) {
    uint32_t a;
    asm("{ .reg .u64 t; cvta.to.shared.u64 t, %1; cvt.u32.u64 %0, t; }" : "=r"(a) : "l"(p));
    return a;
}
__device__ __forceinline__ void cpasync16(uint32_t dst, const void* src) {
    asm volatile("cp.async.cg.shared.global [%0], [%1], 16;" :: "r"(dst), "l"(src));
}
#define CP_COMMIT() asm volatile("cp.async.commit_group;" ::: "memory")
#define CP_WAIT2()  asm volatile("cp.async.wait_group 2;" ::: "memory")
#define CP_WAIT1()  asm volatile("cp.async.wait_group 1;" ::: "memory")
#define CP_WAIT0()  asm volatile("cp.async.wait_group 0;" ::: "memory")

__device__ __forceinline__ void ldsm4(uint32_t* r, uint32_t addr) {
    asm volatile("ldmatrix.sync.aligned.m8n8.x4.shared.b16 {%0,%1,%2,%3}, [%4];"
        : "=r"(r[0]), "=r"(r[1]), "=r"(r[2]), "=r"(r[3]) : "r"(addr));
}
__device__ __forceinline__ void ldsm4t(uint32_t* r, uint32_t addr) {
    asm volatile("ldmatrix.sync.aligned.m8n8.x4.trans.shared.b16 {%0,%1,%2,%3}, [%4];"
        : "=r"(r[0]), "=r"(r[1]), "=r"(r[2]), "=r"(r[3]) : "r"(addr));
}
__device__ __forceinline__ void mma_f16(float* c, const uint32_t* a, const uint32_t* b) {
    asm volatile(
        "mma.sync.aligned.m16n8k16.row.col.f32.f16.f16.f32 "
        "{%0,%1,%2,%3}, {%4,%5,%6,%7}, {%8,%9}, {%0,%1,%2,%3};"
        : "+f"(c[0]), "+f"(c[1]), "+f"(c[2]), "+f"(c[3])
        : "r"(a[0]), "r"(a[1]), "r"(a[2]), "r"(a[3]), "r"(b[0]), "r"(b[1]));
}

// split a float pair into fp16 hi/lo and store packed (global)
__device__ __forceinline__ void split2_store(
    __half* __restrict__ H, __half* __restrict__ L, long off, float v0, float v1)
{
    __half h0 = __float2half(v0);
    __half h1 = __float2half(v1);
    __half l0 = __float2half(v0 - __half2float(h0));
    __half l1 = __float2half(v1 - __half2float(h1));
    uint32_t hw = (uint32_t)*reinterpret_cast<unsigned short*>(&h0)
                | ((uint32_t)*reinterpret_cast<unsigned short*>(&h1) << 16);
    uint32_t lw = (uint32_t)*reinterpret_cast<unsigned short*>(&l0)
                | ((uint32_t)*reinterpret_cast<unsigned short*>(&l1) << 16);
    *reinterpret_cast<uint32_t*>(H + off) = hw;
    *reinterpret_cast<uint32_t*>(L + off) = lw;
}

// store a float pair as fp16 (hi only)
__device__ __forceinline__ void h2_store(__half* __restrict__ H, long off, float v0, float v1)
{
    __half h0 = __float2half(v0);
    __half h1 = __float2half(v1);
    uint32_t hw = (uint32_t)*reinterpret_cast<unsigned short*>(&h0)
                | ((uint32_t)*reinterpret_cast<unsigned short*>(&h1) << 16);
    *reinterpret_cast<uint32_t*>(H + off) = hw;
}

// store a float pair as fp16 to smem
__device__ __forceinline__ void h2_sts(uint32_t addr, float v0, float v1)
{
    __half h0 = __float2half(v0);
    __half h1 = __float2half(v1);
    uint32_t hw = (uint32_t)*reinterpret_cast<unsigned short*>(&h0)
                | ((uint32_t)*reinterpret_cast<unsigned short*>(&h1) << 16);
    asm volatile("st.shared.b32 [%0], %1;" :: "r"(addr), "r"(hw) : "memory");
}

// ---------------- NT HMMA GEMM, fp16 (A hi[/lo], B hi), 3-stage --------------
// C[m,n] (+= bias[n]) = sum_k A[m,k] * B[n,k]
// OUTMODE: 0 = fp32, 1 = fp16 hi/lo split, 2 = fp16 hi only
#define LDSB 80                    // smem bytes per tile row (32 fp16 + pad)
#define TILE_B (128 * LDSB)        // 10240
#define STAGE3 (3 * TILE_B)        // 30720 (Ah, Al, Bh)
#define GEMM_SMEM (3 * STAGE3)     // 92160  -> 2 CTAs/SM

template<bool BIAS, bool GATHER, int OUTMODE, bool A2>
__global__ void __launch_bounds__(256) gemm_mma(
    const __half* __restrict__ Ahb, const __half* __restrict__ Alb,
    const __half* __restrict__ Bhb,
    const float* __restrict__ bias, float* __restrict__ Cb,
    __half* __restrict__ Chb, __half* __restrict__ Clb,
    int M, int Ntot, int Kd,
    long sA, long sB, long sC,
    const int* __restrict__ idxmap)
{
    extern __shared__ char smem[];
    uint32_t sb = smem_u32(smem);

    int tid = threadIdx.x, wid = tid >> 5, lane = tid & 31;
    int warp_m = wid & 3, warp_n = wid >> 2;
    int bz = blockIdx.z;
    long aoff = GATHER ? (long)idxmap[bz] * sA : (long)bz * sA;
    const __half* Ah = Ahb + aoff;
    const __half* Al = A2 ? (Alb + aoff) : nullptr;
    const __half* Bh = Bhb + (long)bz * sB;

    int m0 = blockIdx.y * 128;
    int n0 = blockIdx.x * 128;

    float acc[2][8][4];
#pragma unroll
    for (int i = 0; i < 2; i++)
#pragma unroll
        for (int j = 0; j < 8; j++)
#pragma unroll
            for (int k = 0; k < 4; k++) acc[i][j][k] = 0.f;

    const int nch = Kd / 32;

    auto issue = [&](int ch) {
        uint32_t st = sb + (ch % 3) * STAGE3;
        int k0 = ch * 32;
#pragma unroll
        for (int it = 0; it < 2; it++) {
            int idx = tid + it * 256;
            int r = idx >> 2, c = idx & 3;
            uint32_t so = r * LDSB + c * 16;
            long gA = (long)(m0 + r) * Kd + k0 + c * 8;
            long gB = (long)(n0 + r) * Kd + k0 + c * 8;
            cpasync16(st + so,              Ah + gA);
            if (A2) cpasync16(st + TILE_B + so, Al + gA);
            cpasync16(st + 2 * TILE_B + so, Bh + gB);
        }
        CP_COMMIT();
    };

    issue(0);
    if (nch > 1) issue(1);
    if (nch > 2) issue(2);

    int lr = lane & 15, lc = lane >> 4;

    for (int ch = 0; ch < nch; ch++) {
        if (ch + 2 < nch)      { CP_WAIT2(); }
        else if (ch + 1 < nch) { CP_WAIT1(); }
        else                   { CP_WAIT0(); }
        __syncthreads();

        uint32_t stg = sb + (ch % 3) * STAGE3;
        uint32_t Ah_s = stg;
        uint32_t Al_s = stg + TILE_B;
        uint32_t Bh_s = stg + 2 * TILE_B;

#pragma unroll
        for (int ks = 0; ks < 2; ks++) {
            uint32_t koff = ks * 32 + lc * 16;
            uint32_t ah[2][4], al[2][4], bh[8][2];
#pragma unroll
            for (int mf = 0; mf < 2; mf++) {
                uint32_t row = warp_m * 32 + mf * 16 + lr;
                ldsm4(ah[mf], Ah_s + row * LDSB + koff);
                if (A2) ldsm4(al[mf], Al_s + row * LDSB + koff);
            }
#pragma unroll
            for (int p = 0; p < 4; p++) {
                uint32_t row = warp_n * 64 + p * 16 + lr;
                uint32_t t[4];
                ldsm4(t, Bh_s + row * LDSB + koff);
                bh[2 * p][0] = t[0]; bh[2 * p][1] = t[2];
                bh[2 * p + 1][0] = t[1]; bh[2 * p + 1][1] = t[3];
            }
#pragma unroll
            for (int mf = 0; mf < 2; mf++)
#pragma unroll
                for (int nf = 0; nf < 8; nf++) {
                    mma_f16(acc[mf][nf], ah[mf], bh[nf]);
                    if (A2) mma_f16(acc[mf][nf], al[mf], bh[nf]);
                }
        }
        __syncthreads();
        if (ch + 3 < nch) issue(ch + 3);
    }

#pragma unroll
    for (int mf = 0; mf < 2; mf++) {
        int row0 = m0 + warp_m * 32 + mf * 16 + (lane >> 2);
#pragma unroll
        for (int nf = 0; nf < 8; nf++) {
            int col = n0 + warp_n * 64 + nf * 8 + (lane & 3) * 2;
            float b0 = 0.f, b1 = 0.f;
            if (BIAS) { b0 = bias[col]; b1 = bias[col + 1]; }
            if (OUTMODE == 1) {
                __half* Ch = Chb + (long)blockIdx.z * sC;
                __half* Cl = Clb + (long)blockIdx.z * sC;
                if (row0 < M)
                    split2_store(Ch, Cl, (long)row0 * Ntot + col,
                                 acc[mf][nf][0] + b0, acc[mf][nf][1] + b1);
                if (row0 + 8 < M)
                    split2_store(Ch, Cl, (long)(row0 + 8) * Ntot + col,
                                 acc[mf][nf][2] + b0, acc[mf][nf][3] + b1);
            } else if (OUTMODE == 2) {
                __half* Ch = Chb + (long)blockIdx.z * sC;
                if (row0 < M)
                    h2_store(Ch, (long)row0 * Ntot + col,
                             acc[mf][nf][0] + b0, acc[mf][nf][1] + b1);
                if (row0 + 8 < M)
                    h2_store(Ch, (long)(row0 + 8) * Ntot + col,
                             acc[mf][nf][2] + b0, acc[mf][nf][3] + b1);
            } else {
                float* C = Cb + (long)blockIdx.z * sC;
                if (row0 < M) {
                    float2 v = make_float2(acc[mf][nf][0] + b0, acc[mf][nf][1] + b1);
                    *reinterpret_cast<float2*>(&C[(long)row0 * Ntot + col]) = v;
                }
                if (row0 + 8 < M) {
                    float2 v = make_float2(acc[mf][nf][2] + b0, acc[mf][nf][3] + b1);
                    *reinterpret_cast<float2*>(&C[(long)(row0 + 8) * Ntot + col]) = v;
                }
            }
        }
    }
}

// ---------------- NN HMMA GEMM (B row-major [k][n]), 1-term, 3-stage ---------
// C[m,n] = sum_k A[m,k] * B[k,n];  M = 128 fixed; output fp16 hi only.
#define LDSB_N 272                       // 128 fp16 (256B) + 16B pad
#define NTILE_B (32 * LDSB_N)            // 8704
#define NSTAGE3 (TILE_B + NTILE_B)       // 18944 (Ah, Bh)
#define NN_SMEM (3 * NSTAGE3)            // 56832

__global__ void __launch_bounds__(256) gemm_mma_nn(
    const __half* __restrict__ Ahb,
    const __half* __restrict__ Bhb,
    __half* __restrict__ Chb,
    int Ntot, int Kd, int ldB,
    long sA, long sB, long sC)
{
    extern __shared__ char smem[];
    uint32_t sb = smem_u32(smem);

    int tid = threadIdx.x, wid = tid >> 5, lane = tid & 31;
    int warp_m = wid & 3, warp_n = wid >> 2;
    int bz = blockIdx.z;
    const __half* Ah = Ahb + (long)bz * sA;
    const __half* Bh = Bhb + (long)bz * sB;
    __half* Ch = Chb + (long)bz * sC;

    int n0 = blockIdx.x * 128;

    float acc[2][8][4];
#pragma unroll
    for (int i = 0; i < 2; i++)
#pragma unroll
        for (int j = 0; j < 8; j++)
#pragma unroll
            for (int k = 0; k < 4; k++) acc[i][j][k] = 0.f;

    const int nch = Kd / 32;

    auto issue = [&](int ch) {
        uint32_t st = sb + (ch % 3) * NSTAGE3;
        int k0 = ch * 32;
#pragma unroll
        for (int it = 0; it < 2; it++) {
            int idx = tid + it * 256;
            int r = idx >> 2, c = idx & 3;
            uint32_t so = r * LDSB + c * 16;
            long gA = (long)r * Kd + k0 + c * 8;
            cpasync16(st + so, Ah + gA);
        }
#pragma unroll
        for (int it = 0; it < 2; it++) {
            int idx = tid + it * 256;
            int r = idx >> 4, c = idx & 15;
            uint32_t so = TILE_B + r * LDSB_N + c * 16;
            long gB = (long)(k0 + r) * ldB + n0 + c * 8;
            cpasync16(st + so, Bh + gB);
        }
        CP_COMMIT();
    };

    issue(0);
    if (nch > 1) issue(1);
    if (nch > 2) issue(2);

    int lr = lane & 15, lc = lane >> 4;
    int l8 = (lane >> 3) & 1;
    int krow = ((lane >> 4) & 1) * 8 + (lane & 7);   // 0..15

    for (int ch = 0; ch < nch; ch++) {
        if (ch + 2 < nch)      { CP_WAIT2(); }
        else if (ch + 1 < nch) { CP_WAIT1(); }
        else                   { CP_WAIT0(); }
        __syncthreads();

        uint32_t stg = sb + (ch % 3) * NSTAGE3;
        uint32_t Ah_s = stg;
        uint32_t Bh_s = stg + TILE_B;

#pragma unroll
        for (int ks = 0; ks < 2; ks++) {
            uint32_t koff = ks * 32 + lc * 16;
            uint32_t ah[2][4], bh[8][2];
#pragma unroll
            for (int mf = 0; mf < 2; mf++) {
                uint32_t row = warp_m * 32 + mf * 16 + lr;
                ldsm4(ah[mf], Ah_s + row * LDSB + koff);
            }
            uint32_t brow = (ks * 16 + krow) * LDSB_N + warp_n * 128 + l8 * 16;
#pragma unroll
            for (int p = 0; p < 4; p++) {
                uint32_t t[4];
                ldsm4t(t, Bh_s + brow + p * 32);
                bh[2 * p][0] = t[0]; bh[2 * p][1] = t[2];
                bh[2 * p + 1][0] = t[1]; bh[2 * p + 1][1] = t[3];
            }
#pragma unroll
            for (int mf = 0; mf < 2; mf++)
#pragma unroll
                for (int nf = 0; nf < 8; nf++)
                    mma_f16(acc[mf][nf], ah[mf], bh[nf]);
        }
        __syncthreads();
        if (ch + 3 < nch) issue(ch + 3);
    }

    // epilogue: fp16 hi only (M = 128 exact, no bounds checks)
#pragma unroll
    for (int mf = 0; mf < 2; mf++) {
        int row0 = warp_m * 32 + mf * 16 + (lane >> 2);
#pragma unroll
        for (int nf = 0; nf < 8; nf++) {
            int col = n0 + warp_n * 64 + nf * 8 + (lane & 3) * 2;
            h2_store(Ch, (long)row0 * Ntot + col, acc[mf][nf][0], acc[mf][nf][1]);
            h2_store(Ch, (long)(row0 + 8) * Ntot + col, acc[mf][nf][2], acc[mf][nf][3]);
        }
    }
}

// ---------------- HMMA flash attention (q 2-term S, P 1-term PV) ------------
// grid (9, HH, BB); 256 threads (8 warps x 16 q-rows).
#define SKV 144
#define LDSK 144
#define LDSQ 144
#define LDSP 304
#define A_KH 0                           // 144*144 = 20736
#define A_VH 20736
#define A_QH 41472                       // 128*144 = 18432
#define A_QL (A_QH + 18432)              // ..78336
#define A_PH A_QH                        // P (hi only) reuses q region after sync
#define ATTN_SMEM (A_PH + 128 * LDSP)    // 80384

__global__ void __launch_bounds__(256) attn_mma(
    const __half* __restrict__ qh_g, const __half* __restrict__ ql_g,
    const __half* __restrict__ kvh,
    __half* __restrict__ yh)
{
    extern __shared__ char smem[];
    uint32_t sb = smem_u32(smem);
    int tid = threadIdx.x, wid = tid >> 5, lane = tid & 31;
    int n0 = blockIdx.x * 128;
    int h = blockIdx.y, b = blockIdx.z;

    // ---- loads: K/V hi rows (133) + q hi/lo tile (128 rows) ----
    for (int i = tid; i < CC * 8; i += 256) {
        int m = i >> 3, c = i & 7;
        long g = ((long)(b * CC + m) * 2) * DD + h * HD + c * 8;
        uint32_t so = m * LDSK + c * 16;
        cpasync16(sb + A_KH + so, kvh + g);
        cpasync16(sb + A_VH + so, kvh + g + DD);
    }
    for (int i = tid; i < 128 * 8; i += 256) {
        int r = i >> 3, c = i & 7;
        int qrow = n0 + r; if (qrow >= NN_TOK) qrow = 0;
        long g = (long)(b * NN_TOK + qrow) * DD + h * HD + c * 8;
        cpasync16(sb + A_QH + r * LDSQ + c * 16, qh_g + g);
        cpasync16(sb + A_QL + r * LDSQ + c * 16, ql_g + g);
    }
    CP_COMMIT();
    // zero K/V pad rows 133..143 (V pad must be 0)
    for (int i = tid; i < (SKV - CC) * 32; i += 256) {
        int m = CC + i / 32; int w4 = (i % 32) * 4;
        uint32_t so = m * LDSK + w4;
        *reinterpret_cast<uint32_t*>(smem + A_KH + so) = 0;
        *reinterpret_cast<uint32_t*>(smem + A_VH + so) = 0;
    }
    CP_WAIT0();
    __syncthreads();

    int lr = lane & 15, lg = lane >> 4;

    // ---- S = q @ k^T : warp tile 16 x 144, 2-term ----
    float sacc[18][4];
#pragma unroll
    for (int f = 0; f < 18; f++)
#pragma unroll
        for (int k = 0; k < 4; k++) sacc[f][k] = 0.f;

#pragma unroll
    for (int ks = 0; ks < 4; ks++) {
        uint32_t koff = ks * 32 + lg * 16;
        uint32_t ah[4], al[4];
        ldsm4(ah, sb + A_QH + (wid * 16 + lr) * LDSQ + koff);
        ldsm4(al, sb + A_QL + (wid * 16 + lr) * LDSQ + koff);
#pragma unroll
        for (int p = 0; p < 9; p++) {
            uint32_t th[4];
            ldsm4(th, sb + A_KH + (p * 16 + lr) * LDSK + koff);
            uint32_t bh0[2] = { th[0], th[2] }, bh1[2] = { th[1], th[3] };
            mma_f16(sacc[2 * p],     ah, bh0);
            mma_f16(sacc[2 * p],     al, bh0);
            mma_f16(sacc[2 * p + 1], ah, bh1);
            mma_f16(sacc[2 * p + 1], al, bh1);
        }
    }

    // ---- softmax (no-max exp; scale folded into Wq) ----
    float s0 = 0.f, s1 = 0.f;
#pragma unroll
    for (int f = 0; f < 18; f++) {
        int col = f * 8 + (lane & 3) * 2;
        float e0 = (col     < CC) ? __expf(sacc[f][0]) : 0.f;
        float e1 = (col + 1 < CC) ? __expf(sacc[f][1]) : 0.f;
        float e2 = (col     < CC) ? __expf(sacc[f][2]) : 0.f;
        float e3 = (col + 1 < CC) ? __expf(sacc[f][3]) : 0.f;
        sacc[f][0] = e0; sacc[f][1] = e1; sacc[f][2] = e2; sacc[f][3] = e3;
        s0 += e0 + e1; s1 += e2 + e3;
    }
    s0 += __shfl_xor_sync(0xffffffffu, s0, 1);
    s0 += __shfl_xor_sync(0xffffffffu, s0, 2);
    s1 += __shfl_xor_sync(0xffffffffu, s1, 1);
    s1 += __shfl_xor_sync(0xffffffffu, s1, 2);
    float i0 = 1.f / s0, i1 = 1.f / s1;

    __syncthreads();   // all warps done reading q before P overwrites it

    // ---- write normalized P (fp16 hi only) to smem ----
    int prow0 = wid * 16 + (lane >> 2), prow1 = prow0 + 8;
#pragma unroll
    for (int f = 0; f < 18; f++) {
        uint32_t colb = (f * 8 + (lane & 3) * 2) * 2;
        h2_sts(sb + A_PH + prow0 * LDSP + colb, sacc[f][0] * i0, sacc[f][1] * i0);
        h2_sts(sb + A_PH + prow1 * LDSP + colb, sacc[f][2] * i1, sacc[f][3] * i1);
    }
    __syncthreads();

    // ---- y = P @ V : warp tile 16 x 64, k = 144, 1-term ----
    float yacc[8][4];
#pragma unroll
    for (int f = 0; f < 8; f++)
#pragma unroll
        for (int k = 0; k < 4; k++) yacc[f][k] = 0.f;

    int l8 = (lane >> 3) & 1;
    int krow = ((lane >> 4) & 1) * 8 + (lane & 7);
#pragma unroll
    for (int ks = 0; ks < 9; ks++) {
        uint32_t ph[4];
        ldsm4(ph, sb + A_PH + (wid * 16 + lr) * LDSP + ks * 32 + lg * 16);
        uint32_t vrow = (ks * 16 + krow) * LDSK + l8 * 16;
#pragma unroll
        for (int p = 0; p < 4; p++) {
            uint32_t th[4];
            ldsm4t(th, sb + A_VH + vrow + p * 32);
            uint32_t bh0[2] = { th[0], th[2] }, bh1[2] = { th[1], th[3] };
            mma_f16(yacc[2 * p],     ph, bh0);
            mma_f16(yacc[2 * p + 1], ph, bh1);
        }
    }

    // ---- store y (fp16 hi only), masked to valid rows ----
    int row0 = n0 + wid * 16 + (lane >> 2);
    int row1 = row0 + 8;
#pragma unroll
    for (int f = 0; f < 8; f++) {
        int col = f * 8 + (lane & 3) * 2;
        if (row0 < NN_TOK)
            h2_store(yh, (long)(b * NN_TOK + row0) * DD + h * HD + col,
                     yacc[f][0], yacc[f][1]);
        if (row1 < NN_TOK)
            h2_store(yh, (long)(b * NN_TOK + row1) * DD + h * HD + col,
                     yacc[f][2], yacc[f][3]);
    }
}

// ---------------- split fp32 -> fp16 hi/lo (8 elems / thread) ----------------
__global__ __launch_bounds__(256) void split_kernel(
    const float4* __restrict__ in, uint4* __restrict__ hi, uint4* __restrict__ lo, long n8)
{
    long i = (long)blockIdx.x * 256 + threadIdx.x;
    if (i >= n8) return;
    float4 a = in[2 * i], b = in[2 * i + 1];
    float v[8] = { a.x, a.y, a.z, a.w, b.x, b.y, b.z, b.w };
    uint32_t hw[8], lw[8];
#pragma unroll
    for (int j = 0; j < 8; j++) {
        __half h = __float2half(v[j]);
        __half l = __float2half(v[j] - __half2float(h));
        hw[j] = *reinterpret_cast<unsigned short*>(&h);
        lw[j] = *reinterpret_cast<unsigned short*>(&l);
    }
    uint4 H, L;
    H.x = hw[0] | (hw[1] << 16); H.y = hw[2] | (hw[3] << 16);
    H.z = hw[4] | (hw[5] << 16); H.w = hw[6] | (hw[7] << 16);
    L.x = lw[0] | (lw[1] << 16); L.y = lw[2] | (lw[3] << 16);
    L.z = lw[4] | (lw[5] << 16); L.w = lw[6] | (lw[7] << 16);
    hi[i] = H; lo[i] = L;
}

// ---------------- fp32 -> fp16 hi-only convert (contiguous) -----------------
__global__ __launch_bounds__(256) void hconv_kernel(
    const float* __restrict__ in, __half* __restrict__ oh, long n)
{
    long i = (long)blockIdx.x * 256 + threadIdx.x;
    if (i * 2 + 1 >= n) return;
    float2 v = reinterpret_cast<const float2*>(in)[i];
    h2_store(oh, i * 2, v.x, v.y);
}

// ------------ transpose weights (scale folded), fp16 hi only -----------------
__global__ __launch_bounds__(256) void tsplit_kernel(
    const float* __restrict__ W, __half* __restrict__ hiT,
    int Kd, int Nc, float scale)
{
    int idx = blockIdx.x * 256 + threadIdx.x;
    if (idx >= Kd * Nc) return;
    int k = idx / Nc, n = idx % Nc;
    hiT[(long)n * Kd + k] = __float2half(W[idx] * scale);
}

// ---------------- kernel 1: cls_n, sims, argmax ----------------
__global__ __launch_bounds__(256) void cls_kernel(
    const float* __restrict__ x, const float* __restrict__ cents,
    float* __restrict__ out_cls, float* __restrict__ out_idx, int* __restrict__ idx)
{
    int b = blockIdx.x;
    int t = threadIdx.x;
    __shared__ float red[256];
    __shared__ float snorm;
    __shared__ float best_s;
    __shared__ int best_i;

    const float* xr = x + (long)b * NN_TOK * DD;
    float loc[3];
    float ss = 0.f;
#pragma unroll
    for (int i = 0; i < 3; i++) { loc[i] = xr[t + i * 256]; ss += loc[i] * loc[i]; }
    red[t] = ss; __syncthreads();
    for (int s = 128; s > 0; s >>= 1) { if (t < s) red[t] += red[t + s]; __syncthreads(); }
    if (t == 0) snorm = fmaxf(sqrtf(red[0]), 1e-12f);
    __syncthreads();
    float inv = 1.0f / snorm;
    float c[3];
#pragma unroll
    for (int i = 0; i < 3; i++) {
        c[i] = loc[i] * inv;
        out_cls[(long)b * DD + t + i * 256] = c[i];
    }
    if (t == 0) { best_s = -1e30f; best_i = 0; }
    __syncthreads();
    for (int m = 0; m < MM; m++) {
        float p = 0.f;
#pragma unroll
        for (int i = 0; i < 3; i++) p += c[i] * cents[(long)m * DD + t + i * 256];
        red[t] = p; __syncthreads();
        for (int s = 128; s > 0; s >>= 1) { if (t < s) red[t] += red[t + s]; __syncthreads(); }
        if (t == 0) { if (red[0] > best_s) { best_s = red[0]; best_i = m; } }
        __syncthreads();
    }
    if (t == 0) { idx[b] = best_i; out_idx[b] = (float)best_i; }
}

// ---------------- softmax over rows of length 1024, emit fp16 hi ------------
__global__ __launch_bounds__(256) void softmax1024_h(
    const float* __restrict__ s, __half* __restrict__ oh)
{
    long row = blockIdx.x;
    const float* p = s + row * PP;
    int t = threadIdx.x;
    __shared__ float red[256];

    float4 v = reinterpret_cast<const float4*>(p)[t];
    float mx = fmaxf(fmaxf(v.x, v.y), fmaxf(v.z, v.w));
    red[t] = mx; __syncthreads();
    for (int st = 128; st > 0; st >>= 1) { if (t < st) red[t] = fmaxf(red[t], red[t + st]); __syncthreads(); }
    mx = red[0]; __syncthreads();

    v.x = expf(v.x - mx); v.y = expf(v.y - mx);
    v.z = expf(v.z - mx); v.w = expf(v.w - mx);
    float sm = v.x + v.y + v.z + v.w;
    red[t] = sm; __syncthreads();
    for (int st = 128; st > 0; st >>= 1) { if (t < st) red[t] += red[t + st]; __syncthreads(); }
    float inv = 1.0f / red[0];
    v.x *= inv; v.y *= inv; v.z *= inv; v.w *= inv;

    long off = row * PP + (long)t * 4;
    h2_store(oh, off,     v.x, v.y);
    h2_store(oh, off + 2, v.z, v.w);
}

// ---------------- copy x[:, :R, :] into ctx hi rows 0..R-1 ------------------
__global__ __launch_bounds__(256) void copy_xreg_h(
    const float* __restrict__ x, __half* __restrict__ ch)
{
    long i = (long)blockIdx.x * blockDim.x + threadIdx.x;   // float4 index
    long total = (long)BB * RR * DD / 4;
    if (i >= total) return;
    long per_b = (long)RR * DD / 4;
    long b = i / per_b;
    long r = i - b * per_b;
    float4 v = reinterpret_cast<const float4*>(x)[b * ((long)NN_TOK * DD / 4) + r];
    long off = b * (long)CC * DD + r * 4;
    h2_store(ch, off,     v.x, v.y);
    h2_store(ch, off + 2, v.z, v.w);
}

// ---------------- launch ----------------
extern "C" void kernel_launch(void* const* d_in, const int* in_sizes, int n_in,
                              void* d_out, int out_size)
{
    const float* x      = (const float*)d_in[0];
    const float* Qb     = (const float*)d_in[1];
    const float* Wq     = (const float*)d_in[2];
    const float* Wctx   = (const float*)d_in[3];
    const float* bctx   = (const float*)d_in[4];
    const float* Wout   = (const float*)d_in[5];
    const float* bout   = (const float*)d_in[6];
    const float* cents  = (const float*)d_in[7];
    float* out = (float*)d_out;

    void *p_idx, *p_scores;
    void *p_xh, *p_xl, *p_yh, *p_qh, *p_ql, *p_kvh;
    void *p_ch, *p_sh;
    void *p_qbh, *p_wqh, *p_woh, *p_wch;
    cudaGetSymbolAddress(&p_idx, g_idx);
    cudaGetSymbolAddress(&p_scores, g_scores);
    cudaGetSymbolAddress(&p_xh, g_x_hi);   cudaGetSymbolAddress(&p_xl, g_x_lo);
    cudaGetSymbolAddress(&p_yh, g_y_hi);
    cudaGetSymbolAddress(&p_qh, g_q_hi);   cudaGetSymbolAddress(&p_ql, g_q_lo);
    cudaGetSymbolAddress(&p_kvh, g_kv_hi);
    cudaGetSymbolAddress(&p_ch, g_c_hi);
    cudaGetSymbolAddress(&p_sh, g_s_hi);
    cudaGetSymbolAddress(&p_qbh, g_qb_hi);
    cudaGetSymbolAddress(&p_wqh, g_wq_hi);
    cudaGetSymbolAddress(&p_woh, g_wo_hi);
    cudaGetSymbolAddress(&p_wch, g_wc_hi);

    int*   idxp   = (int*)p_idx;
    float* scores = (float*)p_scores;
    __half *xh = (__half*)p_xh,  *xl = (__half*)p_xl;
    __half *yh = (__half*)p_yh;
    __half *qh = (__half*)p_qh,  *ql = (__half*)p_ql;
    __half *kvh = (__half*)p_kvh;
    __half *ch = (__half*)p_ch;
    __half *shp = (__half*)p_sh;
    __half *qbh = (__half*)p_qbh;
    __half *wqh = (__half*)p_wqh;
    __half *woh = (__half*)p_woh;
    __half *wch = (__half*)p_wch;

    cudaFuncSetAttribute(gemm_mma<false, true,  0, false>, cudaFuncAttributeMaxDynamicSharedMemorySize, GEMM_SMEM);
    cudaFuncSetAttribute(gemm_mma<true,  false, 2, false>, cudaFuncAttributeMaxDynamicSharedMemorySize, GEMM_SMEM);
    cudaFuncSetAttribute(gemm_mma<false, false, 1, false>, cudaFuncAttributeMaxDynamicSharedMemorySize, GEMM_SMEM);
    cudaFuncSetAttribute(gemm_mma<true,  false, 0, false>, cudaFuncAttributeMaxDynamicSharedMemorySize, GEMM_SMEM);
    cudaFuncSetAttribute(gemm_mma_nn, cudaFuncAttributeMaxDynamicSharedMemorySize, NN_SMEM);
    cudaFuncSetAttribute(attn_mma, cudaFuncAttributeMaxDynamicSharedMemorySize, ATTN_SMEM);

    // 1. cls_n / idx
    cls_kernel<<<BB, 256>>>(x, cents, out + OUT_CLS, out + OUT_IDX, idxp);

    // 2. precision conversions
    {
        long n8 = (long)BB * NN_TOK * DD / 8;
        split_kernel<<<(unsigned)((n8 + 255) / 256), 256>>>(
            (const float4*)x, (uint4*)xh, (uint4*)xl, n8);
        long qn = (long)MM * KK * DD;
        hconv_kernel<<<(unsigned)((qn / 2 + 255) / 256), 256>>>(Qb, qbh, qn);
        tsplit_kernel<<<(DD * DD + 255) / 256, 256>>>(Wq, wqh, DD, DD, 0.125f);
        tsplit_kernel<<<(DD * DD + 255) / 256, 256>>>(Wout, woh, DD, DD, 1.0f);
        tsplit_kernel<<<(DD * 2 * DD + 255) / 256, 256>>>(Wctx, wch, DD, 2 * DD, 1.0f);
    }

    // 3. scores = Q_banks[idx] @ xp^T — NT 1-term, fp32 out
    gemm_mma<false, true, 0, false><<<dim3(PP / 128, 1, BB), 256, GEMM_SMEM>>>(
        qbh, nullptr, xh + (long)RR * DD, nullptr, scores, nullptr, nullptr,
        KK, PP, DD,
        (long)KK * DD, (long)NN_TOK * DD, (long)KK * PP, idxp);

    // 4. softmax -> fp16 hi attn weights
    softmax1024_h<<<BB * KK, 256>>>(scores, shp);

    // 5. ctx[:, :R] = xreg (hi only)
    {
        long total = (long)BB * RR * DD / 4;
        copy_xreg_h<<<(unsigned)((total + 255) / 256), 256>>>(x, ch);
    }

    // 6. ctx[:, R:] = attn @ xp — NN 1-term, hi out
    gemm_mma_nn<<<dim3(DD / 128, 1, BB), 256, NN_SMEM>>>(
        shp, xh + (long)RR * DD,
        ch + (long)RR * DD,
        DD, PP, DD,
        (long)KK * PP, (long)NN_TOK * DD, (long)CC * DD);

    // 7. kv = ctx @ Wctx + bctx — NT 1-term (ctx hi), fp16 hi out
    gemm_mma<true, false, 2, false><<<dim3(2 * DD / 128, MPAD_C / 128, 1), 256, GEMM_SMEM>>>(
        ch, nullptr, wch, bctx, nullptr, kvh, nullptr,
        BB * CC, 2 * DD, DD, 0, 0, 0, nullptr);

    // 8. q = x @ (Wq/8) — NT 1-term, hi/lo out (attention S uses both)
    gemm_mma<false, false, 1, false><<<dim3(DD / 128, MPAD_X / 128, 1), 256, GEMM_SMEM>>>(
        xh, nullptr, wqh, nullptr, nullptr, qh, ql,
        BB * NN_TOK, DD, DD, 0, 0, 0, nullptr);

    // 9. attention — HMMA flash (S 2-term, PV 1-term), y hi out
    attn_mma<<<dim3((NN_TOK + 127) / 128, HH, BB), 256, ATTN_SMEM>>>(
        qh, ql, kvh, yh);

    // 10. out = y @ Wout + bout — NT 1-term, fp32 out
    gemm_mma<true, false, 0, false><<<dim3(DD / 128, MPAD_X / 128, 1), 256, GEMM_SMEM>>>(
        yh, nullptr, woh, bout, out, nullptr, nullptr,
        BB * NN_TOK, DD, DD, 0, 0, 0, nullptr);
}

// round 10
// speedup vs baseline: 3.3987x; 1.0034x over previous
#include <cuda_runtime.h>
#include <cuda_fp16.h>
#include <math.h>
#include <stdint.h>

// ---------------- problem constants ----------------
#define BB 64
#define NN_TOK 1029
#define DD 768
#define HH 12
#define HD 64
#define KK 128
#define RR 5
#define MM 4
#define PP 1024              // N - R
#define CC 133               // R + K

#define MPAD_X 65920         // 515*128  (>= B*N = 65856)
#define MPAD_C 8576          // 67*128   (>= B*C = 8512)

// output layout: [out (B*N*D)] [cls_n (B*D)] [idx (B)]
#define OUT_CLS ((long)BB * NN_TOK * DD)
#define OUT_IDX (OUT_CLS + (long)BB * DD)

// ---------------- scratch (device globals; no allocs allowed) ----------------
__device__ int   g_idx[BB];
__device__ float g_rowsum[BB * KK];

// fp16 buffers (zero-init covers padding rows)
__device__ __half g_x_hi[(long)MPAD_X * DD];
__device__ __half g_y_hi[(long)MPAD_X * DD];
__device__ __half g_q_hi[(long)MPAD_X * DD];
__device__ __half g_q_lo[(long)MPAD_X * DD];
__device__ __half g_kv_hi[(long)MPAD_C * 2 * DD];
__device__ __half g_c_hi[(long)MPAD_C * DD];
__device__ __half g_s_hi[(long)BB * KK * PP];   // exp(scores), unnormalized
__device__ __half g_qb_hi[(long)MM * KK * DD];
__device__ __half g_wq_hi[DD * DD];
__device__ __half g_wo_hi[DD * DD];
__device__ __half g_wc_hi[2 * DD * DD];

// ---------------- PTX helpers ----------------
__device__ __forceinline__ uint32_t smem_u32(const void* p) {
    uint32_t a;
    asm("{ .reg .u64 t; cvta.to.shared.u64 t, %1; cvt.u32.u64 %0, t; }" : "=r"(a) : "l"(p));
    return a;
}
__device__ __forceinline__ void cpasync16(uint32_t dst, const void* src) {
    asm volatile("cp.async.cg.shared.global [%0], [%1], 16;" :: "r"(dst), "l"(src));
}
#define CP_COMMIT() asm volatile("cp.async.commit_group;" ::: "memory")
#define CP_WAIT2()  asm volatile("cp.async.wait_group 2;" ::: "memory")
#define CP_WAIT1()  asm volatile("cp.async.wait_group 1;" ::: "memory")
#define CP_WAIT0()  asm volatile("cp.async.wait_group 0;" ::: "memory")

__device__ __forceinline__ void ldsm4(uint32_t* r, uint32_t addr) {
    asm volatile("ldmatrix.sync.aligned.m8n8.x4.shared.b16 {%0,%1,%2,%3}, [%4];"
        : "=r"(r[0]), "=r"(r[1]), "=r"(r[2]), "=r"(r[3]) : "r"(addr));
}
__device__ __forceinline__ void ldsm4t(uint32_t* r, uint32_t addr) {
    asm volatile("ldmatrix.sync.aligned.m8n8.x4.trans.shared.b16 {%0,%1,%2,%3}, [%4];"
        : "=r"(r[0]), "=r"(r[1]), "=r"(r[2]), "=r"(r[3]) : "r"(addr));
}
__device__ __forceinline__ void mma_f16(float* c, const uint32_t* a, const uint32_t* b) {
    asm volatile(
        "mma.sync.aligned.m16n8k16.row.col.f32.f16.f16.f32 "
        "{%0,%1,%2,%3}, {%4,%5,%6,%7}, {%8,%9}, {%0,%1,%2,%3};"
        : "+f"(c[0]), "+f"(c[1]), "+f"(c[2]), "+f"(c[3])
        : "r"(a[0]), "r"(a[1]), "r"(a[2]), "r"(a[3]), "r"(b[0]), "r"(b[1]));
}

// split a float pair into fp16 hi/lo and store packed (global)
__device__ __forceinline__ void split2_store(
    __half* __restrict__ H, __half* __restrict__ L, long off, float v0, float v1)
{
    __half h0 = __float2half(v0);
    __half h1 = __float2half(v1);
    __half l0 = __float2half(v0 - __half2float(h0));
    __half l1 = __float2half(v1 - __half2float(h1));
    uint32_t hw = (uint32_t)*reinterpret_cast<unsigned short*>(&h0)
                | ((uint32_t)*reinterpret_cast<unsigned short*>(&h1) << 16);
    uint32_t lw = (uint32_t)*reinterpret_cast<unsigned short*>(&l0)
                | ((uint32_t)*reinterpret_cast<unsigned short*>(&l1) << 16);
    *reinterpret_cast<uint32_t*>(H + off) = hw;
    *reinterpret_cast<uint32_t*>(L + off) = lw;
}

// store a float pair as fp16 (hi only)
__device__ __forceinline__ void h2_store(__half* __restrict__ H, long off, float v0, float v1)
{
    __half h0 = __float2half(v0);
    __half h1 = __float2half(v1);
    uint32_t hw = (uint32_t)*reinterpret_cast<unsigned short*>(&h0)
                | ((uint32_t)*reinterpret_cast<unsigned short*>(&h1) << 16);
    *reinterpret_cast<uint32_t*>(H + off) = hw;
}

// store a float pair as fp16 to smem
__device__ __forceinline__ void h2_sts(uint32_t addr, float v0, float v1)
{
    __half h0 = __float2half(v0);
    __half h1 = __float2half(v1);
    uint32_t hw = (uint32_t)*reinterpret_cast<unsigned short*>(&h0)
                | ((uint32_t)*reinterpret_cast<unsigned short*>(&h1) << 16);
    asm volatile("st.shared.b32 [%0], %1;" :: "r"(addr), "r"(hw) : "memory");
}

// ---------------- NT HMMA GEMM, fp16 1-term, 3-stage, 2 CTA/SM --------------
// C[m,n] (+= bias[n]) = sum_k A[m,k] * B[n,k]
// OUTMODE: 0 = fp32+bias, 1 = fp16 hi/lo split, 2 = fp16 hi (+bias), 3 = exp fp16 + rowsum
#define LDSB 80                    // smem bytes per tile row (32 fp16 + pad)
#define TILE_B (128 * LDSB)        // 10240
#define STAGE2 (2 * TILE_B)        // 20480 (Ah, Bh)
#define GEMM_SMEM (3 * STAGE2)     // 61440  -> 2 CTAs/SM (smem)

template<bool BIAS, bool GATHER, int OUTMODE>
__global__ void __launch_bounds__(256, 2) gemm_mma(
    const __half* __restrict__ Ahb,
    const __half* __restrict__ Bhb,
    const float* __restrict__ bias, float* __restrict__ Cb,
    __half* __restrict__ Chb, __half* __restrict__ Clb,
    float* __restrict__ rowsum,
    int M, int Ntot, int Kd,
    long sA, long sB, long sC,
    const int* __restrict__ idxmap)
{
    extern __shared__ char smem[];
    uint32_t sb = smem_u32(smem);

    int tid = threadIdx.x, wid = tid >> 5, lane = tid & 31;
    int warp_m = wid & 3, warp_n = wid >> 2;
    int bz = blockIdx.z;
    long aoff = GATHER ? (long)idxmap[bz] * sA : (long)bz * sA;
    const __half* Ah = Ahb + aoff;
    const __half* Bh = Bhb + (long)bz * sB;

    int m0 = blockIdx.y * 128;
    int n0 = blockIdx.x * 128;

    float acc[2][8][4];
#pragma unroll
    for (int i = 0; i < 2; i++)
#pragma unroll
        for (int j = 0; j < 8; j++)
#pragma unroll
            for (int k = 0; k < 4; k++) acc[i][j][k] = 0.f;

    const int nch = Kd / 32;

    auto issue = [&](int ch) {
        uint32_t st = sb + (ch % 3) * STAGE2;
        int k0 = ch * 32;
#pragma unroll
        for (int it = 0; it < 2; it++) {
            int idx = tid + it * 256;
            int r = idx >> 2, c = idx & 3;
            uint32_t so = r * LDSB + c * 16;
            long gA = (long)(m0 + r) * Kd + k0 + c * 8;
            long gB = (long)(n0 + r) * Kd + k0 + c * 8;
            cpasync16(st + so,          Ah + gA);
            cpasync16(st + TILE_B + so, Bh + gB);
        }
        CP_COMMIT();
    };

    issue(0);
    if (nch > 1) issue(1);
    if (nch > 2) issue(2);

    int lr = lane & 15, lc = lane >> 4;

    for (int ch = 0; ch < nch; ch++) {
        if (ch + 2 < nch)      { CP_WAIT2(); }
        else if (ch + 1 < nch) { CP_WAIT1(); }
        else                   { CP_WAIT0(); }
        __syncthreads();

        uint32_t stg = sb + (ch % 3) * STAGE2;
        uint32_t Ah_s = stg;
        uint32_t Bh_s = stg + TILE_B;

#pragma unroll
        for (int ks = 0; ks < 2; ks++) {
            uint32_t koff = ks * 32 + lc * 16;
            uint32_t ah[2][4], bh[8][2];
#pragma unroll
            for (int mf = 0; mf < 2; mf++) {
                uint32_t row = warp_m * 32 + mf * 16 + lr;
                ldsm4(ah[mf], Ah_s + row * LDSB + koff);
            }
#pragma unroll
            for (int p = 0; p < 4; p++) {
                uint32_t row = warp_n * 64 + p * 16 + lr;
                uint32_t t[4];
                ldsm4(t, Bh_s + row * LDSB + koff);
                bh[2 * p][0] = t[0]; bh[2 * p][1] = t[2];
                bh[2 * p + 1][0] = t[1]; bh[2 * p + 1][1] = t[3];
            }
#pragma unroll
            for (int mf = 0; mf < 2; mf++)
#pragma unroll
                for (int nf = 0; nf < 8; nf++)
                    mma_f16(acc[mf][nf], ah[mf], bh[nf]);
        }
        __syncthreads();
        if (ch + 3 < nch) issue(ch + 3);
    }

#pragma unroll
    for (int mf = 0; mf < 2; mf++) {
        int row0 = m0 + warp_m * 32 + mf * 16 + (lane >> 2);
        float s0 = 0.f, s1 = 0.f;
#pragma unroll
        for (int nf = 0; nf < 8; nf++) {
            int col = n0 + warp_n * 64 + nf * 8 + (lane & 3) * 2;
            if (OUTMODE == 3) {
                __half* Ch = Chb + (long)blockIdx.z * sC;
                float e0 = __expf(acc[mf][nf][0]);
                float e1 = __expf(acc[mf][nf][1]);
                float e2 = __expf(acc[mf][nf][2]);
                float e3 = __expf(acc[mf][nf][3]);
                h2_store(Ch, (long)row0 * Ntot + col, e0, e1);
                h2_store(Ch, (long)(row0 + 8) * Ntot + col, e2, e3);
                s0 += e0 + e1; s1 += e2 + e3;
            } else {
                float b0 = 0.f, b1 = 0.f;
                if (BIAS) { b0 = bias[col]; b1 = bias[col + 1]; }
                if (OUTMODE == 1) {
                    __half* Ch = Chb + (long)blockIdx.z * sC;
                    __half* Cl = Clb + (long)blockIdx.z * sC;
                    if (row0 < M)
                        split2_store(Ch, Cl, (long)row0 * Ntot + col,
                                     acc[mf][nf][0] + b0, acc[mf][nf][1] + b1);
                    if (row0 + 8 < M)
                        split2_store(Ch, Cl, (long)(row0 + 8) * Ntot + col,
                                     acc[mf][nf][2] + b0, acc[mf][nf][3] + b1);
                } else if (OUTMODE == 2) {
                    __half* Ch = Chb + (long)blockIdx.z * sC;
                    if (row0 < M)
                        h2_store(Ch, (long)row0 * Ntot + col,
                                 acc[mf][nf][0] + b0, acc[mf][nf][1] + b1);
                    if (row0 + 8 < M)
                        h2_store(Ch, (long)(row0 + 8) * Ntot + col,
                                 acc[mf][nf][2] + b0, acc[mf][nf][3] + b1);
                } else {
                    float* C = Cb + (long)blockIdx.z * sC;
                    if (row0 < M) {
                        float2 v = make_float2(acc[mf][nf][0] + b0, acc[mf][nf][1] + b1);
                        *reinterpret_cast<float2*>(&C[(long)row0 * Ntot + col]) = v;
                    }
                    if (row0 + 8 < M) {
                        float2 v = make_float2(acc[mf][nf][2] + b0, acc[mf][nf][3] + b1);
                        *reinterpret_cast<float2*>(&C[(long)(row0 + 8) * Ntot + col]) = v;
                    }
                }
            }
        }
        if (OUTMODE == 3) {
            // reduce partial sums across the 4 lanes sharing each accum row
            s0 += __shfl_xor_sync(0xffffffffu, s0, 1);
            s0 += __shfl_xor_sync(0xffffffffu, s0, 2);
            s1 += __shfl_xor_sync(0xffffffffu, s1, 1);
            s1 += __shfl_xor_sync(0xffffffffu, s1, 2);
            if ((lane & 3) == 0) {
                float* rs = rowsum + (long)blockIdx.z * 128;
                atomicAdd(&rs[row0], s0);
                atomicAdd(&rs[row0 + 8], s1);
            }
        }
    }
}

// ---------------- NN HMMA GEMM (B row-major [k][n]), row-scaled fp16 out -----
// C[m,n] = (sum_k A[m,k] * B[k,n]) / rowsum[m];  M = 128 fixed.
#define LDSB_N 272                       // 128 fp16 (256B) + 16B pad
#define NTILE_B (32 * LDSB_N)            // 8704
#define NSTAGE3 (TILE_B + NTILE_B)       // 18944 (Ah, Bh)
#define NN_SMEM (3 * NSTAGE3)            // 56832

__global__ void __launch_bounds__(256, 2) gemm_mma_nn(
    const __half* __restrict__ Ahb,
    const __half* __restrict__ Bhb,
    __half* __restrict__ Chb,
    const float* __restrict__ rowsum,
    int Ntot, int Kd, int ldB,
    long sA, long sB, long sC)
{
    extern __shared__ char smem[];
    uint32_t sb = smem_u32(smem);

    int tid = threadIdx.x, wid = tid >> 5, lane = tid & 31;
    int warp_m = wid & 3, warp_n = wid >> 2;
    int bz = blockIdx.z;
    const __half* Ah = Ahb + (long)bz * sA;
    const __half* Bh = Bhb + (long)bz * sB;
    __half* Ch = Chb + (long)bz * sC;
    const float* rs = rowsum + (long)bz * 128;

    int n0 = blockIdx.x * 128;

    float acc[2][8][4];
#pragma unroll
    for (int i = 0; i < 2; i++)
#pragma unroll
        for (int j = 0; j < 8; j++)
#pragma unroll
            for (int k = 0; k < 4; k++) acc[i][j][k] = 0.f;

    const int nch = Kd / 32;

    auto issue = [&](int ch) {
        uint32_t st = sb + (ch % 3) * NSTAGE3;
        int k0 = ch * 32;
#pragma unroll
        for (int it = 0; it < 2; it++) {
            int idx = tid + it * 256;
            int r = idx >> 2, c = idx & 3;
            uint32_t so = r * LDSB + c * 16;
            long gA = (long)r * Kd + k0 + c * 8;
            cpasync16(st + so, Ah + gA);
        }
#pragma unroll
        for (int it = 0; it < 2; it++) {
            int idx = tid + it * 256;
            int r = idx >> 4, c = idx & 15;
            uint32_t so = TILE_B + r * LDSB_N + c * 16;
            long gB = (long)(k0 + r) * ldB + n0 + c * 8;
            cpasync16(st + so, Bh + gB);
        }
        CP_COMMIT();
    };

    issue(0);
    if (nch > 1) issue(1);
    if (nch > 2) issue(2);

    int lr = lane & 15, lc = lane >> 4;
    int l8 = (lane >> 3) & 1;
    int krow = ((lane >> 4) & 1) * 8 + (lane & 7);   // 0..15

    for (int ch = 0; ch < nch; ch++) {
        if (ch + 2 < nch)      { CP_WAIT2(); }
        else if (ch + 1 < nch) { CP_WAIT1(); }
        else                   { CP_WAIT0(); }
        __syncthreads();

        uint32_t stg = sb + (ch % 3) * NSTAGE3;
        uint32_t Ah_s = stg;
        uint32_t Bh_s = stg + TILE_B;

#pragma unroll
        for (int ks = 0; ks < 2; ks++) {
            uint32_t koff = ks * 32 + lc * 16;
            uint32_t ah[2][4], bh[8][2];
#pragma unroll
            for (int mf = 0; mf < 2; mf++) {
                uint32_t row = warp_m * 32 + mf * 16 + lr;
                ldsm4(ah[mf], Ah_s + row * LDSB + koff);
            }
            uint32_t brow = (ks * 16 + krow) * LDSB_N + warp_n * 128 + l8 * 16;
#pragma unroll
            for (int p = 0; p < 4; p++) {
                uint32_t t[4];
                ldsm4t(t, Bh_s + brow + p * 32);
                bh[2 * p][0] = t[0]; bh[2 * p][1] = t[2];
                bh[2 * p + 1][0] = t[1]; bh[2 * p + 1][1] = t[3];
            }
#pragma unroll
            for (int mf = 0; mf < 2; mf++)
#pragma unroll
                for (int nf = 0; nf < 8; nf++)
                    mma_f16(acc[mf][nf], ah[mf], bh[nf]);
        }
        __syncthreads();
        if (ch + 3 < nch) issue(ch + 3);
    }

    // epilogue: normalize by rowsum, fp16 hi (M = 128 exact)
#pragma unroll
    for (int mf = 0; mf < 2; mf++) {
        int row0 = warp_m * 32 + mf * 16 + (lane >> 2);
        float inv0 = 1.f / rs[row0];
        float inv1 = 1.f / rs[row0 + 8];
#pragma unroll
        for (int nf = 0; nf < 8; nf++) {
            int col = n0 + warp_n * 64 + nf * 8 + (lane & 3) * 2;
            h2_store(Ch, (long)row0 * Ntot + col,
                     acc[mf][nf][0] * inv0, acc[mf][nf][1] * inv0);
            h2_store(Ch, (long)(row0 + 8) * Ntot + col,
                     acc[mf][nf][2] * inv1, acc[mf][nf][3] * inv1);
        }
    }
}

// ---------------- HMMA flash attention (q 2-term S, P 1-term PV) ------------
// grid (9, HH, BB); 256 threads (8 warps x 16 q-rows).
#define SKV 144
#define LDSK 144
#define LDSQ 144
#define LDSP 304
#define A_KH 0                           // 144*144 = 20736
#define A_VH 20736
#define A_QH 41472                       // 128*144 = 18432
#define A_QL (A_QH + 18432)              // ..78336
#define A_PH A_QH                        // P (hi only) reuses q region after sync
#define ATTN_SMEM (A_PH + 128 * LDSP)    // 80384

__global__ void __launch_bounds__(256) attn_mma(
    const __half* __restrict__ qh_g, const __half* __restrict__ ql_g,
    const __half* __restrict__ kvh,
    __half* __restrict__ yh)
{
    extern __shared__ char smem[];
    uint32_t sb = smem_u32(smem);
    int tid = threadIdx.x, wid = tid >> 5, lane = tid & 31;
    int n0 = blockIdx.x * 128;
    int h = blockIdx.y, b = blockIdx.z;

    // ---- loads: K/V hi rows (133) + q hi/lo tile (128 rows) ----
    for (int i = tid; i < CC * 8; i += 256) {
        int m = i >> 3, c = i & 7;
        long g = ((long)(b * CC + m) * 2) * DD + h * HD + c * 8;
        uint32_t so = m * LDSK + c * 16;
        cpasync16(sb + A_KH + so, kvh + g);
        cpasync16(sb + A_VH + so, kvh + g + DD);
    }
    for (int i = tid; i < 128 * 8; i += 256) {
        int r = i >> 3, c = i & 7;
        int qrow = n0 + r; if (qrow >= NN_TOK) qrow = 0;
        long g = (long)(b * NN_TOK + qrow) * DD + h * HD + c * 8;
        cpasync16(sb + A_QH + r * LDSQ + c * 16, qh_g + g);
        cpasync16(sb + A_QL + r * LDSQ + c * 16, ql_g + g);
    }
    CP_COMMIT();
    // zero K/V pad rows 133..143 (V pad must be 0)
    for (int i = tid; i < (SKV - CC) * 32; i += 256) {
        int m = CC + i / 32; int w4 = (i % 32) * 4;
        uint32_t so = m * LDSK + w4;
        *reinterpret_cast<uint32_t*>(smem + A_KH + so) = 0;
        *reinterpret_cast<uint32_t*>(smem + A_VH + so) = 0;
    }
    CP_WAIT0();
    __syncthreads();

    int lr = lane & 15, lg = lane >> 4;

    // ---- S = q @ k^T : warp tile 16 x 144, 2-term ----
    float sacc[18][4];
#pragma unroll
    for (int f = 0; f < 18; f++)
#pragma unroll
        for (int k = 0; k < 4; k++) sacc[f][k] = 0.f;

#pragma unroll
    for (int ks = 0; ks < 4; ks++) {
        uint32_t koff = ks * 32 + lg * 16;
        uint32_t ah[4], al[4];
        ldsm4(ah, sb + A_QH + (wid * 16 + lr) * LDSQ + koff);
        ldsm4(al, sb + A_QL + (wid * 16 + lr) * LDSQ + koff);
#pragma unroll
        for (int p = 0; p < 9; p++) {
            uint32_t th[4];
            ldsm4(th, sb + A_KH + (p * 16 + lr) * LDSK + koff);
            uint32_t bh0[2] = { th[0], th[2] }, bh1[2] = { th[1], th[3] };
            mma_f16(sacc[2 * p],     ah, bh0);
            mma_f16(sacc[2 * p],     al, bh0);
            mma_f16(sacc[2 * p + 1], ah, bh1);
            mma_f16(sacc[2 * p + 1], al, bh1);
        }
    }

    // ---- softmax (no-max exp; scale folded into Wq) ----
    float s0 = 0.f, s1 = 0.f;
#pragma unroll
    for (int f = 0; f < 18; f++) {
        int col = f * 8 + (lane & 3) * 2;
        float e0 = (col     < CC) ? __expf(sacc[f][0]) : 0.f;
        float e1 = (col + 1 < CC) ? __expf(sacc[f][1]) : 0.f;
        float e2 = (col     < CC) ? __expf(sacc[f][2]) : 0.f;
        float e3 = (col + 1 < CC) ? __expf(sacc[f][3]) : 0.f;
        sacc[f][0] = e0; sacc[f][1] = e1; sacc[f][2] = e2; sacc[f][3] = e3;
        s0 += e0 + e1; s1 += e2 + e3;
    }
    s0 += __shfl_xor_sync(0xffffffffu, s0, 1);
    s0 += __shfl_xor_sync(0xffffffffu, s0, 2);
    s1 += __shfl_xor_sync(0xffffffffu, s1, 1);
    s1 += __shfl_xor_sync(0xffffffffu, s1, 2);
    float i0 = 1.f / s0, i1 = 1.f / s1;

    __syncthreads();   // all warps done reading q before P overwrites it

    // ---- write normalized P (fp16 hi only) to smem ----
    int prow0 = wid * 16 + (lane >> 2), prow1 = prow0 + 8;
#pragma unroll
    for (int f = 0; f < 18; f++) {
        uint32_t colb = (f * 8 + (lane & 3) * 2) * 2;
        h2_sts(sb + A_PH + prow0 * LDSP + colb, sacc[f][0] * i0, sacc[f][1] * i0);
        h2_sts(sb + A_PH + prow1 * LDSP + colb, sacc[f][2] * i1, sacc[f][3] * i1);
    }
    __syncthreads();

    // ---- y = P @ V : warp tile 16 x 64, k = 144, 1-term ----
    float yacc[8][4];
#pragma unroll
    for (int f = 0; f < 8; f++)
#pragma unroll
        for (int k = 0; k < 4; k++) yacc[f][k] = 0.f;

    int l8 = (lane >> 3) & 1;
    int krow = ((lane >> 4) & 1) * 8 + (lane & 7);
#pragma unroll
    for (int ks = 0; ks < 9; ks++) {
        uint32_t ph[4];
        ldsm4(ph, sb + A_PH + (wid * 16 + lr) * LDSP + ks * 32 + lg * 16);
        uint32_t vrow = (ks * 16 + krow) * LDSK + l8 * 16;
#pragma unroll
        for (int p = 0; p < 4; p++) {
            uint32_t th[4];
            ldsm4t(th, sb + A_VH + vrow + p * 32);
            uint32_t bh0[2] = { th[0], th[2] }, bh1[2] = { th[1], th[3] };
            mma_f16(yacc[2 * p],     ph, bh0);
            mma_f16(yacc[2 * p + 1], ph, bh1);
        }
    }

    // ---- store y (fp16 hi only), masked to valid rows ----
    int row0 = n0 + wid * 16 + (lane >> 2);
    int row1 = row0 + 8;
#pragma unroll
    for (int f = 0; f < 8; f++) {
        int col = f * 8 + (lane & 3) * 2;
        if (row0 < NN_TOK)
            h2_store(yh, (long)(b * NN_TOK + row0) * DD + h * HD + col,
                     yacc[f][0], yacc[f][1]);
        if (row1 < NN_TOK)
            h2_store(yh, (long)(b * NN_TOK + row1) * DD + h * HD + col,
                     yacc[f][2], yacc[f][3]);
    }
}

// ---------------- fp32 -> fp16 hi-only convert (contiguous) -----------------
__global__ __launch_bounds__(256) void hconv_kernel(
    const float* __restrict__ in, __half* __restrict__ oh, long n)
{
    long i = (long)blockIdx.x * 256 + threadIdx.x;
    if (i * 2 + 1 >= n) return;
    float2 v = reinterpret_cast<const float2*>(in)[i];
    h2_store(oh, i * 2, v.x, v.y);
}

// ------------ transpose weights (scale folded), fp16 hi only -----------------
__global__ __launch_bounds__(256) void tsplit_kernel(
    const float* __restrict__ W, __half* __restrict__ hiT,
    int Kd, int Nc, float scale)
{
    int idx = blockIdx.x * 256 + threadIdx.x;
    if (idx >= Kd * Nc) return;
    int k = idx / Nc, n = idx % Nc;
    hiT[(long)n * Kd + k] = __float2half(W[idx] * scale);
}

// ---------------- kernel 1: cls_n, sims, argmax ----------------
__global__ __launch_bounds__(256) void cls_kernel(
    const float* __restrict__ x, const float* __restrict__ cents,
    float* __restrict__ out_cls, float* __restrict__ out_idx, int* __restrict__ idx)
{
    int b = blockIdx.x;
    int t = threadIdx.x;
    __shared__ float red[256];
    __shared__ float snorm;
    __shared__ float best_s;
    __shared__ int best_i;

    const float* xr = x + (long)b * NN_TOK * DD;
    float loc[3];
    float ss = 0.f;
#pragma unroll
    for (int i = 0; i < 3; i++) { loc[i] = xr[t + i * 256]; ss += loc[i] * loc[i]; }
    red[t] = ss; __syncthreads();
    for (int s = 128; s > 0; s >>= 1) { if (t < s) red[t] += red[t + s]; __syncthreads(); }
    if (t == 0) snorm = fmaxf(sqrtf(red[0]), 1e-12f);
    __syncthreads();
    float inv = 1.0f / snorm;
    float c[3];
#pragma unroll
    for (int i = 0; i < 3; i++) {
        c[i] = loc[i] * inv;
        out_cls[(long)b * DD + t + i * 256] = c[i];
    }
    if (t == 0) { best_s = -1e30f; best_i = 0; }
    __syncthreads();
    for (int m = 0; m < MM; m++) {
        float p = 0.f;
#pragma unroll
        for (int i = 0; i < 3; i++) p += c[i] * cents[(long)m * DD + t + i * 256];
        red[t] = p; __syncthreads();
        for (int s = 128; s > 0; s >>= 1) { if (t < s) red[t] += red[t + s]; __syncthreads(); }
        if (t == 0) { if (red[0] > best_s) { best_s = red[0]; best_i = m; } }
        __syncthreads();
    }
    if (t == 0) { idx[b] = best_i; out_idx[b] = (float)best_i; }
}

// ---------------- copy x[:, :R, :] into ctx hi rows 0..R-1 ------------------
__global__ __launch_bounds__(256) void copy_xreg_h(
    const float* __restrict__ x, __half* __restrict__ ch)
{
    long i = (long)blockIdx.x * blockDim.x + threadIdx.x;   // float4 index
    long total = (long)BB * RR * DD / 4;
    if (i >= total) return;
    long per_b = (long)RR * DD / 4;
    long b = i / per_b;
    long r = i - b * per_b;
    float4 v = reinterpret_cast<const float4*>(x)[b * ((long)NN_TOK * DD / 4) + r];
    long off = b * (long)CC * DD + r * 4;
    h2_store(ch, off,     v.x, v.y);
    h2_store(ch, off + 2, v.z, v.w);
}

// ---------------- launch ----------------
extern "C" void kernel_launch(void* const* d_in, const int* in_sizes, int n_in,
                              void* d_out, int out_size)
{
    const float* x      = (const float*)d_in[0];
    const float* Qb     = (const float*)d_in[1];
    const float* Wq     = (const float*)d_in[2];
    const float* Wctx   = (const float*)d_in[3];
    const float* bctx   = (const float*)d_in[4];
    const float* Wout   = (const float*)d_in[5];
    const float* bout   = (const float*)d_in[6];
    const float* cents  = (const float*)d_in[7];
    float* out = (float*)d_out;

    void *p_idx, *p_rs;
    void *p_xh, *p_yh, *p_qh, *p_ql, *p_kvh;
    void *p_ch, *p_sh;
    void *p_qbh, *p_wqh, *p_woh, *p_wch;
    cudaGetSymbolAddress(&p_idx, g_idx);
    cudaGetSymbolAddress(&p_rs, g_rowsum);
    cudaGetSymbolAddress(&p_xh, g_x_hi);
    cudaGetSymbolAddress(&p_yh, g_y_hi);
    cudaGetSymbolAddress(&p_qh, g_q_hi);   cudaGetSymbolAddress(&p_ql, g_q_lo);
    cudaGetSymbolAddress(&p_kvh, g_kv_hi);
    cudaGetSymbolAddress(&p_ch, g_c_hi);
    cudaGetSymbolAddress(&p_sh, g_s_hi);
    cudaGetSymbolAddress(&p_qbh, g_qb_hi);
    cudaGetSymbolAddress(&p_wqh, g_wq_hi);
    cudaGetSymbolAddress(&p_woh, g_wo_hi);
    cudaGetSymbolAddress(&p_wch, g_wc_hi);

    int*   idxp = (int*)p_idx;
    float* rsum = (float*)p_rs;
    __half *xh = (__half*)p_xh;
    __half *yh = (__half*)p_yh;
    __half *qh = (__half*)p_qh,  *ql = (__half*)p_ql;
    __half *kvh = (__half*)p_kvh;
    __half *ch = (__half*)p_ch;
    __half *shp = (__half*)p_sh;
    __half *qbh = (__half*)p_qbh;
    __half *wqh = (__half*)p_wqh;
    __half *woh = (__half*)p_woh;
    __half *wch = (__half*)p_wch;

    cudaFuncSetAttribute(gemm_mma<false, true,  3>, cudaFuncAttributeMaxDynamicSharedMemorySize, GEMM_SMEM);
    cudaFuncSetAttribute(gemm_mma<true,  false, 2>, cudaFuncAttributeMaxDynamicSharedMemorySize, GEMM_SMEM);
    cudaFuncSetAttribute(gemm_mma<false, false, 1>, cudaFuncAttributeMaxDynamicSharedMemorySize, GEMM_SMEM);
    cudaFuncSetAttribute(gemm_mma<true,  false, 0>, cudaFuncAttributeMaxDynamicSharedMemorySize, GEMM_SMEM);
    cudaFuncSetAttribute(gemm_mma_nn, cudaFuncAttributeMaxDynamicSharedMemorySize, NN_SMEM);
    cudaFuncSetAttribute(attn_mma, cudaFuncAttributeMaxDynamicSharedMemorySize, ATTN_SMEM);

    // 0. zero rowsum accumulators (graph-capturable)
    cudaMemsetAsync(rsum, 0, BB * KK * sizeof(float));

    // 1. cls_n / idx
    cls_kernel<<<BB, 256>>>(x, cents, out + OUT_CLS, out + OUT_IDX, idxp);

    // 2. precision conversions (x hi only — x_lo is dead)
    {
        long xn = (long)BB * NN_TOK * DD;
        hconv_kernel<<<(unsigned)((xn / 2 + 255) / 256), 256>>>(x, xh, xn);
        long qn = (long)MM * KK * DD;
        hconv_kernel<<<(unsigned)((qn / 2 + 255) / 256), 256>>>(Qb, qbh, qn);
        tsplit_kernel<<<(DD * DD + 255) / 256, 256>>>(Wq, wqh, DD, DD, 0.125f);
        tsplit_kernel<<<(DD * DD + 255) / 256, 256>>>(Wout, woh, DD, DD, 1.0f);
        tsplit_kernel<<<(DD * 2 * DD + 255) / 256, 256>>>(Wctx, wch, DD, 2 * DD, 1.0f);
    }

    // 3. exp(scores) = exp(Q_banks[idx] @ xp^T) — NT 1-term, fused exp + rowsum
    gemm_mma<false, true, 3><<<dim3(PP / 128, 1, BB), 256, GEMM_SMEM>>>(
        qbh, xh + (long)RR * DD, nullptr, nullptr, shp, nullptr, rsum,
        KK, PP, DD,
        (long)KK * DD, (long)NN_TOK * DD, (long)KK * PP, idxp);

    // 4. ctx[:, :R] = xreg (hi only)
    {
        long total = (long)BB * RR * DD / 4;
        copy_xreg_h<<<(unsigned)((total + 255) / 256), 256>>>(x, ch);
    }

    // 5. ctx[:, R:] = (exp_s @ xp) / rowsum — NN 1-term, fused normalize
    gemm_mma_nn<<<dim3(DD / 128, 1, BB), 256, NN_SMEM>>>(
        shp, xh + (long)RR * DD,
        ch + (long)RR * DD, rsum,
        DD, PP, DD,
        (long)KK * PP, (long)NN_TOK * DD, (long)CC * DD);

    // 6. kv = ctx @ Wctx + bctx — NT 1-term, fp16 hi out
    gemm_mma<true, false, 2><<<dim3(2 * DD / 128, MPAD_C / 128, 1), 256, GEMM_SMEM>>>(
        ch, wch, bctx, nullptr, kvh, nullptr, nullptr,
        BB * CC, 2 * DD, DD, 0, 0, 0, nullptr);

    // 7. q = x @ (Wq/8) — NT 1-term, hi/lo out (attention S uses both)
    gemm_mma<false, false, 1><<<dim3(DD / 128, MPAD_X / 128, 1), 256, GEMM_SMEM>>>(
        xh, wqh, nullptr, nullptr, qh, ql, nullptr,
        BB * NN_TOK, DD, DD, 0, 0, 0, nullptr);

    // 8. attention — HMMA flash (S 2-term, PV 1-term), y hi out
    attn_mma<<<dim3((NN_TOK + 127) / 128, HH, BB), 256, ATTN_SMEM>>>(
        qh, ql, kvh, yh);

    // 9. out = y @ Wout + bout — NT 1-term, fp32 out
    gemm_mma<true, false, 0><<<dim3(DD / 128, MPAD_X / 128, 1), 256, GEMM_SMEM>>>(
        yh, woh, bout, out, nullptr, nullptr, nullptr,
        BB * NN_TOK, DD, DD, 0, 0, 0, nullptr);
}

// round 11
// speedup vs baseline: 3.5352x; 1.0402x over previous
#include <cuda_runtime.h>
#include <cuda_fp16.h>
#include <math.h>
#include <stdint.h>

// ---------------- problem constants ----------------
#define BB 64
#define NN_TOK 1029
#define DD 768
#define HH 12
#define HD 64
#define KK 128
#define RR 5
#define MM 4
#define PP 1024              // N - R
#define CC 133               // R + K

#define MPAD_X 65920         // 515*128  (>= B*N = 65856)
#define MPAD_C 8576          // 67*128   (>= B*C = 8512)

// output layout: [out (B*N*D)] [cls_n (B*D)] [idx (B)]
#define OUT_CLS ((long)BB * NN_TOK * DD)
#define OUT_IDX (OUT_CLS + (long)BB * DD)

// ---------------- scratch (device globals; no allocs allowed) ----------------
__device__ int   g_idx[BB];
__device__ float g_rowsum[BB * KK];

// fp16 buffers (zero-init covers padding rows)
__device__ __half g_x_hi[(long)MPAD_X * DD];
__device__ __half g_y_hi[(long)MPAD_X * DD];
__device__ __half g_q_hi[(long)MPAD_X * DD];
__device__ __half g_kv_hi[(long)MPAD_C * 2 * DD];
__device__ __half g_c_hi[(long)MPAD_C * DD];
__device__ __half g_s_hi[(long)BB * KK * PP];   // exp(scores), unnormalized
__device__ __half g_qb_hi[(long)MM * KK * DD];
__device__ __half g_wq_hi[DD * DD];
__device__ __half g_wo_hi[DD * DD];
__device__ __half g_wc_hi[2 * DD * DD];

// ---------------- PTX helpers ----------------
__device__ __forceinline__ uint32_t smem_u32(const void* p) {
    uint32_t a;
    asm("{ .reg .u64 t; cvta.to.shared.u64 t, %1; cvt.u32.u64 %0, t; }" : "=r"(a) : "l"(p));
    return a;
}
__device__ __forceinline__ void cpasync16(uint32_t dst, const void* src) {
    asm volatile("cp.async.cg.shared.global [%0], [%1], 16;" :: "r"(dst), "l"(src));
}
#define CP_COMMIT() asm volatile("cp.async.commit_group;" ::: "memory")
#define CP_WAIT2()  asm volatile("cp.async.wait_group 2;" ::: "memory")
#define CP_WAIT1()  asm volatile("cp.async.wait_group 1;" ::: "memory")
#define CP_WAIT0()  asm volatile("cp.async.wait_group 0;" ::: "memory")

__device__ __forceinline__ void ldsm4(uint32_t* r, uint32_t addr) {
    asm volatile("ldmatrix.sync.aligned.m8n8.x4.shared.b16 {%0,%1,%2,%3}, [%4];"
        : "=r"(r[0]), "=r"(r[1]), "=r"(r[2]), "=r"(r[3]) : "r"(addr));
}
__device__ __forceinline__ void ldsm4t(uint32_t* r, uint32_t addr) {
    asm volatile("ldmatrix.sync.aligned.m8n8.x4.trans.shared.b16 {%0,%1,%2,%3}, [%4];"
        : "=r"(r[0]), "=r"(r[1]), "=r"(r[2]), "=r"(r[3]) : "r"(addr));
}
__device__ __forceinline__ void mma_f16(float* c, const uint32_t* a, const uint32_t* b) {
    asm volatile(
        "mma.sync.aligned.m16n8k16.row.col.f32.f16.f16.f32 "
        "{%0,%1,%2,%3}, {%4,%5,%6,%7}, {%8,%9}, {%0,%1,%2,%3};"
        : "+f"(c[0]), "+f"(c[1]), "+f"(c[2]), "+f"(c[3])
        : "r"(a[0]), "r"(a[1]), "r"(a[2]), "r"(a[3]), "r"(b[0]), "r"(b[1]));
}

// store a float pair as fp16 (hi only)
__device__ __forceinline__ void h2_store(__half* __restrict__ H, long off, float v0, float v1)
{
    __half h0 = __float2half(v0);
    __half h1 = __float2half(v1);
    uint32_t hw = (uint32_t)*reinterpret_cast<unsigned short*>(&h0)
                | ((uint32_t)*reinterpret_cast<unsigned short*>(&h1) << 16);
    *reinterpret_cast<uint32_t*>(H + off) = hw;
}

// store a float pair as fp16 to smem
__device__ __forceinline__ void h2_sts(uint32_t addr, float v0, float v1)
{
    __half h0 = __float2half(v0);
    __half h1 = __float2half(v1);
    uint32_t hw = (uint32_t)*reinterpret_cast<unsigned short*>(&h0)
                | ((uint32_t)*reinterpret_cast<unsigned short*>(&h1) << 16);
    asm volatile("st.shared.b32 [%0], %1;" :: "r"(addr), "r"(hw) : "memory");
}

// ---------------- NT HMMA GEMM, fp16 1-term, 3-stage, 2 CTA/SM --------------
// C[m,n] (+= bias[n]) = sum_k A[m,k] * B[n,k]
// OUTMODE: 0 = fp32+bias, 2 = fp16 hi (+bias), 3 = exp fp16 + rowsum
#define LDSB 80                    // smem bytes per tile row (32 fp16 + pad)
#define TILE_B (128 * LDSB)        // 10240
#define STAGE2 (2 * TILE_B)        // 20480 (Ah, Bh)
#define GEMM_SMEM (3 * STAGE2)     // 61440  -> 2 CTAs/SM (smem)

template<bool BIAS, bool GATHER, int OUTMODE>
__global__ void __launch_bounds__(256, 2) gemm_mma(
    const __half* __restrict__ Ahb,
    const __half* __restrict__ Bhb,
    const float* __restrict__ bias, float* __restrict__ Cb,
    __half* __restrict__ Chb,
    float* __restrict__ rowsum,
    int M, int Ntot, int Kd,
    long sA, long sB, long sC,
    const int* __restrict__ idxmap)
{
    extern __shared__ char smem[];
    uint32_t sb = smem_u32(smem);

    int tid = threadIdx.x, wid = tid >> 5, lane = tid & 31;
    int warp_m = wid & 3, warp_n = wid >> 2;
    int bz = blockIdx.z;
    long aoff = GATHER ? (long)idxmap[bz] * sA : (long)bz * sA;
    const __half* Ah = Ahb + aoff;
    const __half* Bh = Bhb + (long)bz * sB;

    int m0 = blockIdx.y * 128;
    int n0 = blockIdx.x * 128;

    float acc[2][8][4];
#pragma unroll
    for (int i = 0; i < 2; i++)
#pragma unroll
        for (int j = 0; j < 8; j++)
#pragma unroll
            for (int k = 0; k < 4; k++) acc[i][j][k] = 0.f;

    const int nch = Kd / 32;

    auto issue = [&](int ch) {
        uint32_t st = sb + (ch % 3) * STAGE2;
        int k0 = ch * 32;
#pragma unroll
        for (int it = 0; it < 2; it++) {
            int idx = tid + it * 256;
            int r = idx >> 2, c = idx & 3;
            uint32_t so = r * LDSB + c * 16;
            long gA = (long)(m0 + r) * Kd + k0 + c * 8;
            long gB = (long)(n0 + r) * Kd + k0 + c * 8;
            cpasync16(st + so,          Ah + gA);
            cpasync16(st + TILE_B + so, Bh + gB);
        }
        CP_COMMIT();
    };

    issue(0);
    if (nch > 1) issue(1);
    if (nch > 2) issue(2);

    int lr = lane & 15, lc = lane >> 4;

    for (int ch = 0; ch < nch; ch++) {
        if (ch + 2 < nch)      { CP_WAIT2(); }
        else if (ch + 1 < nch) { CP_WAIT1(); }
        else                   { CP_WAIT0(); }
        __syncthreads();

        uint32_t stg = sb + (ch % 3) * STAGE2;
        uint32_t Ah_s = stg;
        uint32_t Bh_s = stg + TILE_B;

#pragma unroll
        for (int ks = 0; ks < 2; ks++) {
            uint32_t koff = ks * 32 + lc * 16;
            uint32_t ah[2][4], bh[8][2];
#pragma unroll
            for (int mf = 0; mf < 2; mf++) {
                uint32_t row = warp_m * 32 + mf * 16 + lr;
                ldsm4(ah[mf], Ah_s + row * LDSB + koff);
            }
#pragma unroll
            for (int p = 0; p < 4; p++) {
                uint32_t row = warp_n * 64 + p * 16 + lr;
                uint32_t t[4];
                ldsm4(t, Bh_s + row * LDSB + koff);
                bh[2 * p][0] = t[0]; bh[2 * p][1] = t[2];
                bh[2 * p + 1][0] = t[1]; bh[2 * p + 1][1] = t[3];
            }
#pragma unroll
            for (int mf = 0; mf < 2; mf++)
#pragma unroll
                for (int nf = 0; nf < 8; nf++)
                    mma_f16(acc[mf][nf], ah[mf], bh[nf]);
        }
        __syncthreads();
        if (ch + 3 < nch) issue(ch + 3);
    }

#pragma unroll
    for (int mf = 0; mf < 2; mf++) {
        int row0 = m0 + warp_m * 32 + mf * 16 + (lane >> 2);
        float s0 = 0.f, s1 = 0.f;
#pragma unroll
        for (int nf = 0; nf < 8; nf++) {
            int col = n0 + warp_n * 64 + nf * 8 + (lane & 3) * 2;
            if (OUTMODE == 3) {
                __half* Ch = Chb + (long)blockIdx.z * sC;
                float e0 = __expf(acc[mf][nf][0]);
                float e1 = __expf(acc[mf][nf][1]);
                float e2 = __expf(acc[mf][nf][2]);
                float e3 = __expf(acc[mf][nf][3]);
                h2_store(Ch, (long)row0 * Ntot + col, e0, e1);
                h2_store(Ch, (long)(row0 + 8) * Ntot + col, e2, e3);
                s0 += e0 + e1; s1 += e2 + e3;
            } else {
                float b0 = 0.f, b1 = 0.f;
                if (BIAS) { b0 = bias[col]; b1 = bias[col + 1]; }
                if (OUTMODE == 2) {
                    __half* Ch = Chb + (long)blockIdx.z * sC;
                    if (row0 < M)
                        h2_store(Ch, (long)row0 * Ntot + col,
                                 acc[mf][nf][0] + b0, acc[mf][nf][1] + b1);
                    if (row0 + 8 < M)
                        h2_store(Ch, (long)(row0 + 8) * Ntot + col,
                                 acc[mf][nf][2] + b0, acc[mf][nf][3] + b1);
                } else {
                    float* C = Cb + (long)blockIdx.z * sC;
                    if (row0 < M) {
                        float2 v = make_float2(acc[mf][nf][0] + b0, acc[mf][nf][1] + b1);
                        *reinterpret_cast<float2*>(&C[(long)row0 * Ntot + col]) = v;
                    }
                    if (row0 + 8 < M) {
                        float2 v = make_float2(acc[mf][nf][2] + b0, acc[mf][nf][3] + b1);
                        *reinterpret_cast<float2*>(&C[(long)(row0 + 8) * Ntot + col]) = v;
                    }
                }
            }
        }
        if (OUTMODE == 3) {
            s0 += __shfl_xor_sync(0xffffffffu, s0, 1);
            s0 += __shfl_xor_sync(0xffffffffu, s0, 2);
            s1 += __shfl_xor_sync(0xffffffffu, s1, 1);
            s1 += __shfl_xor_sync(0xffffffffu, s1, 2);
            if ((lane & 3) == 0) {
                float* rs = rowsum + (long)blockIdx.z * 128;
                atomicAdd(&rs[row0], s0);
                atomicAdd(&rs[row0 + 8], s1);
            }
        }
    }
}

// ---------------- NN HMMA GEMM (B row-major [k][n]), row-scaled fp16 out -----
// C[m,n] = (sum_k A[m,k] * B[k,n]) / rowsum[m];  M = 128 fixed.
#define LDSB_N 272                       // 128 fp16 (256B) + 16B pad
#define NTILE_B (32 * LDSB_N)            // 8704
#define NSTAGE3 (TILE_B + NTILE_B)       // 18944 (Ah, Bh)
#define NN_SMEM (3 * NSTAGE3)            // 56832

__global__ void __launch_bounds__(256, 2) gemm_mma_nn(
    const __half* __restrict__ Ahb,
    const __half* __restrict__ Bhb,
    __half* __restrict__ Chb,
    const float* __restrict__ rowsum,
    int Ntot, int Kd, int ldB,
    long sA, long sB, long sC)
{
    extern __shared__ char smem[];
    uint32_t sb = smem_u32(smem);

    int tid = threadIdx.x, wid = tid >> 5, lane = tid & 31;
    int warp_m = wid & 3, warp_n = wid >> 2;
    int bz = blockIdx.z;
    const __half* Ah = Ahb + (long)bz * sA;
    const __half* Bh = Bhb + (long)bz * sB;
    __half* Ch = Chb + (long)bz * sC;
    const float* rs = rowsum + (long)bz * 128;

    int n0 = blockIdx.x * 128;

    float acc[2][8][4];
#pragma unroll
    for (int i = 0; i < 2; i++)
#pragma unroll
        for (int j = 0; j < 8; j++)
#pragma unroll
            for (int k = 0; k < 4; k++) acc[i][j][k] = 0.f;

    const int nch = Kd / 32;

    auto issue = [&](int ch) {
        uint32_t st = sb + (ch % 3) * NSTAGE3;
        int k0 = ch * 32;
#pragma unroll
        for (int it = 0; it < 2; it++) {
            int idx = tid + it * 256;
            int r = idx >> 2, c = idx & 3;
            uint32_t so = r * LDSB + c * 16;
            long gA = (long)r * Kd + k0 + c * 8;
            cpasync16(st + so, Ah + gA);
        }
#pragma unroll
        for (int it = 0; it < 2; it++) {
            int idx = tid + it * 256;
            int r = idx >> 4, c = idx & 15;
            uint32_t so = TILE_B + r * LDSB_N + c * 16;
            long gB = (long)(k0 + r) * ldB + n0 + c * 8;
            cpasync16(st + so, Bh + gB);
        }
        CP_COMMIT();
    };

    issue(0);
    if (nch > 1) issue(1);
    if (nch > 2) issue(2);

    int lr = lane & 15, lc = lane >> 4;
    int l8 = (lane >> 3) & 1;
    int krow = ((lane >> 4) & 1) * 8 + (lane & 7);   // 0..15

    for (int ch = 0; ch < nch; ch++) {
        if (ch + 2 < nch)      { CP_WAIT2(); }
        else if (ch + 1 < nch) { CP_WAIT1(); }
        else                   { CP_WAIT0(); }
        __syncthreads();

        uint32_t stg = sb + (ch % 3) * NSTAGE3;
        uint32_t Ah_s = stg;
        uint32_t Bh_s = stg + TILE_B;

#pragma unroll
        for (int ks = 0; ks < 2; ks++) {
            uint32_t koff = ks * 32 + lc * 16;
            uint32_t ah[2][4], bh[8][2];
#pragma unroll
            for (int mf = 0; mf < 2; mf++) {
                uint32_t row = warp_m * 32 + mf * 16 + lr;
                ldsm4(ah[mf], Ah_s + row * LDSB + koff);
            }
            uint32_t brow = (ks * 16 + krow) * LDSB_N + warp_n * 128 + l8 * 16;
#pragma unroll
            for (int p = 0; p < 4; p++) {
                uint32_t t[4];
                ldsm4t(t, Bh_s + brow + p * 32);
                bh[2 * p][0] = t[0]; bh[2 * p][1] = t[2];
                bh[2 * p + 1][0] = t[1]; bh[2 * p + 1][1] = t[3];
            }
#pragma unroll
            for (int mf = 0; mf < 2; mf++)
#pragma unroll
                for (int nf = 0; nf < 8; nf++)
                    mma_f16(acc[mf][nf], ah[mf], bh[nf]);
        }
        __syncthreads();
        if (ch + 3 < nch) issue(ch + 3);
    }

    // epilogue: normalize by rowsum, fp16 hi (M = 128 exact)
#pragma unroll
    for (int mf = 0; mf < 2; mf++) {
        int row0 = warp_m * 32 + mf * 16 + (lane >> 2);
        float inv0 = 1.f / rs[row0];
        float inv1 = 1.f / rs[row0 + 8];
#pragma unroll
        for (int nf = 0; nf < 8; nf++) {
            int col = n0 + warp_n * 64 + nf * 8 + (lane & 3) * 2;
            h2_store(Ch, (long)row0 * Ntot + col,
                     acc[mf][nf][0] * inv0, acc[mf][nf][1] * inv0);
            h2_store(Ch, (long)(row0 + 8) * Ntot + col,
                     acc[mf][nf][2] * inv1, acc[mf][nf][3] * inv1);
        }
    }
}

// ---------------- HMMA flash attention (all 1-term fp16) --------------------
// grid (9, HH, BB); 256 threads (8 warps x 16 q-rows).
#define SKV 144
#define LDSK 144
#define LDSQ 144
#define LDSP 304
#define A_KH 0                           // 144*144 = 20736
#define A_VH 20736
#define A_QH 41472                       // 128*144 = 18432
#define A_PH A_QH                        // P (hi only) reuses q region after sync
#define ATTN_SMEM (A_PH + 128 * LDSP)    // 80384

__global__ void __launch_bounds__(256) attn_mma(
    const __half* __restrict__ qh_g,
    const __half* __restrict__ kvh,
    __half* __restrict__ yh)
{
    extern __shared__ char smem[];
    uint32_t sb = smem_u32(smem);
    int tid = threadIdx.x, wid = tid >> 5, lane = tid & 31;
    int n0 = blockIdx.x * 128;
    int h = blockIdx.y, b = blockIdx.z;

    // ---- loads: K/V hi rows (133) + q hi tile (128 rows) ----
    for (int i = tid; i < CC * 8; i += 256) {
        int m = i >> 3, c = i & 7;
        long g = ((long)(b * CC + m) * 2) * DD + h * HD + c * 8;
        uint32_t so = m * LDSK + c * 16;
        cpasync16(sb + A_KH + so, kvh + g);
        cpasync16(sb + A_VH + so, kvh + g + DD);
    }
    for (int i = tid; i < 128 * 8; i += 256) {
        int r = i >> 3, c = i & 7;
        int qrow = n0 + r; if (qrow >= NN_TOK) qrow = 0;
        long g = (long)(b * NN_TOK + qrow) * DD + h * HD + c * 8;
        cpasync16(sb + A_QH + r * LDSQ + c * 16, qh_g + g);
    }
    CP_COMMIT();
    // zero K/V pad rows 133..143 (V pad must be 0)
    for (int i = tid; i < (SKV - CC) * 32; i += 256) {
        int m = CC + i / 32; int w4 = (i % 32) * 4;
        uint32_t so = m * LDSK + w4;
        *reinterpret_cast<uint32_t*>(smem + A_KH + so) = 0;
        *reinterpret_cast<uint32_t*>(smem + A_VH + so) = 0;
    }
    CP_WAIT0();
    __syncthreads();

    int lr = lane & 15, lg = lane >> 4;

    // ---- S = q @ k^T : warp tile 16 x 144, 1-term ----
    float sacc[18][4];
#pragma unroll
    for (int f = 0; f < 18; f++)
#pragma unroll
        for (int k = 0; k < 4; k++) sacc[f][k] = 0.f;

#pragma unroll
    for (int ks = 0; ks < 4; ks++) {
        uint32_t koff = ks * 32 + lg * 16;
        uint32_t ah[4];
        ldsm4(ah, sb + A_QH + (wid * 16 + lr) * LDSQ + koff);
#pragma unroll
        for (int p = 0; p < 9; p++) {
            uint32_t th[4];
            ldsm4(th, sb + A_KH + (p * 16 + lr) * LDSK + koff);
            uint32_t bh0[2] = { th[0], th[2] }, bh1[2] = { th[1], th[3] };
            mma_f16(sacc[2 * p],     ah, bh0);
            mma_f16(sacc[2 * p + 1], ah, bh1);
        }
    }

    // ---- softmax (no-max exp; scale folded into Wq) ----
    float s0 = 0.f, s1 = 0.f;
#pragma unroll
    for (int f = 0; f < 18; f++) {
        int col = f * 8 + (lane & 3) * 2;
        float e0 = (col     < CC) ? __expf(sacc[f][0]) : 0.f;
        float e1 = (col + 1 < CC) ? __expf(sacc[f][1]) : 0.f;
        float e2 = (col     < CC) ? __expf(sacc[f][2]) : 0.f;
        float e3 = (col + 1 < CC) ? __expf(sacc[f][3]) : 0.f;
        sacc[f][0] = e0; sacc[f][1] = e1; sacc[f][2] = e2; sacc[f][3] = e3;
        s0 += e0 + e1; s1 += e2 + e3;
    }
    s0 += __shfl_xor_sync(0xffffffffu, s0, 1);
    s0 += __shfl_xor_sync(0xffffffffu, s0, 2);
    s1 += __shfl_xor_sync(0xffffffffu, s1, 1);
    s1 += __shfl_xor_sync(0xffffffffu, s1, 2);
    float i0 = 1.f / s0, i1 = 1.f / s1;

    __syncthreads();   // all warps done reading q before P overwrites it

    // ---- write normalized P (fp16 hi only) to smem ----
    int prow0 = wid * 16 + (lane >> 2), prow1 = prow0 + 8;
#pragma unroll
    for (int f = 0; f < 18; f++) {
        uint32_t colb = (f * 8 + (lane & 3) * 2) * 2;
        h2_sts(sb + A_PH + prow0 * LDSP + colb, sacc[f][0] * i0, sacc[f][1] * i0);
        h2_sts(sb + A_PH + prow1 * LDSP + colb, sacc[f][2] * i1, sacc[f][3] * i1);
    }
    __syncthreads();

    // ---- y = P @ V : warp tile 16 x 64, k = 144, 1-term ----
    float yacc[8][4];
#pragma unroll
    for (int f = 0; f < 8; f++)
#pragma unroll
        for (int k = 0; k < 4; k++) yacc[f][k] = 0.f;

    int l8 = (lane >> 3) & 1;
    int krow = ((lane >> 4) & 1) * 8 + (lane & 7);
#pragma unroll
    for (int ks = 0; ks < 9; ks++) {
        uint32_t ph[4];
        ldsm4(ph, sb + A_PH + (wid * 16 + lr) * LDSP + ks * 32 + lg * 16);
        uint32_t vrow = (ks * 16 + krow) * LDSK + l8 * 16;
#pragma unroll
        for (int p = 0; p < 4; p++) {
            uint32_t th[4];
            ldsm4t(th, sb + A_VH + vrow + p * 32);
            uint32_t bh0[2] = { th[0], th[2] }, bh1[2] = { th[1], th[3] };
            mma_f16(yacc[2 * p],     ph, bh0);
            mma_f16(yacc[2 * p + 1], ph, bh1);
        }
    }

    // ---- store y (fp16 hi only), masked to valid rows ----
    int row0 = n0 + wid * 16 + (lane >> 2);
    int row1 = row0 + 8;
#pragma unroll
    for (int f = 0; f < 8; f++) {
        int col = f * 8 + (lane & 3) * 2;
        if (row0 < NN_TOK)
            h2_store(yh, (long)(b * NN_TOK + row0) * DD + h * HD + col,
                     yacc[f][0], yacc[f][1]);
        if (row1 < NN_TOK)
            h2_store(yh, (long)(b * NN_TOK + row1) * DD + h * HD + col,
                     yacc[f][2], yacc[f][3]);
    }
}

// ---------------- fp32 -> fp16 hi-only convert (contiguous) -----------------
__global__ __launch_bounds__(256) void hconv_kernel(
    const float* __restrict__ in, __half* __restrict__ oh, long n)
{
    long i = (long)blockIdx.x * 256 + threadIdx.x;
    if (i * 2 + 1 >= n) return;
    float2 v = reinterpret_cast<const float2*>(in)[i];
    h2_store(oh, i * 2, v.x, v.y);
}

// ------------ transpose weights (scale folded), fp16 hi only -----------------
__global__ __launch_bounds__(256) void tsplit_kernel(
    const float* __restrict__ W, __half* __restrict__ hiT,
    int Kd, int Nc, float scale)
{
    int idx = blockIdx.x * 256 + threadIdx.x;
    if (idx >= Kd * Nc) return;
    int k = idx / Nc, n = idx % Nc;
    hiT[(long)n * Kd + k] = __float2half(W[idx] * scale);
}

// ---------------- kernel 1: cls_n, sims, argmax ----------------
__global__ __launch_bounds__(256) void cls_kernel(
    const float* __restrict__ x, const float* __restrict__ cents,
    float* __restrict__ out_cls, float* __restrict__ out_idx, int* __restrict__ idx)
{
    int b = blockIdx.x;
    int t = threadIdx.x;
    __shared__ float red[256];
    __shared__ float snorm;
    __shared__ float best_s;
    __shared__ int best_i;

    const float* xr = x + (long)b * NN_TOK * DD;
    float loc[3];
    float ss = 0.f;
#pragma unroll
    for (int i = 0; i < 3; i++) { loc[i] = xr[t + i * 256]; ss += loc[i] * loc[i]; }
    red[t] = ss; __syncthreads();
    for (int s = 128; s > 0; s >>= 1) { if (t < s) red[t] += red[t + s]; __syncthreads(); }
    if (t == 0) snorm = fmaxf(sqrtf(red[0]), 1e-12f);
    __syncthreads();
    float inv = 1.0f / snorm;
    float c[3];
#pragma unroll
    for (int i = 0; i < 3; i++) {
        c[i] = loc[i] * inv;
        out_cls[(long)b * DD + t + i * 256] = c[i];
    }
    if (t == 0) { best_s = -1e30f; best_i = 0; }
    __syncthreads();
    for (int m = 0; m < MM; m++) {
        float p = 0.f;
#pragma unroll
        for (int i = 0; i < 3; i++) p += c[i] * cents[(long)m * DD + t + i * 256];
        red[t] = p; __syncthreads();
        for (int s = 128; s > 0; s >>= 1) { if (t < s) red[t] += red[t + s]; __syncthreads(); }
        if (t == 0) { if (red[0] > best_s) { best_s = red[0]; best_i = m; } }
        __syncthreads();
    }
    if (t == 0) { idx[b] = best_i; out_idx[b] = (float)best_i; }
}

// ---------------- copy x[:, :R, :] into ctx hi rows 0..R-1 ------------------
__global__ __launch_bounds__(256) void copy_xreg_h(
    const float* __restrict__ x, __half* __restrict__ ch)
{
    long i = (long)blockIdx.x * blockDim.x + threadIdx.x;   // float4 index
    long total = (long)BB * RR * DD / 4;
    if (i >= total) return;
    long per_b = (long)RR * DD / 4;
    long b = i / per_b;
    long r = i - b * per_b;
    float4 v = reinterpret_cast<const float4*>(x)[b * ((long)NN_TOK * DD / 4) + r];
    long off = b * (long)CC * DD + r * 4;
    h2_store(ch, off,     v.x, v.y);
    h2_store(ch, off + 2, v.z, v.w);
}

// ---------------- launch ----------------
extern "C" void kernel_launch(void* const* d_in, const int* in_sizes, int n_in,
                              void* d_out, int out_size)
{
    const float* x      = (const float*)d_in[0];
    const float* Qb     = (const float*)d_in[1];
    const float* Wq     = (const float*)d_in[2];
    const float* Wctx   = (const float*)d_in[3];
    const float* bctx   = (const float*)d_in[4];
    const float* Wout   = (const float*)d_in[5];
    const float* bout   = (const float*)d_in[6];
    const float* cents  = (const float*)d_in[7];
    float* out = (float*)d_out;

    void *p_idx, *p_rs;
    void *p_xh, *p_yh, *p_qh, *p_kvh;
    void *p_ch, *p_sh;
    void *p_qbh, *p_wqh, *p_woh, *p_wch;
    cudaGetSymbolAddress(&p_idx, g_idx);
    cudaGetSymbolAddress(&p_rs, g_rowsum);
    cudaGetSymbolAddress(&p_xh, g_x_hi);
    cudaGetSymbolAddress(&p_yh, g_y_hi);
    cudaGetSymbolAddress(&p_qh, g_q_hi);
    cudaGetSymbolAddress(&p_kvh, g_kv_hi);
    cudaGetSymbolAddress(&p_ch, g_c_hi);
    cudaGetSymbolAddress(&p_sh, g_s_hi);
    cudaGetSymbolAddress(&p_qbh, g_qb_hi);
    cudaGetSymbolAddress(&p_wqh, g_wq_hi);
    cudaGetSymbolAddress(&p_woh, g_wo_hi);
    cudaGetSymbolAddress(&p_wch, g_wc_hi);

    int*   idxp = (int*)p_idx;
    float* rsum = (float*)p_rs;
    __half *xh = (__half*)p_xh;
    __half *yh = (__half*)p_yh;
    __half *qh = (__half*)p_qh;
    __half *kvh = (__half*)p_kvh;
    __half *ch = (__half*)p_ch;
    __half *shp = (__half*)p_sh;
    __half *qbh = (__half*)p_qbh;
    __half *wqh = (__half*)p_wqh;
    __half *woh = (__half*)p_woh;
    __half *wch = (__half*)p_wch;

    cudaFuncSetAttribute(gemm_mma<false, true,  3>, cudaFuncAttributeMaxDynamicSharedMemorySize, GEMM_SMEM);
    cudaFuncSetAttribute(gemm_mma<true,  false, 2>, cudaFuncAttributeMaxDynamicSharedMemorySize, GEMM_SMEM);
    cudaFuncSetAttribute(gemm_mma<false, false, 2>, cudaFuncAttributeMaxDynamicSharedMemorySize, GEMM_SMEM);
    cudaFuncSetAttribute(gemm_mma<true,  false, 0>, cudaFuncAttributeMaxDynamicSharedMemorySize, GEMM_SMEM);
    cudaFuncSetAttribute(gemm_mma_nn, cudaFuncAttributeMaxDynamicSharedMemorySize, NN_SMEM);
    cudaFuncSetAttribute(attn_mma, cudaFuncAttributeMaxDynamicSharedMemorySize, ATTN_SMEM);

    // 0. zero rowsum accumulators (graph-capturable)
    cudaMemsetAsync(rsum, 0, BB * KK * sizeof(float));

    // 1. cls_n / idx
    cls_kernel<<<BB, 256>>>(x, cents, out + OUT_CLS, out + OUT_IDX, idxp);

    // 2. precision conversions (all hi-only)
    {
        long xn = (long)BB * NN_TOK * DD;
        hconv_kernel<<<(unsigned)((xn / 2 + 255) / 256), 256>>>(x, xh, xn);
        long qn = (long)MM * KK * DD;
        hconv_kernel<<<(unsigned)((qn / 2 + 255) / 256), 256>>>(Qb, qbh, qn);
        tsplit_kernel<<<(DD * DD + 255) / 256, 256>>>(Wq, wqh, DD, DD, 0.125f);
        tsplit_kernel<<<(DD * DD + 255) / 256, 256>>>(Wout, woh, DD, DD, 1.0f);
        tsplit_kernel<<<(DD * 2 * DD + 255) / 256, 256>>>(Wctx, wch, DD, 2 * DD, 1.0f);
    }

    // 3. exp(scores) = exp(Q_banks[idx] @ xp^T) — NT 1-term, fused exp + rowsum
    gemm_mma<false, true, 3><<<dim3(PP / 128, 1, BB), 256, GEMM_SMEM>>>(
        qbh, xh + (long)RR * DD, nullptr, nullptr, shp, rsum,
        KK, PP, DD,
        (long)KK * DD, (long)NN_TOK * DD, (long)KK * PP, idxp);

    // 4. ctx[:, :R] = xreg (hi only)
    {
        long total = (long)BB * RR * DD / 4;
        copy_xreg_h<<<(unsigned)((total + 255) / 256), 256>>>(x, ch);
    }

    // 5. ctx[:, R:] = (exp_s @ xp) / rowsum — NN 1-term, fused normalize
    gemm_mma_nn<<<dim3(DD / 128, 1, BB), 256, NN_SMEM>>>(
        shp, xh + (long)RR * DD,
        ch + (long)RR * DD, rsum,
        DD, PP, DD,
        (long)KK * PP, (long)NN_TOK * DD, (long)CC * DD);

    // 6. kv = ctx @ Wctx + bctx — NT 1-term, fp16 hi out
    gemm_mma<true, false, 2><<<dim3(2 * DD / 128, MPAD_C / 128, 1), 256, GEMM_SMEM>>>(
        ch, wch, bctx, nullptr, kvh, nullptr,
        BB * CC, 2 * DD, DD, 0, 0, 0, nullptr);

    // 7. q = x @ (Wq/8) — NT 1-term, fp16 hi out
    gemm_mma<false, false, 2><<<dim3(DD / 128, MPAD_X / 128, 1), 256, GEMM_SMEM>>>(
        xh, wqh, nullptr, nullptr, qh, nullptr,
        BB * NN_TOK, DD, DD, 0, 0, 0, nullptr);

    // 8. attention — HMMA flash (all 1-term), y hi out
    attn_mma<<<dim3((NN_TOK + 127) / 128, HH, BB), 256, ATTN_SMEM>>>(
        qh, kvh, yh);

    // 9. out = y @ Wout + bout — NT 1-term, fp32 out
    gemm_mma<true, false, 0><<<dim3(DD / 128, MPAD_X / 128, 1), 256, GEMM_SMEM>>>(
        yh, woh, bout, out, nullptr, nullptr,
        BB * NN_TOK, DD, DD, 0, 0, 0, nullptr);
}

// round 12
// speedup vs baseline: 3.6483x; 1.0320x over previous
#include <cuda_runtime.h>
#include <cuda_fp16.h>
#include <math.h>
#include <stdint.h>

// ---------------- problem constants ----------------
#define BB 64
#define NN_TOK 1029
#define DD 768
#define HH 12
#define HD 64
#define KK 128
#define RR 5
#define MM 4
#define PP 1024              // N - R
#define CC 133               // R + K

#define MPAD_X 65920         // 515*128  (>= B*N = 65856)
#define MPAD_C 8576          // 67*128   (>= B*C = 8512)

// output layout: [out (B*N*D)] [cls_n (B*D)] [idx (B)]
#define OUT_CLS ((long)BB * NN_TOK * DD)
#define OUT_IDX (OUT_CLS + (long)BB * DD)

// ---------------- scratch (device globals; no allocs allowed) ----------------
__device__ int   g_idx[BB];
__device__ float g_rowsum[BB * KK];

// fp16 buffers (zero-init covers padding rows)
__device__ __half g_x_hi[(long)MPAD_X * DD];
__device__ __half g_y_hi[(long)MPAD_X * DD];
__device__ __half g_q_hi[(long)MPAD_X * DD];
__device__ __half g_kv_hi[(long)MPAD_C * 2 * DD];
__device__ __half g_c_hi[(long)MPAD_C * DD];
__device__ __half g_s_hi[(long)BB * KK * PP];   // exp(scores), unnormalized
__device__ __half g_qb_hi[(long)MM * KK * DD];
__device__ __half g_wq_hi[DD * DD];
__device__ __half g_wo_hi[DD * DD];
__device__ __half g_wc_hi[2 * DD * DD];

// ---------------- PTX helpers ----------------
__device__ __forceinline__ uint32_t smem_u32(const void* p) {
    uint32_t a;
    asm("{ .reg .u64 t; cvta.to.shared.u64 t, %1; cvt.u32.u64 %0, t; }" : "=r"(a) : "l"(p));
    return a;
}
__device__ __forceinline__ void cpasync16(uint32_t dst, const void* src) {
    asm volatile("cp.async.cg.shared.global [%0], [%1], 16;" :: "r"(dst), "l"(src));
}
#define CP_COMMIT() asm volatile("cp.async.commit_group;" ::: "memory")
#define CP_WAIT2()  asm volatile("cp.async.wait_group 2;" ::: "memory")
#define CP_WAIT1()  asm volatile("cp.async.wait_group 1;" ::: "memory")
#define CP_WAIT0()  asm volatile("cp.async.wait_group 0;" ::: "memory")

__device__ __forceinline__ void ldsm4(uint32_t* r, uint32_t addr) {
    asm volatile("ldmatrix.sync.aligned.m8n8.x4.shared.b16 {%0,%1,%2,%3}, [%4];"
        : "=r"(r[0]), "=r"(r[1]), "=r"(r[2]), "=r"(r[3]) : "r"(addr));
}
__device__ __forceinline__ void ldsm4t(uint32_t* r, uint32_t addr) {
    asm volatile("ldmatrix.sync.aligned.m8n8.x4.trans.shared.b16 {%0,%1,%2,%3}, [%4];"
        : "=r"(r[0]), "=r"(r[1]), "=r"(r[2]), "=r"(r[3]) : "r"(addr));
}
__device__ __forceinline__ void mma_f16(float* c, const uint32_t* a, const uint32_t* b) {
    asm volatile(
        "mma.sync.aligned.m16n8k16.row.col.f32.f16.f16.f32 "
        "{%0,%1,%2,%3}, {%4,%5,%6,%7}, {%8,%9}, {%0,%1,%2,%3};"
        : "+f"(c[0]), "+f"(c[1]), "+f"(c[2]), "+f"(c[3])
        : "r"(a[0]), "r"(a[1]), "r"(a[2]), "r"(a[3]), "r"(b[0]), "r"(b[1]));
}

// store a float pair as fp16 (hi only)
__device__ __forceinline__ void h2_store(__half* __restrict__ H, long off, float v0, float v1)
{
    __half h0 = __float2half(v0);
    __half h1 = __float2half(v1);
    uint32_t hw = (uint32_t)*reinterpret_cast<unsigned short*>(&h0)
                | ((uint32_t)*reinterpret_cast<unsigned short*>(&h1) << 16);
    *reinterpret_cast<uint32_t*>(H + off) = hw;
}

// store a float pair as fp16 to smem
__device__ __forceinline__ void h2_sts(uint32_t addr, float v0, float v1)
{
    __half h0 = __float2half(v0);
    __half h1 = __float2half(v1);
    uint32_t hw = (uint32_t)*reinterpret_cast<unsigned short*>(&h0)
                | ((uint32_t)*reinterpret_cast<unsigned short*>(&h1) << 16);
    asm volatile("st.shared.b32 [%0], %1;" :: "r"(addr), "r"(hw) : "memory");
}
__device__ __forceinline__ uint32_t pack2h(float v0, float v1)
{
    __half h0 = __float2half(v0);
    __half h1 = __float2half(v1);
    return (uint32_t)*reinterpret_cast<unsigned short*>(&h0)
         | ((uint32_t)*reinterpret_cast<unsigned short*>(&h1) << 16);
}

// ---------------- NT HMMA GEMM, fp16 1-term, 3-stage, 2 CTA/SM --------------
// C[m,n] (+= bias[n]) = sum_k A[m,k] * B[n,k]
// OUTMODE: 0 = fp32+bias, 2 = fp16 hi (+bias), 3 = exp fp16 + rowsum
#define LDSB 80                    // smem bytes per tile row (32 fp16 + pad)
#define TILE_B (128 * LDSB)        // 10240
#define STAGE2 (2 * TILE_B)        // 20480 (Ah, Bh)
#define GEMM_SMEM (3 * STAGE2)     // 61440  -> 2 CTAs/SM (smem)

template<bool BIAS, bool GATHER, int OUTMODE>
__global__ void __launch_bounds__(256, 2) gemm_mma(
    const __half* __restrict__ Ahb,
    const __half* __restrict__ Bhb,
    const float* __restrict__ bias, float* __restrict__ Cb,
    __half* __restrict__ Chb,
    float* __restrict__ rowsum,
    int M, int Ntot, int Kd,
    long sA, long sB, long sC,
    const int* __restrict__ idxmap)
{
    extern __shared__ char smem[];
    uint32_t sb = smem_u32(smem);

    int tid = threadIdx.x, wid = tid >> 5, lane = tid & 31;
    int warp_m = wid & 3, warp_n = wid >> 2;
    int bz = blockIdx.z;
    long aoff = GATHER ? (long)idxmap[bz] * sA : (long)bz * sA;
    const __half* Ah = Ahb + aoff;
    const __half* Bh = Bhb + (long)bz * sB;

    int m0 = blockIdx.y * 128;
    int n0 = blockIdx.x * 128;

    float acc[2][8][4];
#pragma unroll
    for (int i = 0; i < 2; i++)
#pragma unroll
        for (int j = 0; j < 8; j++)
#pragma unroll
            for (int k = 0; k < 4; k++) acc[i][j][k] = 0.f;

    const int nch = Kd / 32;

    auto issue = [&](int ch) {
        uint32_t st = sb + (ch % 3) * STAGE2;
        int k0 = ch * 32;
#pragma unroll
        for (int it = 0; it < 2; it++) {
            int idx = tid + it * 256;
            int r = idx >> 2, c = idx & 3;
            uint32_t so = r * LDSB + c * 16;
            long gA = (long)(m0 + r) * Kd + k0 + c * 8;
            long gB = (long)(n0 + r) * Kd + k0 + c * 8;
            cpasync16(st + so,          Ah + gA);
            cpasync16(st + TILE_B + so, Bh + gB);
        }
        CP_COMMIT();
    };

    issue(0);
    if (nch > 1) issue(1);
    if (nch > 2) issue(2);

    int lr = lane & 15, lc = lane >> 4;

    for (int ch = 0; ch < nch; ch++) {
        if (ch + 2 < nch)      { CP_WAIT2(); }
        else if (ch + 1 < nch) { CP_WAIT1(); }
        else                   { CP_WAIT0(); }
        __syncthreads();

        uint32_t stg = sb + (ch % 3) * STAGE2;
        uint32_t Ah_s = stg;
        uint32_t Bh_s = stg + TILE_B;

#pragma unroll
        for (int ks = 0; ks < 2; ks++) {
            uint32_t koff = ks * 32 + lc * 16;
            uint32_t ah[2][4], bh[8][2];
#pragma unroll
            for (int mf = 0; mf < 2; mf++) {
                uint32_t row = warp_m * 32 + mf * 16 + lr;
                ldsm4(ah[mf], Ah_s + row * LDSB + koff);
            }
#pragma unroll
            for (int p = 0; p < 4; p++) {
                uint32_t row = warp_n * 64 + p * 16 + lr;
                uint32_t t[4];
                ldsm4(t, Bh_s + row * LDSB + koff);
                bh[2 * p][0] = t[0]; bh[2 * p][1] = t[2];
                bh[2 * p + 1][0] = t[1]; bh[2 * p + 1][1] = t[3];
            }
#pragma unroll
            for (int mf = 0; mf < 2; mf++)
#pragma unroll
                for (int nf = 0; nf < 8; nf++)
                    mma_f16(acc[mf][nf], ah[mf], bh[nf]);
        }
        __syncthreads();
        if (ch + 3 < nch) issue(ch + 3);
    }

#pragma unroll
    for (int mf = 0; mf < 2; mf++) {
        int row0 = m0 + warp_m * 32 + mf * 16 + (lane >> 2);
        float s0 = 0.f, s1 = 0.f;
#pragma unroll
        for (int nf = 0; nf < 8; nf++) {
            int col = n0 + warp_n * 64 + nf * 8 + (lane & 3) * 2;
            if (OUTMODE == 3) {
                __half* Ch = Chb + (long)blockIdx.z * sC;
                float e0 = __expf(acc[mf][nf][0]);
                float e1 = __expf(acc[mf][nf][1]);
                float e2 = __expf(acc[mf][nf][2]);
                float e3 = __expf(acc[mf][nf][3]);
                h2_store(Ch, (long)row0 * Ntot + col, e0, e1);
                h2_store(Ch, (long)(row0 + 8) * Ntot + col, e2, e3);
                s0 += e0 + e1; s1 += e2 + e3;
            } else {
                float b0 = 0.f, b1 = 0.f;
                if (BIAS) { b0 = bias[col]; b1 = bias[col + 1]; }
                if (OUTMODE == 2) {
                    __half* Ch = Chb + (long)blockIdx.z * sC;
                    if (row0 < M)
                        h2_store(Ch, (long)row0 * Ntot + col,
                                 acc[mf][nf][0] + b0, acc[mf][nf][1] + b1);
                    if (row0 + 8 < M)
                        h2_store(Ch, (long)(row0 + 8) * Ntot + col,
                                 acc[mf][nf][2] + b0, acc[mf][nf][3] + b1);
                } else {
                    float* C = Cb + (long)blockIdx.z * sC;
                    if (row0 < M) {
                        float2 v = make_float2(acc[mf][nf][0] + b0, acc[mf][nf][1] + b1);
                        *reinterpret_cast<float2*>(&C[(long)row0 * Ntot + col]) = v;
                    }
                    if (row0 + 8 < M) {
                        float2 v = make_float2(acc[mf][nf][2] + b0, acc[mf][nf][3] + b1);
                        *reinterpret_cast<float2*>(&C[(long)(row0 + 8) * Ntot + col]) = v;
                    }
                }
            }
        }
        if (OUTMODE == 3) {
            s0 += __shfl_xor_sync(0xffffffffu, s0, 1);
            s0 += __shfl_xor_sync(0xffffffffu, s0, 2);
            s1 += __shfl_xor_sync(0xffffffffu, s1, 1);
            s1 += __shfl_xor_sync(0xffffffffu, s1, 2);
            if ((lane & 3) == 0) {
                float* rs = rowsum + (long)blockIdx.z * 128;
                atomicAdd(&rs[row0], s0);
                atomicAdd(&rs[row0 + 8], s1);
            }
        }
    }
}

// ---------------- NN HMMA GEMM (B row-major [k][n]), row-scaled fp16 out -----
// C[m,n] = (sum_k A[m,k] * B[k,n]) / rowsum[m];  M = 128 fixed.
#define LDSB_N 272                       // 128 fp16 (256B) + 16B pad
#define NTILE_B (32 * LDSB_N)            // 8704
#define NSTAGE3 (TILE_B + NTILE_B)       // 18944 (Ah, Bh)
#define NN_SMEM (3 * NSTAGE3)            // 56832

__global__ void __launch_bounds__(256, 2) gemm_mma_nn(
    const __half* __restrict__ Ahb,
    const __half* __restrict__ Bhb,
    __half* __restrict__ Chb,
    const float* __restrict__ rowsum,
    int Ntot, int Kd, int ldB,
    long sA, long sB, long sC)
{
    extern __shared__ char smem[];
    uint32_t sb = smem_u32(smem);

    int tid = threadIdx.x, wid = tid >> 5, lane = tid & 31;
    int warp_m = wid & 3, warp_n = wid >> 2;
    int bz = blockIdx.z;
    const __half* Ah = Ahb + (long)bz * sA;
    const __half* Bh = Bhb + (long)bz * sB;
    __half* Ch = Chb + (long)bz * sC;
    const float* rs = rowsum + (long)bz * 128;

    int n0 = blockIdx.x * 128;

    float acc[2][8][4];
#pragma unroll
    for (int i = 0; i < 2; i++)
#pragma unroll
        for (int j = 0; j < 8; j++)
#pragma unroll
            for (int k = 0; k < 4; k++) acc[i][j][k] = 0.f;

    const int nch = Kd / 32;

    auto issue = [&](int ch) {
        uint32_t st = sb + (ch % 3) * NSTAGE3;
        int k0 = ch * 32;
#pragma unroll
        for (int it = 0; it < 2; it++) {
            int idx = tid + it * 256;
            int r = idx >> 2, c = idx & 3;
            uint32_t so = r * LDSB + c * 16;
            long gA = (long)r * Kd + k0 + c * 8;
            cpasync16(st + so, Ah + gA);
        }
#pragma unroll
        for (int it = 0; it < 2; it++) {
            int idx = tid + it * 256;
            int r = idx >> 4, c = idx & 15;
            uint32_t so = TILE_B + r * LDSB_N + c * 16;
            long gB = (long)(k0 + r) * ldB + n0 + c * 8;
            cpasync16(st + so, Bh + gB);
        }
        CP_COMMIT();
    };

    issue(0);
    if (nch > 1) issue(1);
    if (nch > 2) issue(2);

    int lr = lane & 15, lc = lane >> 4;
    int l8 = (lane >> 3) & 1;
    int krow = ((lane >> 4) & 1) * 8 + (lane & 7);   // 0..15

    for (int ch = 0; ch < nch; ch++) {
        if (ch + 2 < nch)      { CP_WAIT2(); }
        else if (ch + 1 < nch) { CP_WAIT1(); }
        else                   { CP_WAIT0(); }
        __syncthreads();

        uint32_t stg = sb + (ch % 3) * NSTAGE3;
        uint32_t Ah_s = stg;
        uint32_t Bh_s = stg + TILE_B;

#pragma unroll
        for (int ks = 0; ks < 2; ks++) {
            uint32_t koff = ks * 32 + lc * 16;
            uint32_t ah[2][4], bh[8][2];
#pragma unroll
            for (int mf = 0; mf < 2; mf++) {
                uint32_t row = warp_m * 32 + mf * 16 + lr;
                ldsm4(ah[mf], Ah_s + row * LDSB + koff);
            }
            uint32_t brow = (ks * 16 + krow) * LDSB_N + warp_n * 128 + l8 * 16;
#pragma unroll
            for (int p = 0; p < 4; p++) {
                uint32_t t[4];
                ldsm4t(t, Bh_s + brow + p * 32);
                bh[2 * p][0] = t[0]; bh[2 * p][1] = t[2];
                bh[2 * p + 1][0] = t[1]; bh[2 * p + 1][1] = t[3];
            }
#pragma unroll
            for (int mf = 0; mf < 2; mf++)
#pragma unroll
                for (int nf = 0; nf < 8; nf++)
                    mma_f16(acc[mf][nf], ah[mf], bh[nf]);
        }
        __syncthreads();
        if (ch + 3 < nch) issue(ch + 3);
    }

    // epilogue: normalize by rowsum, fp16 hi (M = 128 exact)
#pragma unroll
    for (int mf = 0; mf < 2; mf++) {
        int row0 = warp_m * 32 + mf * 16 + (lane >> 2);
        float inv0 = 1.f / rs[row0];
        float inv1 = 1.f / rs[row0 + 8];
#pragma unroll
        for (int nf = 0; nf < 8; nf++) {
            int col = n0 + warp_n * 64 + nf * 8 + (lane & 3) * 2;
            h2_store(Ch, (long)row0 * Ntot + col,
                     acc[mf][nf][0] * inv0, acc[mf][nf][1] * inv0);
            h2_store(Ch, (long)(row0 + 8) * Ntot + col,
                     acc[mf][nf][2] * inv1, acc[mf][nf][3] * inv1);
        }
    }
}

// ---------------- HMMA flash attention (all 1-term fp16) --------------------
// grid (9, HH, BB); 256 threads (8 warps x 16 q-rows); 2 CTAs/SM.
// Load pipeline: group A = K + q (needed for S), group B = V (needed for PV).
#define SKV 144
#define LDSK 144
#define LDSQ 144
#define LDSP 304
#define A_KH 0                           // 144*144 = 20736
#define A_VH 20736
#define A_QH 41472                       // 128*144 = 18432
#define A_PH A_QH                        // P (hi only) reuses q region after sync
#define ATTN_SMEM (A_PH + 128 * LDSP)    // 80384

__global__ void __launch_bounds__(256, 2) attn_mma(
    const __half* __restrict__ qh_g,
    const __half* __restrict__ kvh,
    __half* __restrict__ yh)
{
    extern __shared__ char smem[];
    uint32_t sb = smem_u32(smem);
    int tid = threadIdx.x, wid = tid >> 5, lane = tid & 31;
    int n0 = blockIdx.x * 128;
    int h = blockIdx.y, b = blockIdx.z;

    // ---- group A: K rows (133) + q tile (128 rows) ----
    for (int i = tid; i < CC * 8; i += 256) {
        int m = i >> 3, c = i & 7;
        long g = ((long)(b * CC + m) * 2) * DD + h * HD + c * 8;
        cpasync16(sb + A_KH + m * LDSK + c * 16, kvh + g);
    }
    for (int i = tid; i < 128 * 8; i += 256) {
        int r = i >> 3, c = i & 7;
        int qrow = n0 + r; if (qrow >= NN_TOK) qrow = 0;
        long g = (long)(b * NN_TOK + qrow) * DD + h * HD + c * 8;
        cpasync16(sb + A_QH + r * LDSQ + c * 16, qh_g + g);
    }
    CP_COMMIT();
    // ---- group B: V rows (133) ----
    for (int i = tid; i < CC * 8; i += 256) {
        int m = i >> 3, c = i & 7;
        long g = ((long)(b * CC + m) * 2) * DD + h * HD + c * 8 + DD;
        cpasync16(sb + A_VH + m * LDSK + c * 16, kvh + g);
    }
    CP_COMMIT();
    // zero K/V pad rows 133..143 (plain smem stores; region untouched by cp.async)
    for (int i = tid; i < (SKV - CC) * 32; i += 256) {
        int m = CC + i / 32; int w4 = (i % 32) * 4;
        uint32_t so = m * LDSK + w4;
        *reinterpret_cast<uint32_t*>(smem + A_KH + so) = 0;
        *reinterpret_cast<uint32_t*>(smem + A_VH + so) = 0;
    }
    CP_WAIT1();          // K + q resident; V still streaming
    __syncthreads();

    int lr = lane & 15, lg = lane >> 4;

    // ---- S = q @ k^T : warp tile 16 x 144, 1-term ----
    float sacc[18][4];
#pragma unroll
    for (int f = 0; f < 18; f++)
#pragma unroll
        for (int k = 0; k < 4; k++) sacc[f][k] = 0.f;

#pragma unroll
    for (int ks = 0; ks < 4; ks++) {
        uint32_t koff = ks * 32 + lg * 16;
        uint32_t ah[4];
        ldsm4(ah, sb + A_QH + (wid * 16 + lr) * LDSQ + koff);
#pragma unroll
        for (int p = 0; p < 9; p++) {
            uint32_t th[4];
            ldsm4(th, sb + A_KH + (p * 16 + lr) * LDSK + koff);
            uint32_t bh0[2] = { th[0], th[2] }, bh1[2] = { th[1], th[3] };
            mma_f16(sacc[2 * p],     ah, bh0);
            mma_f16(sacc[2 * p + 1], ah, bh1);
        }
    }

    // ---- softmax (no-max exp; scale folded into Wq) ----
    float s0 = 0.f, s1 = 0.f;
#pragma unroll
    for (int f = 0; f < 18; f++) {
        int col = f * 8 + (lane & 3) * 2;
        float e0 = (col     < CC) ? __expf(sacc[f][0]) : 0.f;
        float e1 = (col + 1 < CC) ? __expf(sacc[f][1]) : 0.f;
        float e2 = (col     < CC) ? __expf(sacc[f][2]) : 0.f;
        float e3 = (col + 1 < CC) ? __expf(sacc[f][3]) : 0.f;
        sacc[f][0] = e0; sacc[f][1] = e1; sacc[f][2] = e2; sacc[f][3] = e3;
        s0 += e0 + e1; s1 += e2 + e3;
    }
    s0 += __shfl_xor_sync(0xffffffffu, s0, 1);
    s0 += __shfl_xor_sync(0xffffffffu, s0, 2);
    s1 += __shfl_xor_sync(0xffffffffu, s1, 1);
    s1 += __shfl_xor_sync(0xffffffffu, s1, 2);
    float i0 = 1.f / s0, i1 = 1.f / s1;

    __syncthreads();   // all warps done reading q before P overwrites it

    // ---- write normalized P (fp16 hi only) to smem ----
    int prow0 = wid * 16 + (lane >> 2), prow1 = prow0 + 8;
#pragma unroll
    for (int f = 0; f < 18; f++) {
        uint32_t colb = (f * 8 + (lane & 3) * 2) * 2;
        h2_sts(sb + A_PH + prow0 * LDSP + colb, sacc[f][0] * i0, sacc[f][1] * i0);
        h2_sts(sb + A_PH + prow1 * LDSP + colb, sacc[f][2] * i1, sacc[f][3] * i1);
    }
    CP_WAIT0();        // V resident
    __syncthreads();

    // ---- y = P @ V : warp tile 16 x 64, k = 144, 1-term ----
    float yacc[8][4];
#pragma unroll
    for (int f = 0; f < 8; f++)
#pragma unroll
        for (int k = 0; k < 4; k++) yacc[f][k] = 0.f;

    int l8 = (lane >> 3) & 1;
    int krow = ((lane >> 4) & 1) * 8 + (lane & 7);
#pragma unroll
    for (int ks = 0; ks < 9; ks++) {
        uint32_t ph[4];
        ldsm4(ph, sb + A_PH + (wid * 16 + lr) * LDSP + ks * 32 + lg * 16);
        uint32_t vrow = (ks * 16 + krow) * LDSK + l8 * 16;
#pragma unroll
        for (int p = 0; p < 4; p++) {
            uint32_t th[4];
            ldsm4t(th, sb + A_VH + vrow + p * 32);
            uint32_t bh0[2] = { th[0], th[2] }, bh1[2] = { th[1], th[3] };
            mma_f16(yacc[2 * p],     ph, bh0);
            mma_f16(yacc[2 * p + 1], ph, bh1);
        }
    }

    // ---- store y (fp16 hi only), masked to valid rows ----
    int row0 = n0 + wid * 16 + (lane >> 2);
    int row1 = row0 + 8;
#pragma unroll
    for (int f = 0; f < 8; f++) {
        int col = f * 8 + (lane & 3) * 2;
        if (row0 < NN_TOK)
            h2_store(yh, (long)(b * NN_TOK + row0) * DD + h * HD + col,
                     yacc[f][0], yacc[f][1]);
        if (row1 < NN_TOK)
            h2_store(yh, (long)(b * NN_TOK + row1) * DD + h * HD + col,
                     yacc[f][2], yacc[f][3]);
    }
}

// ---------------- fp32 -> fp16 hi-only convert (8 elems / thread) -----------
__global__ __launch_bounds__(256) void hconv_kernel(
    const float4* __restrict__ in, uint4* __restrict__ oh, long n8)
{
    long i = (long)blockIdx.x * 256 + threadIdx.x;
    if (i >= n8) return;
    float4 a = in[2 * i], b = in[2 * i + 1];
    uint4 o;
    o.x = pack2h(a.x, a.y);
    o.y = pack2h(a.z, a.w);
    o.z = pack2h(b.x, b.y);
    o.w = pack2h(b.z, b.w);
    oh[i] = o;
}

// ------------ transpose weights (scale folded), fp16 hi only -----------------
__global__ __launch_bounds__(256) void tsplit_kernel(
    const float* __restrict__ W, __half* __restrict__ hiT,
    int Kd, int Nc, float scale)
{
    int idx = blockIdx.x * 256 + threadIdx.x;
    if (idx >= Kd * Nc) return;
    int k = idx / Nc, n = idx % Nc;
    hiT[(long)n * Kd + k] = __float2half(W[idx] * scale);
}

// ---------------- kernel 1: cls_n, sims, argmax ----------------
__global__ __launch_bounds__(256) void cls_kernel(
    const float* __restrict__ x, const float* __restrict__ cents,
    float* __restrict__ out_cls, float* __restrict__ out_idx, int* __restrict__ idx)
{
    int b = blockIdx.x;
    int t = threadIdx.x;
    __shared__ float red[256];
    __shared__ float snorm;
    __shared__ float best_s;
    __shared__ int best_i;

    const float* xr = x + (long)b * NN_TOK * DD;
    float loc[3];
    float ss = 0.f;
#pragma unroll
    for (int i = 0; i < 3; i++) { loc[i] = xr[t + i * 256]; ss += loc[i] * loc[i]; }
    red[t] = ss; __syncthreads();
    for (int s = 128; s > 0; s >>= 1) { if (t < s) red[t] += red[t + s]; __syncthreads(); }
    if (t == 0) snorm = fmaxf(sqrtf(red[0]), 1e-12f);
    __syncthreads();
    float inv = 1.0f / snorm;
    float c[3];
#pragma unroll
    for (int i = 0; i < 3; i++) {
        c[i] = loc[i] * inv;
        out_cls[(long)b * DD + t + i * 256] = c[i];
    }
    if (t == 0) { best_s = -1e30f; best_i = 0; }
    __syncthreads();
    for (int m = 0; m < MM; m++) {
        float p = 0.f;
#pragma unroll
        for (int i = 0; i < 3; i++) p += c[i] * cents[(long)m * DD + t + i * 256];
        red[t] = p; __syncthreads();
        for (int s = 128; s > 0; s >>= 1) { if (t < s) red[t] += red[t + s]; __syncthreads(); }
        if (t == 0) { if (red[0] > best_s) { best_s = red[0]; best_i = m; } }
        __syncthreads();
    }
    if (t == 0) { idx[b] = best_i; out_idx[b] = (float)best_i; }
}

// ---------------- copy x[:, :R, :] into ctx hi rows 0..R-1 ------------------
__global__ __launch_bounds__(256) void copy_xreg_h(
    const float* __restrict__ x, __half* __restrict__ ch)
{
    long i = (long)blockIdx.x * blockDim.x + threadIdx.x;   // float4 index
    long total = (long)BB * RR * DD / 4;
    if (i >= total) return;
    long per_b = (long)RR * DD / 4;
    long b = i / per_b;
    long r = i - b * per_b;
    float4 v = reinterpret_cast<const float4*>(x)[b * ((long)NN_TOK * DD / 4) + r];
    long off = b * (long)CC * DD + r * 4;
    h2_store(ch, off,     v.x, v.y);
    h2_store(ch, off + 2, v.z, v.w);
}

// ---------------- launch ----------------
extern "C" void kernel_launch(void* const* d_in, const int* in_sizes, int n_in,
                              void* d_out, int out_size)
{
    const float* x      = (const float*)d_in[0];
    const float* Qb     = (const float*)d_in[1];
    const float* Wq     = (const float*)d_in[2];
    const float* Wctx   = (const float*)d_in[3];
    const float* bctx   = (const float*)d_in[4];
    const float* Wout   = (const float*)d_in[5];
    const float* bout   = (const float*)d_in[6];
    const float* cents  = (const float*)d_in[7];
    float* out = (float*)d_out;

    void *p_idx, *p_rs;
    void *p_xh, *p_yh, *p_qh, *p_kvh;
    void *p_ch, *p_sh;
    void *p_qbh, *p_wqh, *p_woh, *p_wch;
    cudaGetSymbolAddress(&p_idx, g_idx);
    cudaGetSymbolAddress(&p_rs, g_rowsum);
    cudaGetSymbolAddress(&p_xh, g_x_hi);
    cudaGetSymbolAddress(&p_yh, g_y_hi);
    cudaGetSymbolAddress(&p_qh, g_q_hi);
    cudaGetSymbolAddress(&p_kvh, g_kv_hi);
    cudaGetSymbolAddress(&p_ch, g_c_hi);
    cudaGetSymbolAddress(&p_sh, g_s_hi);
    cudaGetSymbolAddress(&p_qbh, g_qb_hi);
    cudaGetSymbolAddress(&p_wqh, g_wq_hi);
    cudaGetSymbolAddress(&p_woh, g_wo_hi);
    cudaGetSymbolAddress(&p_wch, g_wc_hi);

    int*   idxp = (int*)p_idx;
    float* rsum = (float*)p_rs;
    __half *xh = (__half*)p_xh;
    __half *yh = (__half*)p_yh;
    __half *qh = (__half*)p_qh;
    __half *kvh = (__half*)p_kvh;
    __half *ch = (__half*)p_ch;
    __half *shp = (__half*)p_sh;
    __half *qbh = (__half*)p_qbh;
    __half *wqh = (__half*)p_wqh;
    __half *woh = (__half*)p_woh;
    __half *wch = (__half*)p_wch;

    cudaFuncSetAttribute(gemm_mma<false, true,  3>, cudaFuncAttributeMaxDynamicSharedMemorySize, GEMM_SMEM);
    cudaFuncSetAttribute(gemm_mma<true,  false, 2>, cudaFuncAttributeMaxDynamicSharedMemorySize, GEMM_SMEM);
    cudaFuncSetAttribute(gemm_mma<false, false, 2>, cudaFuncAttributeMaxDynamicSharedMemorySize, GEMM_SMEM);
    cudaFuncSetAttribute(gemm_mma<true,  false, 0>, cudaFuncAttributeMaxDynamicSharedMemorySize, GEMM_SMEM);
    cudaFuncSetAttribute(gemm_mma_nn, cudaFuncAttributeMaxDynamicSharedMemorySize, NN_SMEM);
    cudaFuncSetAttribute(attn_mma, cudaFuncAttributeMaxDynamicSharedMemorySize, ATTN_SMEM);

    // 0. zero rowsum accumulators (graph-capturable)
    cudaMemsetAsync(rsum, 0, BB * KK * sizeof(float));

    // 1. cls_n / idx
    cls_kernel<<<BB, 256>>>(x, cents, out + OUT_CLS, out + OUT_IDX, idxp);

    // 2. precision conversions (all hi-only)
    {
        long x8 = (long)BB * NN_TOK * DD / 8;
        hconv_kernel<<<(unsigned)((x8 + 255) / 256), 256>>>(
            (const float4*)x, (uint4*)xh, x8);
        long q8 = (long)MM * KK * DD / 8;
        hconv_kernel<<<(unsigned)((q8 + 255) / 256), 256>>>(
            (const float4*)Qb, (uint4*)qbh, q8);
        tsplit_kernel<<<(DD * DD + 255) / 256, 256>>>(Wq, wqh, DD, DD, 0.125f);
        tsplit_kernel<<<(DD * DD + 255) / 256, 256>>>(Wout, woh, DD, DD, 1.0f);
        tsplit_kernel<<<(DD * 2 * DD + 255) / 256, 256>>>(Wctx, wch, DD, 2 * DD, 1.0f);
    }

    // 3. exp(scores) = exp(Q_banks[idx] @ xp^T) — NT 1-term, fused exp + rowsum
    gemm_mma<false, true, 3><<<dim3(PP / 128, 1, BB), 256, GEMM_SMEM>>>(
        qbh, xh + (long)RR * DD, nullptr, nullptr, shp, rsum,
        KK, PP, DD,
        (long)KK * DD, (long)NN_TOK * DD, (long)KK * PP, idxp);

    // 4. ctx[:, :R] = xreg (hi only)
    {
        long total = (long)BB * RR * DD / 4;
        copy_xreg_h<<<(unsigned)((total + 255) / 256), 256>>>(x, ch);
    }

    // 5. ctx[:, R:] = (exp_s @ xp) / rowsum — NN 1-term, fused normalize
    gemm_mma_nn<<<dim3(DD / 128, 1, BB), 256, NN_SMEM>>>(
        shp, xh + (long)RR * DD,
        ch + (long)RR * DD, rsum,
        DD, PP, DD,
        (long)KK * PP, (long)NN_TOK * DD, (long)CC * DD);

    // 6. kv = ctx @ Wctx + bctx — NT 1-term, fp16 hi out
    gemm_mma<true, false, 2><<<dim3(2 * DD / 128, MPAD_C / 128, 1), 256, GEMM_SMEM>>>(
        ch, wch, bctx, nullptr, kvh, nullptr,
        BB * CC, 2 * DD, DD, 0, 0, 0, nullptr);

    // 7. q = x @ (Wq/8) — NT 1-term, fp16 hi out
    gemm_mma<false, false, 2><<<dim3(DD / 128, MPAD_X / 128, 1), 256, GEMM_SMEM>>>(
        xh, wqh, nullptr, nullptr, qh, nullptr,
        BB * NN_TOK, DD, DD, 0, 0, 0, nullptr);

    // 8. attention — HMMA flash (all 1-term, split load groups), y hi out
    attn_mma<<<dim3((NN_TOK + 127) / 128, HH, BB), 256, ATTN_SMEM>>>(
        qh, kvh, yh);

    // 9. out = y @ Wout + bout — NT 1-term, fp32 out
    gemm_mma<true, false, 0><<<dim3(DD / 128, MPAD_X / 128, 1), 256, GEMM_SMEM>>>(
        yh, woh, bout, out, nullptr, nullptr,
        BB * NN_TOK, DD, DD, 0, 0, 0, nullptr);
}

// round 13
// speedup vs baseline: 3.7141x; 1.0180x over previous
#include <cuda_runtime.h>
#include <cuda_fp16.h>
#include <math.h>
#include <stdint.h>

// ---------------- problem constants ----------------
#define BB 64
#define NN_TOK 1029
#define DD 768
#define HH 12
#define HD 64
#define KK 128
#define RR 5
#define MM 4
#define PP 1024              // N - R
#define CC 133               // R + K

#define MPAD_X 65920         // 515*128  (>= B*N = 65856)
#define MPAD_C 8576          // 67*128   (>= B*C = 8512)

// output layout: [out (B*N*D)] [cls_n (B*D)] [idx (B)]
#define OUT_CLS ((long)BB * NN_TOK * DD)
#define OUT_IDX (OUT_CLS + (long)BB * DD)

// ---------------- scratch (device globals; no allocs allowed) ----------------
__device__ int   g_idx[BB];
__device__ float g_rowsum[BB * KK];

// fp16 buffers (zero-init covers padding rows)
__device__ __half g_x_hi[(long)MPAD_X * DD];
__device__ __half g_y_hi[(long)MPAD_X * DD];
__device__ __half g_q_hi[(long)MPAD_X * DD];
__device__ __half g_kv_hi[(long)MPAD_C * 2 * DD];
__device__ __half g_c_hi[(long)MPAD_C * DD];
__device__ __half g_s_hi[(long)BB * KK * PP];   // exp(scores), unnormalized
__device__ __half g_qb_hi[(long)MM * KK * DD];
__device__ __half g_wq_hi[DD * DD];
__device__ __half g_wo_hi[DD * DD];
__device__ __half g_wc_hi[2 * DD * DD];

// ---------------- PTX helpers ----------------
__device__ __forceinline__ uint32_t smem_u32(const void* p) {
    uint32_t a;
    asm("{ .reg .u64 t; cvta.to.shared.u64 t, %1; cvt.u32.u64 %0, t; }" : "=r"(a) : "l"(p));
    return a;
}
__device__ __forceinline__ void cpasync16(uint32_t dst, const void* src) {
    asm volatile("cp.async.cg.shared.global [%0], [%1], 16;" :: "r"(dst), "l"(src));
}
#define CP_COMMIT() asm volatile("cp.async.commit_group;" ::: "memory")
#define CP_WAIT2()  asm volatile("cp.async.wait_group 2;" ::: "memory")
#define CP_WAIT1()  asm volatile("cp.async.wait_group 1;" ::: "memory")
#define CP_WAIT0()  asm volatile("cp.async.wait_group 0;" ::: "memory")

__device__ __forceinline__ void ldsm4(uint32_t* r, uint32_t addr) {
    asm volatile("ldmatrix.sync.aligned.m8n8.x4.shared.b16 {%0,%1,%2,%3}, [%4];"
        : "=r"(r[0]), "=r"(r[1]), "=r"(r[2]), "=r"(r[3]) : "r"(addr));
}
__device__ __forceinline__ void ldsm4t(uint32_t* r, uint32_t addr) {
    asm volatile("ldmatrix.sync.aligned.m8n8.x4.trans.shared.b16 {%0,%1,%2,%3}, [%4];"
        : "=r"(r[0]), "=r"(r[1]), "=r"(r[2]), "=r"(r[3]) : "r"(addr));
}
__device__ __forceinline__ void mma_f16(float* c, const uint32_t* a, const uint32_t* b) {
    asm volatile(
        "mma.sync.aligned.m16n8k16.row.col.f32.f16.f16.f32 "
        "{%0,%1,%2,%3}, {%4,%5,%6,%7}, {%8,%9}, {%0,%1,%2,%3};"
        : "+f"(c[0]), "+f"(c[1]), "+f"(c[2]), "+f"(c[3])
        : "r"(a[0]), "r"(a[1]), "r"(a[2]), "r"(a[3]), "r"(b[0]), "r"(b[1]));
}

// store a float pair as fp16 (hi only)
__device__ __forceinline__ void h2_store(__half* __restrict__ H, long off, float v0, float v1)
{
    __half h0 = __float2half(v0);
    __half h1 = __float2half(v1);
    uint32_t hw = (uint32_t)*reinterpret_cast<unsigned short*>(&h0)
                | ((uint32_t)*reinterpret_cast<unsigned short*>(&h1) << 16);
    *reinterpret_cast<uint32_t*>(H + off) = hw;
}

// store a float pair as fp16 to smem
__device__ __forceinline__ void h2_sts(uint32_t addr, float v0, float v1)
{
    __half h0 = __float2half(v0);
    __half h1 = __float2half(v1);
    uint32_t hw = (uint32_t)*reinterpret_cast<unsigned short*>(&h0)
                | ((uint32_t)*reinterpret_cast<unsigned short*>(&h1) << 16);
    asm volatile("st.shared.b32 [%0], %1;" :: "r"(addr), "r"(hw) : "memory");
}
__device__ __forceinline__ uint32_t pack2h(float v0, float v1)
{
    __half h0 = __float2half(v0);
    __half h1 = __float2half(v1);
    return (uint32_t)*reinterpret_cast<unsigned short*>(&h0)
         | ((uint32_t)*reinterpret_cast<unsigned short*>(&h1) << 16);
}

// ---------------- NT HMMA GEMM, fp16 1-term, 3-stage, 2 CTA/SM --------------
// C[m,n] (+= bias[n]) = sum_k A[m,k] * B[n,k]
// OUTMODE: 0 = fp32+bias, 3 = exp fp16 + rowsum
#define LDSB 80                    // smem bytes per tile row (32 fp16 + pad)
#define TILE_B (128 * LDSB)        // 10240
#define STAGE2 (2 * TILE_B)        // 20480 (Ah, Bh)
#define GEMM_SMEM (3 * STAGE2)     // 61440  -> 2 CTAs/SM (smem)

template<bool BIAS, bool GATHER, int OUTMODE>
__global__ void __launch_bounds__(256, 2) gemm_mma(
    const __half* __restrict__ Ahb,
    const __half* __restrict__ Bhb,
    const float* __restrict__ bias, float* __restrict__ Cb,
    __half* __restrict__ Chb,
    float* __restrict__ rowsum,
    int M, int Ntot, int Kd,
    long sA, long sB, long sC,
    const int* __restrict__ idxmap)
{
    extern __shared__ char smem[];
    uint32_t sb = smem_u32(smem);

    int tid = threadIdx.x, wid = tid >> 5, lane = tid & 31;
    int warp_m = wid & 3, warp_n = wid >> 2;
    int bz = blockIdx.z;
    long aoff = GATHER ? (long)idxmap[bz] * sA : (long)bz * sA;
    const __half* Ah = Ahb + aoff;
    const __half* Bh = Bhb + (long)bz * sB;

    int m0 = blockIdx.y * 128;
    int n0 = blockIdx.x * 128;

    float acc[2][8][4];
#pragma unroll
    for (int i = 0; i < 2; i++)
#pragma unroll
        for (int j = 0; j < 8; j++)
#pragma unroll
            for (int k = 0; k < 4; k++) acc[i][j][k] = 0.f;

    const int nch = Kd / 32;

    auto issue = [&](int ch) {
        uint32_t st = sb + (ch % 3) * STAGE2;
        int k0 = ch * 32;
#pragma unroll
        for (int it = 0; it < 2; it++) {
            int idx = tid + it * 256;
            int r = idx >> 2, c = idx & 3;
            uint32_t so = r * LDSB + c * 16;
            long gA = (long)(m0 + r) * Kd + k0 + c * 8;
            long gB = (long)(n0 + r) * Kd + k0 + c * 8;
            cpasync16(st + so,          Ah + gA);
            cpasync16(st + TILE_B + so, Bh + gB);
        }
        CP_COMMIT();
    };

    issue(0);
    if (nch > 1) issue(1);
    if (nch > 2) issue(2);

    int lr = lane & 15, lc = lane >> 4;

    for (int ch = 0; ch < nch; ch++) {
        if (ch + 2 < nch)      { CP_WAIT2(); }
        else if (ch + 1 < nch) { CP_WAIT1(); }
        else                   { CP_WAIT0(); }
        __syncthreads();

        uint32_t stg = sb + (ch % 3) * STAGE2;
        uint32_t Ah_s = stg;
        uint32_t Bh_s = stg + TILE_B;

#pragma unroll
        for (int ks = 0; ks < 2; ks++) {
            uint32_t koff = ks * 32 + lc * 16;
            uint32_t ah[2][4], bh[8][2];
#pragma unroll
            for (int mf = 0; mf < 2; mf++) {
                uint32_t row = warp_m * 32 + mf * 16 + lr;
                ldsm4(ah[mf], Ah_s + row * LDSB + koff);
            }
#pragma unroll
            for (int p = 0; p < 4; p++) {
                uint32_t row = warp_n * 64 + p * 16 + lr;
                uint32_t t[4];
                ldsm4(t, Bh_s + row * LDSB + koff);
                bh[2 * p][0] = t[0]; bh[2 * p][1] = t[2];
                bh[2 * p + 1][0] = t[1]; bh[2 * p + 1][1] = t[3];
            }
#pragma unroll
            for (int mf = 0; mf < 2; mf++)
#pragma unroll
                for (int nf = 0; nf < 8; nf++)
                    mma_f16(acc[mf][nf], ah[mf], bh[nf]);
        }
        __syncthreads();
        if (ch + 3 < nch) issue(ch + 3);
    }

#pragma unroll
    for (int mf = 0; mf < 2; mf++) {
        int row0 = m0 + warp_m * 32 + mf * 16 + (lane >> 2);
        float s0 = 0.f, s1 = 0.f;
#pragma unroll
        for (int nf = 0; nf < 8; nf++) {
            int col = n0 + warp_n * 64 + nf * 8 + (lane & 3) * 2;
            if (OUTMODE == 3) {
                __half* Ch = Chb + (long)blockIdx.z * sC;
                float e0 = __expf(acc[mf][nf][0]);
                float e1 = __expf(acc[mf][nf][1]);
                float e2 = __expf(acc[mf][nf][2]);
                float e3 = __expf(acc[mf][nf][3]);
                h2_store(Ch, (long)row0 * Ntot + col, e0, e1);
                h2_store(Ch, (long)(row0 + 8) * Ntot + col, e2, e3);
                s0 += e0 + e1; s1 += e2 + e3;
            } else {
                float b0 = 0.f, b1 = 0.f;
                if (BIAS) { b0 = bias[col]; b1 = bias[col + 1]; }
                float* C = Cb + (long)blockIdx.z * sC;
                if (row0 < M) {
                    float2 v = make_float2(acc[mf][nf][0] + b0, acc[mf][nf][1] + b1);
                    *reinterpret_cast<float2*>(&C[(long)row0 * Ntot + col]) = v;
                }
                if (row0 + 8 < M) {
                    float2 v = make_float2(acc[mf][nf][2] + b0, acc[mf][nf][3] + b1);
                    *reinterpret_cast<float2*>(&C[(long)(row0 + 8) * Ntot + col]) = v;
                }
            }
        }
        if (OUTMODE == 3) {
            s0 += __shfl_xor_sync(0xffffffffu, s0, 1);
            s0 += __shfl_xor_sync(0xffffffffu, s0, 2);
            s1 += __shfl_xor_sync(0xffffffffu, s1, 1);
            s1 += __shfl_xor_sync(0xffffffffu, s1, 2);
            if ((lane & 3) == 0) {
                float* rs = rowsum + (long)blockIdx.z * 128;
                atomicAdd(&rs[row0], s0);
                atomicAdd(&rs[row0 + 8], s1);
            }
        }
    }
}

// ---------------- merged kv + q NT GEMM (fp16 hi out, padded buffers) --------
// First KVB blocks: kv = ctx @ Wctx + bctx  (grid 12 x 67)
// Remaining:        q  = x @ (Wq/8)         (grid 6 x 515)
#define KVB (12 * 67)          // 804
#define QB  (6 * (MPAD_X / 128))   // 3090
__global__ void __launch_bounds__(256, 2) gemm_kvq(
    const __half* __restrict__ ch, const __half* __restrict__ wch,
    const float* __restrict__ bctx, __half* __restrict__ kvh,
    const __half* __restrict__ xh, const __half* __restrict__ wqh,
    __half* __restrict__ qh)
{
    extern __shared__ char smem[];
    uint32_t sb = smem_u32(smem);

    int tid = threadIdx.x, wid = tid >> 5, lane = tid & 31;
    int warp_m = wid & 3, warp_n = wid >> 2;

    const __half *Ah, *Bh;
    __half* Ch;
    const float* bias;
    int Ntot, m0, n0;
    int bid = blockIdx.x;
    if (bid < KVB) {
        Ah = ch; Bh = wch; Ch = kvh; bias = bctx; Ntot = 2 * DD;
        n0 = (bid % 12) * 128; m0 = (bid / 12) * 128;
    } else {
        int b2 = bid - KVB;
        Ah = xh; Bh = wqh; Ch = qh; bias = nullptr; Ntot = DD;
        n0 = (b2 % 6) * 128; m0 = (b2 / 6) * 128;
    }

    float acc[2][8][4];
#pragma unroll
    for (int i = 0; i < 2; i++)
#pragma unroll
        for (int j = 0; j < 8; j++)
#pragma unroll
            for (int k = 0; k < 4; k++) acc[i][j][k] = 0.f;

    const int nch = DD / 32;   // 24

    auto issue = [&](int chn) {
        uint32_t st = sb + (chn % 3) * STAGE2;
        int k0 = chn * 32;
#pragma unroll
        for (int it = 0; it < 2; it++) {
            int idx = tid + it * 256;
            int r = idx >> 2, c = idx & 3;
            uint32_t so = r * LDSB + c * 16;
            long gA = (long)(m0 + r) * DD + k0 + c * 8;
            long gB = (long)(n0 + r) * DD + k0 + c * 8;
            cpasync16(st + so,          Ah + gA);
            cpasync16(st + TILE_B + so, Bh + gB);
        }
        CP_COMMIT();
    };

    issue(0); issue(1); issue(2);

    int lr = lane & 15, lc = lane >> 4;

    for (int chn = 0; chn < nch; chn++) {
        if (chn + 2 < nch)      { CP_WAIT2(); }
        else if (chn + 1 < nch) { CP_WAIT1(); }
        else                    { CP_WAIT0(); }
        __syncthreads();

        uint32_t stg = sb + (chn % 3) * STAGE2;
        uint32_t Ah_s = stg;
        uint32_t Bh_s = stg + TILE_B;

#pragma unroll
        for (int ks = 0; ks < 2; ks++) {
            uint32_t koff = ks * 32 + lc * 16;
            uint32_t ah[2][4], bh[8][2];
#pragma unroll
            for (int mf = 0; mf < 2; mf++) {
                uint32_t row = warp_m * 32 + mf * 16 + lr;
                ldsm4(ah[mf], Ah_s + row * LDSB + koff);
            }
#pragma unroll
            for (int p = 0; p < 4; p++) {
                uint32_t row = warp_n * 64 + p * 16 + lr;
                uint32_t t[4];
                ldsm4(t, Bh_s + row * LDSB + koff);
                bh[2 * p][0] = t[0]; bh[2 * p][1] = t[2];
                bh[2 * p + 1][0] = t[1]; bh[2 * p + 1][1] = t[3];
            }
#pragma unroll
            for (int mf = 0; mf < 2; mf++)
#pragma unroll
                for (int nf = 0; nf < 8; nf++)
                    mma_f16(acc[mf][nf], ah[mf], bh[nf]);
        }
        __syncthreads();
        if (chn + 3 < nch) issue(chn + 3);
    }

    // epilogue: fp16 hi out; buffers are row-padded so no bounds checks
#pragma unroll
    for (int mf = 0; mf < 2; mf++) {
        int row0 = m0 + warp_m * 32 + mf * 16 + (lane >> 2);
#pragma unroll
        for (int nf = 0; nf < 8; nf++) {
            int col = n0 + warp_n * 64 + nf * 8 + (lane & 3) * 2;
            float b0 = 0.f, b1 = 0.f;
            if (bias) { b0 = bias[col]; b1 = bias[col + 1]; }
            h2_store(Ch, (long)row0 * Ntot + col,
                     acc[mf][nf][0] + b0, acc[mf][nf][1] + b1);
            h2_store(Ch, (long)(row0 + 8) * Ntot + col,
                     acc[mf][nf][2] + b0, acc[mf][nf][3] + b1);
        }
    }
}

// ---------------- NN HMMA GEMM (B row-major [k][n]), row-scaled fp16 out -----
// C[m,n] = (sum_k A[m,k] * B[k,n]) / rowsum[m];  M = 128 fixed.
#define LDSB_N 272                       // 128 fp16 (256B) + 16B pad
#define NTILE_B (32 * LDSB_N)            // 8704
#define NSTAGE3 (TILE_B + NTILE_B)       // 18944 (Ah, Bh)
#define NN_SMEM (3 * NSTAGE3)            // 56832

__global__ void __launch_bounds__(256, 2) gemm_mma_nn(
    const __half* __restrict__ Ahb,
    const __half* __restrict__ Bhb,
    __half* __restrict__ Chb,
    const float* __restrict__ rowsum,
    int Ntot, int Kd, int ldB,
    long sA, long sB, long sC)
{
    extern __shared__ char smem[];
    uint32_t sb = smem_u32(smem);

    int tid = threadIdx.x, wid = tid >> 5, lane = tid & 31;
    int warp_m = wid & 3, warp_n = wid >> 2;
    int bz = blockIdx.z;
    const __half* Ah = Ahb + (long)bz * sA;
    const __half* Bh = Bhb + (long)bz * sB;
    __half* Ch = Chb + (long)bz * sC;
    const float* rs = rowsum + (long)bz * 128;

    int n0 = blockIdx.x * 128;

    float acc[2][8][4];
#pragma unroll
    for (int i = 0; i < 2; i++)
#pragma unroll
        for (int j = 0; j < 8; j++)
#pragma unroll
            for (int k = 0; k < 4; k++) acc[i][j][k] = 0.f;

    const int nch = Kd / 32;

    auto issue = [&](int ch) {
        uint32_t st = sb + (ch % 3) * NSTAGE3;
        int k0 = ch * 32;
#pragma unroll
        for (int it = 0; it < 2; it++) {
            int idx = tid + it * 256;
            int r = idx >> 2, c = idx & 3;
            uint32_t so = r * LDSB + c * 16;
            long gA = (long)r * Kd + k0 + c * 8;
            cpasync16(st + so, Ah + gA);
        }
#pragma unroll
        for (int it = 0; it < 2; it++) {
            int idx = tid + it * 256;
            int r = idx >> 4, c = idx & 15;
            uint32_t so = TILE_B + r * LDSB_N + c * 16;
            long gB = (long)(k0 + r) * ldB + n0 + c * 8;
            cpasync16(st + so, Bh + gB);
        }
        CP_COMMIT();
    };

    issue(0);
    if (nch > 1) issue(1);
    if (nch > 2) issue(2);

    int lr = lane & 15, lc = lane >> 4;
    int l8 = (lane >> 3) & 1;
    int krow = ((lane >> 4) & 1) * 8 + (lane & 7);   // 0..15

    for (int ch = 0; ch < nch; ch++) {
        if (ch + 2 < nch)      { CP_WAIT2(); }
        else if (ch + 1 < nch) { CP_WAIT1(); }
        else                   { CP_WAIT0(); }
        __syncthreads();

        uint32_t stg = sb + (ch % 3) * NSTAGE3;
        uint32_t Ah_s = stg;
        uint32_t Bh_s = stg + TILE_B;

#pragma unroll
        for (int ks = 0; ks < 2; ks++) {
            uint32_t koff = ks * 32 + lc * 16;
            uint32_t ah[2][4], bh[8][2];
#pragma unroll
            for (int mf = 0; mf < 2; mf++) {
                uint32_t row = warp_m * 32 + mf * 16 + lr;
                ldsm4(ah[mf], Ah_s + row * LDSB + koff);
            }
            uint32_t brow = (ks * 16 + krow) * LDSB_N + warp_n * 128 + l8 * 16;
#pragma unroll
            for (int p = 0; p < 4; p++) {
                uint32_t t[4];
                ldsm4t(t, Bh_s + brow + p * 32);
                bh[2 * p][0] = t[0]; bh[2 * p][1] = t[2];
                bh[2 * p + 1][0] = t[1]; bh[2 * p + 1][1] = t[3];
            }
#pragma unroll
            for (int mf = 0; mf < 2; mf++)
#pragma unroll
                for (int nf = 0; nf < 8; nf++)
                    mma_f16(acc[mf][nf], ah[mf], bh[nf]);
        }
        __syncthreads();
        if (ch + 3 < nch) issue(ch + 3);
    }

    // epilogue: normalize by rowsum, fp16 hi (M = 128 exact)
#pragma unroll
    for (int mf = 0; mf < 2; mf++) {
        int row0 = warp_m * 32 + mf * 16 + (lane >> 2);
        float inv0 = 1.f / rs[row0];
        float inv1 = 1.f / rs[row0 + 8];
#pragma unroll
        for (int nf = 0; nf < 8; nf++) {
            int col = n0 + warp_n * 64 + nf * 8 + (lane & 3) * 2;
            h2_store(Ch, (long)row0 * Ntot + col,
                     acc[mf][nf][0] * inv0, acc[mf][nf][1] * inv0);
            h2_store(Ch, (long)(row0 + 8) * Ntot + col,
                     acc[mf][nf][2] * inv1, acc[mf][nf][3] * inv1);
        }
    }
}

// ---------------- HMMA flash attention (all 1-term fp16) --------------------
// grid (9, HH, BB); 256 threads (8 warps x 16 q-rows); 2 CTAs/SM.
#define SKV 144
#define LDSK 144
#define LDSQ 144
#define LDSP 304
#define A_KH 0                           // 144*144 = 20736
#define A_VH 20736
#define A_QH 41472                       // 128*144 = 18432
#define A_PH A_QH                        // P (hi only) reuses q region after sync
#define ATTN_SMEM (A_PH + 128 * LDSP)    // 80384

__global__ void __launch_bounds__(256, 2) attn_mma(
    const __half* __restrict__ qh_g,
    const __half* __restrict__ kvh,
    __half* __restrict__ yh)
{
    extern __shared__ char smem[];
    uint32_t sb = smem_u32(smem);
    int tid = threadIdx.x, wid = tid >> 5, lane = tid & 31;
    int n0 = blockIdx.x * 128;
    int h = blockIdx.y, b = blockIdx.z;

    // ---- group A: K rows (133) + q tile (128 rows) ----
    for (int i = tid; i < CC * 8; i += 256) {
        int m = i >> 3, c = i & 7;
        long g = ((long)(b * CC + m) * 2) * DD + h * HD + c * 8;
        cpasync16(sb + A_KH + m * LDSK + c * 16, kvh + g);
    }
    for (int i = tid; i < 128 * 8; i += 256) {
        int r = i >> 3, c = i & 7;
        int qrow = n0 + r; if (qrow >= NN_TOK) qrow = 0;
        long g = (long)(b * NN_TOK + qrow) * DD + h * HD + c * 8;
        cpasync16(sb + A_QH + r * LDSQ + c * 16, qh_g + g);
    }
    CP_COMMIT();
    // ---- group B: V rows (133) ----
    for (int i = tid; i < CC * 8; i += 256) {
        int m = i >> 3, c = i & 7;
        long g = ((long)(b * CC + m) * 2) * DD + h * HD + c * 8 + DD;
        cpasync16(sb + A_VH + m * LDSK + c * 16, kvh + g);
    }
    CP_COMMIT();
    // zero K/V pad rows 133..143
    for (int i = tid; i < (SKV - CC) * 32; i += 256) {
        int m = CC + i / 32; int w4 = (i % 32) * 4;
        uint32_t so = m * LDSK + w4;
        *reinterpret_cast<uint32_t*>(smem + A_KH + so) = 0;
        *reinterpret_cast<uint32_t*>(smem + A_VH + so) = 0;
    }
    CP_WAIT1();          // K + q resident; V still streaming
    __syncthreads();

    int lr = lane & 15, lg = lane >> 4;

    // ---- S = q @ k^T : warp tile 16 x 144, 1-term ----
    float sacc[18][4];
#pragma unroll
    for (int f = 0; f < 18; f++)
#pragma unroll
        for (int k = 0; k < 4; k++) sacc[f][k] = 0.f;

#pragma unroll
    for (int ks = 0; ks < 4; ks++) {
        uint32_t koff = ks * 32 + lg * 16;
        uint32_t ah[4];
        ldsm4(ah, sb + A_QH + (wid * 16 + lr) * LDSQ + koff);
#pragma unroll
        for (int p = 0; p < 9; p++) {
            uint32_t th[4];
            ldsm4(th, sb + A_KH + (p * 16 + lr) * LDSK + koff);
            uint32_t bh0[2] = { th[0], th[2] }, bh1[2] = { th[1], th[3] };
            mma_f16(sacc[2 * p],     ah, bh0);
            mma_f16(sacc[2 * p + 1], ah, bh1);
        }
    }

    // ---- softmax (no-max exp; scale folded into Wq) ----
    float s0 = 0.f, s1 = 0.f;
#pragma unroll
    for (int f = 0; f < 18; f++) {
        int col = f * 8 + (lane & 3) * 2;
        float e0 = (col     < CC) ? __expf(sacc[f][0]) : 0.f;
        float e1 = (col + 1 < CC) ? __expf(sacc[f][1]) : 0.f;
        float e2 = (col     < CC) ? __expf(sacc[f][2]) : 0.f;
        float e3 = (col + 1 < CC) ? __expf(sacc[f][3]) : 0.f;
        sacc[f][0] = e0; sacc[f][1] = e1; sacc[f][2] = e2; sacc[f][3] = e3;
        s0 += e0 + e1; s1 += e2 + e3;
    }
    s0 += __shfl_xor_sync(0xffffffffu, s0, 1);
    s0 += __shfl_xor_sync(0xffffffffu, s0, 2);
    s1 += __shfl_xor_sync(0xffffffffu, s1, 1);
    s1 += __shfl_xor_sync(0xffffffffu, s1, 2);
    float i0 = 1.f / s0, i1 = 1.f / s1;

    __syncthreads();   // all warps done reading q before P overwrites it

    // ---- write normalized P (fp16 hi only) to smem ----
    int prow0 = wid * 16 + (lane >> 2), prow1 = prow0 + 8;
#pragma unroll
    for (int f = 0; f < 18; f++) {
        uint32_t colb = (f * 8 + (lane & 3) * 2) * 2;
        h2_sts(sb + A_PH + prow0 * LDSP + colb, sacc[f][0] * i0, sacc[f][1] * i0);
        h2_sts(sb + A_PH + prow1 * LDSP + colb, sacc[f][2] * i1, sacc[f][3] * i1);
    }
    CP_WAIT0();        // V resident
    __syncthreads();

    // ---- y = P @ V : warp tile 16 x 64, k = 144, 1-term ----
    float yacc[8][4];
#pragma unroll
    for (int f = 0; f < 8; f++)
#pragma unroll
        for (int k = 0; k < 4; k++) yacc[f][k] = 0.f;

    int l8 = (lane >> 3) & 1;
    int krow = ((lane >> 4) & 1) * 8 + (lane & 7);
#pragma unroll
    for (int ks = 0; ks < 9; ks++) {
        uint32_t ph[4];
        ldsm4(ph, sb + A_PH + (wid * 16 + lr) * LDSP + ks * 32 + lg * 16);
        uint32_t vrow = (ks * 16 + krow) * LDSK + l8 * 16;
#pragma unroll
        for (int p = 0; p < 4; p++) {
            uint32_t th[4];
            ldsm4t(th, sb + A_VH + vrow + p * 32);
            uint32_t bh0[2] = { th[0], th[2] }, bh1[2] = { th[1], th[3] };
            mma_f16(yacc[2 * p],     ph, bh0);
            mma_f16(yacc[2 * p + 1], ph, bh1);
        }
    }

    // ---- store y (fp16 hi only), masked to valid rows ----
    int row0 = n0 + wid * 16 + (lane >> 2);
    int row1 = row0 + 8;
#pragma unroll
    for (int f = 0; f < 8; f++) {
        int col = f * 8 + (lane & 3) * 2;
        if (row0 < NN_TOK)
            h2_store(yh, (long)(b * NN_TOK + row0) * DD + h * HD + col,
                     yacc[f][0], yacc[f][1]);
        if (row1 < NN_TOK)
            h2_store(yh, (long)(b * NN_TOK + row1) * DD + h * HD + col,
                     yacc[f][2], yacc[f][3]);
    }
}

// ---------------- mega prep: cls + rowsum-zero + conversions + xreg ----------
#define NX8   ((long)BB * NN_TOK * DD / 8)      // 6322176
#define PB_X  24696
#define NQ8   ((long)MM * KK * DD / 8)          // 49152
#define PB_Q  192
#define PB_WQ 2304                              // DD*DD/256
#define PB_WC 4608                              // 2*DD*DD/256
#define NXREG ((long)BB * RR * DD / 4)          // 61440
#define PB_XREG 240
#define PREP_BLOCKS (64 + PB_X + PB_Q + PB_WQ + PB_WQ + PB_WC + PB_XREG)   // 34408

__global__ void __launch_bounds__(256) prep_kernel(
    const float* __restrict__ x, const float* __restrict__ Qb,
    const float* __restrict__ Wq, const float* __restrict__ Wctx,
    const float* __restrict__ Wout, const float* __restrict__ cents,
    float* __restrict__ out_cls, float* __restrict__ out_idx,
    int* __restrict__ idxp, float* __restrict__ rsum,
    __half* __restrict__ xh, __half* __restrict__ qbh,
    __half* __restrict__ wqh, __half* __restrict__ wch,
    __half* __restrict__ woh, __half* __restrict__ ch)
{
    int bid = blockIdx.x;
    int t = threadIdx.x;

    if (bid < 64) {
        // zero rowsum slice + cls for batch b = bid
        int b = bid;
        if (t < 128) rsum[b * 128 + t] = 0.f;

        __shared__ float red[256];
        __shared__ float snorm;
        __shared__ float best_s;
        __shared__ int best_i;

        const float* xr = x + (long)b * NN_TOK * DD;
        float loc[3];
        float ss = 0.f;
#pragma unroll
        for (int i = 0; i < 3; i++) { loc[i] = xr[t + i * 256]; ss += loc[i] * loc[i]; }
        red[t] = ss; __syncthreads();
        for (int s = 128; s > 0; s >>= 1) { if (t < s) red[t] += red[t + s]; __syncthreads(); }
        if (t == 0) snorm = fmaxf(sqrtf(red[0]), 1e-12f);
        __syncthreads();
        float inv = 1.0f / snorm;
        float c[3];
#pragma unroll
        for (int i = 0; i < 3; i++) {
            c[i] = loc[i] * inv;
            out_cls[(long)b * DD + t + i * 256] = c[i];
        }
        if (t == 0) { best_s = -1e30f; best_i = 0; }
        __syncthreads();
        for (int m = 0; m < MM; m++) {
            float p = 0.f;
#pragma unroll
            for (int i = 0; i < 3; i++) p += c[i] * cents[(long)m * DD + t + i * 256];
            red[t] = p; __syncthreads();
            for (int s = 128; s > 0; s >>= 1) { if (t < s) red[t] += red[t + s]; __syncthreads(); }
            if (t == 0) { if (red[0] > best_s) { best_s = red[0]; best_i = m; } }
            __syncthreads();
        }
        if (t == 0) { idxp[b] = best_i; out_idx[b] = (float)best_i; }
        return;
    }
    bid -= 64;

    if (bid < PB_X) {     // x -> fp16 (8 elems/thread)
        long i = (long)bid * 256 + t;
        if (i < NX8) {
            const float4* in = (const float4*)x;
            float4 a = in[2 * i], bb = in[2 * i + 1];
            uint4 o;
            o.x = pack2h(a.x, a.y);  o.y = pack2h(a.z, a.w);
            o.z = pack2h(bb.x, bb.y); o.w = pack2h(bb.z, bb.w);
            ((uint4*)xh)[i] = o;
        }
        return;
    }
    bid -= PB_X;

    if (bid < PB_Q) {     // Q_banks -> fp16
        long i = (long)bid * 256 + t;
        if (i < NQ8) {
            const float4* in = (const float4*)Qb;
            float4 a = in[2 * i], bb = in[2 * i + 1];
            uint4 o;
            o.x = pack2h(a.x, a.y);  o.y = pack2h(a.z, a.w);
            o.z = pack2h(bb.x, bb.y); o.w = pack2h(bb.z, bb.w);
            ((uint4*)qbh)[i] = o;
        }
        return;
    }
    bid -= PB_Q;

    if (bid < PB_WQ) {    // Wq transpose, scale 1/8
        int idx = bid * 256 + t;
        int k = idx / DD, n = idx % DD;
        wqh[(long)n * DD + k] = __float2half(Wq[idx] * 0.125f);
        return;
    }
    bid -= PB_WQ;

    if (bid < PB_WQ) {    // Wout transpose
        int idx = bid * 256 + t;
        int k = idx / DD, n = idx % DD;
        woh[(long)n * DD + k] = __float2half(Wout[idx]);
        return;
    }
    bid -= PB_WQ;

    if (bid < PB_WC) {    // Wctx transpose
        int idx = bid * 256 + t;
        int k = idx / (2 * DD), n = idx % (2 * DD);
        wch[(long)n * DD + k] = __float2half(Wctx[idx]);
        return;
    }
    bid -= PB_WC;

    {                     // xreg copy into ctx rows 0..R-1 (fp16 hi)
        long i = (long)bid * 256 + t;
        if (i < NXREG) {
            long per_b = (long)RR * DD / 4;
            long b = i / per_b;
            long r = i - b * per_b;
            float4 v = reinterpret_cast<const float4*>(x)[b * ((long)NN_TOK * DD / 4) + r];
            long off = b * (long)CC * DD + r * 4;
            h2_store(ch, off,     v.x, v.y);
            h2_store(ch, off + 2, v.z, v.w);
        }
    }
}

// ---------------- launch ----------------
extern "C" void kernel_launch(void* const* d_in, const int* in_sizes, int n_in,
                              void* d_out, int out_size)
{
    const float* x      = (const float*)d_in[0];
    const float* Qb     = (const float*)d_in[1];
    const float* Wq     = (const float*)d_in[2];
    const float* Wctx   = (const float*)d_in[3];
    const float* bctx   = (const float*)d_in[4];
    const float* Wout   = (const float*)d_in[5];
    const float* bout   = (const float*)d_in[6];
    const float* cents  = (const float*)d_in[7];
    float* out = (float*)d_out;

    void *p_idx, *p_rs;
    void *p_xh, *p_yh, *p_qh, *p_kvh;
    void *p_ch, *p_sh;
    void *p_qbh, *p_wqh, *p_woh, *p_wch;
    cudaGetSymbolAddress(&p_idx, g_idx);
    cudaGetSymbolAddress(&p_rs, g_rowsum);
    cudaGetSymbolAddress(&p_xh, g_x_hi);
    cudaGetSymbolAddress(&p_yh, g_y_hi);
    cudaGetSymbolAddress(&p_qh, g_q_hi);
    cudaGetSymbolAddress(&p_kvh, g_kv_hi);
    cudaGetSymbolAddress(&p_ch, g_c_hi);
    cudaGetSymbolAddress(&p_sh, g_s_hi);
    cudaGetSymbolAddress(&p_qbh, g_qb_hi);
    cudaGetSymbolAddress(&p_wqh, g_wq_hi);
    cudaGetSymbolAddress(&p_woh, g_wo_hi);
    cudaGetSymbolAddress(&p_wch, g_wc_hi);

    int*   idxp = (int*)p_idx;
    float* rsum = (float*)p_rs;
    __half *xh = (__half*)p_xh;
    __half *yh = (__half*)p_yh;
    __half *qh = (__half*)p_qh;
    __half *kvh = (__half*)p_kvh;
    __half *ch = (__half*)p_ch;
    __half *shp = (__half*)p_sh;
    __half *qbh = (__half*)p_qbh;
    __half *wqh = (__half*)p_wqh;
    __half *woh = (__half*)p_woh;
    __half *wch = (__half*)p_wch;

    cudaFuncSetAttribute(gemm_mma<false, true,  3>, cudaFuncAttributeMaxDynamicSharedMemorySize, GEMM_SMEM);
    cudaFuncSetAttribute(gemm_mma<true,  false, 0>, cudaFuncAttributeMaxDynamicSharedMemorySize, GEMM_SMEM);
    cudaFuncSetAttribute(gemm_kvq, cudaFuncAttributeMaxDynamicSharedMemorySize, GEMM_SMEM);
    cudaFuncSetAttribute(gemm_mma_nn, cudaFuncAttributeMaxDynamicSharedMemorySize, NN_SMEM);
    cudaFuncSetAttribute(attn_mma, cudaFuncAttributeMaxDynamicSharedMemorySize, ATTN_SMEM);

    // 1. prep: cls + rowsum zero + conversions + weight transposes + xreg copy
    prep_kernel<<<PREP_BLOCKS, 256>>>(
        x, Qb, Wq, Wctx, Wout, cents,
        out + OUT_CLS, out + OUT_IDX, idxp, rsum,
        xh, qbh, wqh, wch, woh, ch);

    // 2. exp(scores) = exp(Q_banks[idx] @ xp^T) — NT 1-term, fused exp + rowsum
    gemm_mma<false, true, 3><<<dim3(PP / 128, 1, BB), 256, GEMM_SMEM>>>(
        qbh, xh + (long)RR * DD, nullptr, nullptr, shp, rsum,
        KK, PP, DD,
        (long)KK * DD, (long)NN_TOK * DD, (long)KK * PP, idxp);

    // 3. ctx[:, R:] = (exp_s @ xp) / rowsum — NN 1-term, fused normalize
    gemm_mma_nn<<<dim3(DD / 128, 1, BB), 256, NN_SMEM>>>(
        shp, xh + (long)RR * DD,
        ch + (long)RR * DD, rsum,
        DD, PP, DD,
        (long)KK * PP, (long)NN_TOK * DD, (long)CC * DD);

    // 4. merged kv + q GEMMs (single launch)
    gemm_kvq<<<KVB + QB, 256, GEMM_SMEM>>>(
        ch, wch, bctx, kvh, xh, wqh, qh);

    // 5. attention — HMMA flash, y hi out
    attn_mma<<<dim3((NN_TOK + 127) / 128, HH, BB), 256, ATTN_SMEM>>>(
        qh, kvh, yh);

    // 6. out = y @ Wout + bout — NT 1-term, fp32 out
    gemm_mma<true, false, 0><<<dim3(DD / 128, MPAD_X / 128, 1), 256, GEMM_SMEM>>>(
        yh, woh, bout, out, nullptr, nullptr,
        BB * NN_TOK, DD, DD, 0, 0, 0, nullptr);
}